// round 7
// baseline (speedup 1.0000x reference)
#include <cuda_runtime.h>
#include <cstdint>

#define BN_EPS_F 1e-3f

__device__ __align__(16) float g_w1f[256*128];
__device__ float g_b1[128];
__device__ __align__(16) unsigned char g_w2q[9*128*128]; // [tap][co][ci] s8
__device__ __align__(16) float g_w2t[9*128*128];         // [tap][ci][co] fp32
__device__ float g_b2[128];
__device__ int   g_c2[128];
__device__ __align__(16) unsigned char g_w3q[512*128];   // [co][ci] s8
__device__ float g_b3[512];
__device__ int   g_c3[512];
__device__ float g_inv[2];
__device__ int   g_tctr;
__device__ __align__(16) unsigned g_act1[100352*32];
__device__ __align__(16) unsigned g_act2[100352*32];

__device__ __forceinline__ uint32_t smem_u32(const void* p){
    uint32_t a;
    asm("{ .reg .u64 t; cvta.to.shared.u64 t, %1; cvt.u32.u64 %0, t; }" : "=r"(a) : "l"(p));
    return a;
}
#define SWZ(o) ((o) ^ (((o) >> 3) & 0x70))
#define BARG(id) asm volatile("bar.sync %0, %1;" :: "r"(id), "r"(256) : "memory")

__device__ __forceinline__ void ldsm4(unsigned* r, uint32_t addr){
    asm volatile("ldmatrix.sync.aligned.m8n8.x4.shared.b16 {%0,%1,%2,%3}, [%4];"
        : "=r"(r[0]), "=r"(r[1]), "=r"(r[2]), "=r"(r[3]) : "r"(addr));
}
__device__ __forceinline__ void mma_s8(int* d, const unsigned* a, const unsigned* b){
    asm volatile("mma.sync.aligned.m16n8k32.row.col.s32.s8.s8.s32 "
        "{%0,%1,%2,%3}, {%4,%5,%6,%7}, {%8,%9}, {%0,%1,%2,%3};"
        : "+r"(d[0]), "+r"(d[1]), "+r"(d[2]), "+r"(d[3])
        : "r"(a[0]), "r"(a[1]), "r"(a[2]), "r"(a[3]), "r"(b[0]), "r"(b[1]));
}

// ---------------- prep ----------------
__global__ __launch_bounds__(512) void prep1_kernel(
    const float* __restrict__ w, const float* __restrict__ b,
    const float* __restrict__ g, const float* __restrict__ be,
    const float* __restrict__ m, const float* __restrict__ v)
{
    __shared__ float sc[128]; __shared__ float red[512];
    int tid = threadIdx.x;
    if (tid < 128) sc[tid] = __fdiv_rn(g[tid], __fsqrt_rn(__fadd_rn(v[tid], BN_EPS_F)));
    __syncthreads();
    float lmax = 0.f;
    for (int i = tid; i < 32768; i += 512) lmax = fmaxf(lmax, fabsf(__fmul_rn(w[i], sc[i>>8])));
    red[tid] = lmax; __syncthreads();
    for (int s = 256; s > 0; s >>= 1) { if (tid < s) red[tid] = fmaxf(red[tid], red[tid+s]); __syncthreads(); }
    float sw = __fdiv_rn(127.f, fmaxf(red[0], 1e-8f));
    __syncthreads();
    for (int i = tid; i < 32768; i += 512) {
        float wf = __fmul_rn(w[i], sc[i>>8]);
        g_w1f[(i & 255) * 128 + (i >> 8)] = __fdiv_rn(rintf(__fmul_rn(wf, sw)), sw);
    }
    float bf = 0.f;
    if (tid < 128) bf = __fadd_rn(__fmul_rn(__fsub_rn(b[tid], m[tid]), sc[tid]), be[tid]);
    red[tid] = fabsf(bf); __syncthreads();
    for (int s = 256; s > 0; s >>= 1) { if (tid < s) red[tid] = fmaxf(red[tid], red[tid+s]); __syncthreads(); }
    float sb = __fdiv_rn(32767.f, fmaxf(red[0], 1e-8f));
    if (tid < 128) g_b1[tid] = __fdiv_rn(rintf(__fmul_rn(bf, sb)), sb);
}

__global__ __launch_bounds__(512) void prep2_kernel(
    const float* __restrict__ w, const float* __restrict__ b,
    const float* __restrict__ g, const float* __restrict__ be,
    const float* __restrict__ m, const float* __restrict__ v)
{
    __shared__ float sc[128]; __shared__ float red[512];
    int tid = threadIdx.x;
    if (tid < 128) { sc[tid] = __fdiv_rn(g[tid], __fsqrt_rn(__fadd_rn(v[tid], BN_EPS_F))); g_c2[tid] = 0; }
    __syncthreads();
    float lmax = 0.f;
    for (int i = tid; i < 147456; i += 512) lmax = fmaxf(lmax, fabsf(__fmul_rn(w[i], sc[i/1152])));
    red[tid] = lmax; __syncthreads();
    for (int s = 256; s > 0; s >>= 1) { if (tid < s) red[tid] = fmaxf(red[tid], red[tid+s]); __syncthreads(); }
    float sw = __fdiv_rn(127.f, fmaxf(red[0], 1e-8f));
    __syncthreads();
    for (int i = 0; i < 147456; i += 512) {
        int idx = i + tid;
        int o = idx / 1152, rem = idx - o * 1152, ci = rem / 9, t = rem - ci * 9;
        int q = (int)rintf(__fmul_rn(__fmul_rn(w[idx], sc[o]), sw));
        ((signed char*)g_w2q)[(t * 128 + o) * 128 + ci] = (signed char)q;
        g_w2t[(t * 128 + ci) * 128 + o] = (float)q;
    }
    float bf = 0.f;
    if (tid < 128) bf = __fadd_rn(__fmul_rn(__fsub_rn(b[tid], m[tid]), sc[tid]), be[tid]);
    red[tid] = fabsf(bf); __syncthreads();
    for (int s = 256; s > 0; s >>= 1) { if (tid < s) red[tid] = fmaxf(red[tid], red[tid+s]); __syncthreads(); }
    float sb = __fdiv_rn(32767.f, fmaxf(red[0], 1e-8f));
    if (tid < 128) g_b2[tid] = __fdiv_rn(rintf(__fmul_rn(bf, sb)), sb);
    if (tid == 0)  g_inv[0] = __fdiv_rn(1.f, __fmul_rn(sw, 25.5f));
    int o = tid >> 2, qq = tid & 3, s = 0;
    const signed char* wp = (const signed char*)g_w2q;
    for (int u = qq * 288; u < qq * 288 + 288; u++) {
        int t = u >> 7, ci = u & 127;
        s += wp[(t * 128 + o) * 128 + ci];
    }
    atomicAdd(&g_c2[o], 128 * s);
}

__global__ __launch_bounds__(512) void prep3_kernel(
    const float* __restrict__ w, const float* __restrict__ b,
    const float* __restrict__ g, const float* __restrict__ be,
    const float* __restrict__ m, const float* __restrict__ v)
{
    __shared__ float sc[512]; __shared__ float red[512];
    int tid = threadIdx.x;
    sc[tid] = __fdiv_rn(g[tid], __fsqrt_rn(__fadd_rn(v[tid], BN_EPS_F)));
    __syncthreads();
    float lmax = 0.f;
    for (int i = tid; i < 65536; i += 512) lmax = fmaxf(lmax, fabsf(__fmul_rn(w[i], sc[i>>7])));
    red[tid] = lmax; __syncthreads();
    for (int s = 256; s > 0; s >>= 1) { if (tid < s) red[tid] = fmaxf(red[tid], red[tid+s]); __syncthreads(); }
    float sw = __fdiv_rn(127.f, fmaxf(red[0], 1e-8f));
    __syncthreads();
    for (int i = tid; i < 65536; i += 512)
        ((signed char*)g_w3q)[i] = (signed char)(int)rintf(__fmul_rn(__fmul_rn(w[i], sc[i>>7]), sw));
    float bf = __fadd_rn(__fmul_rn(__fsub_rn(b[tid], m[tid]), sc[tid]), be[tid]);
    red[tid] = fabsf(bf); __syncthreads();
    for (int s = 256; s > 0; s >>= 1) { if (tid < s) red[tid] = fmaxf(red[tid], red[tid+s]); __syncthreads(); }
    float sb = __fdiv_rn(32767.f, fmaxf(red[0], 1e-8f));
    g_b3[tid] = __fdiv_rn(rintf(__fmul_rn(bf, sb)), sb);
    int s = 0;
    const signed char* wp = (const signed char*)g_w3q;
    for (int ci = 0; ci < 128; ci++) s += wp[tid * 128 + ci];
    g_c3[tid] = 128 * s;
    if (tid == 0) g_inv[1] = __fdiv_rn(1.f, __fmul_rn(sw, 25.5f));
}

// ---------------- conv1 (SIMT fp32 GEMM, known good) ----------------
__global__ __launch_bounds__(256) void conv1_kernel(const float* __restrict__ x)
{
    __shared__ float As[16 * 128];
    __shared__ float Ws[16 * 128];
    int n  = blockIdx.y;
    int p0 = blockIdx.x * 128;
    int tid = threadIdx.x;
    int tr = tid >> 4, tc = tid & 15;
    int co0 = tr * 8;
    int pxa = tc * 4, pxb = tc * 4 + 64;

    float acc[8][8];
#pragma unroll
    for (int j = 0; j < 8; j++)
#pragma unroll
        for (int q = 0; q < 8; q++) acc[j][q] = 0.f;

    const float* xn = x + ((size_t)n * 256) * 3136;
    int lr = tid >> 4;
    int lc1 = (tid & 15) * 4, lc2 = lc1 + 64;
    int pc1 = min(p0 + lc1, 3132), pc2 = min(p0 + lc2, 3132);

    float4 a1 = *(const float4*)(xn + (size_t)lr * 3136 + pc1);
    float4 a2 = *(const float4*)(xn + (size_t)lr * 3136 + pc2);
    float4 w1 = *(const float4*)(g_w1f + lr * 128 + lc1);
    float4 w2 = *(const float4*)(g_w1f + lr * 128 + lc2);

    for (int k0 = 0; k0 < 256; k0 += 16) {
        __syncthreads();
        *(float4*)(As + lr * 128 + lc1) = a1;
        *(float4*)(As + lr * 128 + lc2) = a2;
        *(float4*)(Ws + lr * 128 + lc1) = w1;
        *(float4*)(Ws + lr * 128 + lc2) = w2;
        __syncthreads();
        if (k0 < 240) {
            a1 = *(const float4*)(xn + (size_t)(k0 + 16 + lr) * 3136 + pc1);
            a2 = *(const float4*)(xn + (size_t)(k0 + 16 + lr) * 3136 + pc2);
            w1 = *(const float4*)(g_w1f + (k0 + 16 + lr) * 128 + lc1);
            w2 = *(const float4*)(g_w1f + (k0 + 16 + lr) * 128 + lc2);
        }
#pragma unroll
        for (int k = 0; k < 16; k++) {
            float4 av0 = *(const float4*)(As + k * 128 + pxa);
            float4 av1 = *(const float4*)(As + k * 128 + pxb);
            float4 wv0 = *(const float4*)(Ws + k * 128 + co0);
            float4 wv1 = *(const float4*)(Ws + k * 128 + co0 + 4);
            float wreg[8] = {wv0.x, wv0.y, wv0.z, wv0.w, wv1.x, wv1.y, wv1.z, wv1.w};
            float areg[8] = {av0.x, av0.y, av0.z, av0.w, av1.x, av1.y, av1.z, av1.w};
#pragma unroll
            for (int j = 0; j < 8; j++)
#pragma unroll
                for (int q = 0; q < 8; q++)
                    acc[j][q] += wreg[j] * areg[q];
        }
    }

    float bias[8];
#pragma unroll
    for (int j = 0; j < 8; j++) bias[j] = g_b1[co0 + j];
#pragma unroll
    for (int q = 0; q < 8; q++) {
        int p = p0 + (q < 4 ? (pxa + q) : (pxb + q - 4));
        if (p >= 3136) continue;
        unsigned b0 = 0, b1 = 0;
#pragma unroll
        for (int j = 0; j < 8; j++) {
            float vv = acc[j][q] + bias[j];
            vv = fminf(fmaxf(vv, 0.f), 10.f);
            unsigned a = (unsigned)(int)rintf(vv * 25.5f);
            if (j < 4) b0 |= a << (8 * j); else b1 |= a << (8 * (j - 4));
        }
        *(uint2*)&g_act1[((unsigned)(n * 3136 + p)) * 32 + tr * 2] = make_uint2(b0, b1);
    }
}

// ---------------- conv2 hybrid: warps 0-7 int8 mma engine, warps 8-15 fp32 FFMA engine ----------------
// Both engines compute identical exact integer results; tiles pulled from a global counter.
__global__ __launch_bounds__(512, 1) void conv2_hyb()
{
    extern __shared__ char smem[];
    const uint32_t SM_W = 0, SM_A = 147456, SM_ST = 170496, SM_FB = 186880, SM_CR = 187392;
    const uint32_t SM_FA = 187904, SM_FW = 196096, SM_T1 = 204288, SM_T2 = 204292;
    uint32_t sb = smem_u32(smem);
    int tid = threadIdx.x;

    for (int u = tid; u < 9216; u += 512) {
        uint4 wv = *(const uint4*)(g_w2q + u * 16);
        *(uint4*)(smem + SM_W + SWZ(u * 16)) = wv;
    }
    if (tid < 128) {
        ((float*)(smem + SM_FB))[tid] = g_b2[tid];
        ((int*)(smem + SM_CR))[tid]   = g_c2[tid];
    }
    __syncthreads();
    const float* fbs = (const float*)(smem + SM_FB);
    const int*   crs = (const int*)(smem + SM_CR);
    float inv2 = g_inv[0];

    if (tid < 256) {
        // ===== int8 mma engine =====
        int wid = tid >> 5, lane = tid & 31;
        int wrb = (wid & 3) * 32, wcb = (wid >> 2) * 64;
        int sub = lane >> 3, r8 = lane & 7;
        int row8 = (sub & 1) * 8, kh = (sub >> 1) * 16;
        int rowb = (sub >> 1) * 8, khb = (sub & 1) * 16;

        int yym[2], xxm[2];
#pragma unroll
        for (int mt = 0; mt < 2; mt++) {
            int px = wrb + mt * 16 + row8 + r8;
            yym[mt] = px >> 4; xxm[mt] = px & 15;
        }
        uint32_t wbb[4]; int wxx[4];
#pragma unroll
        for (int bt = 0; bt < 4; bt++) {
            int co = wcb + bt * 16 + rowb + r8;
            wbb[bt] = sb + SM_W + co * 128;
            wxx[bt] = (co & 7) * 16;
        }

        while (1) {
            if (tid == 0) *(volatile int*)(smem + SM_T1) = atomicAdd(&g_tctr, 1);
            BARG(1);
            int t = *(volatile int*)(smem + SM_T1);
            if (t >= 896) break;
            int n = t / 28, r = t - n * 28;
            int y0 = (r >> 2) * 8, tx = r & 3;
            int x0 = (tx < 3) ? tx * 16 : 40;

            for (int u = tid; u < 1440; u += 256) {
                int hrow = u >> 3, c16 = u & 7;
                int iy = hrow / 18, ix = hrow - iy * 18;
                int gy = y0 + iy - 1, gx = x0 + ix - 1;
                uint4 vv = make_uint4(0x80808080u, 0x80808080u, 0x80808080u, 0x80808080u);
                if (gy >= 0 && gy < 56 && gx >= 0 && gx < 56) {
                    vv = *(const uint4*)&g_act1[((unsigned)(n * 3136 + gy * 56 + gx)) * 32 + c16 * 4];
                    vv.x ^= 0x80808080u; vv.y ^= 0x80808080u; vv.z ^= 0x80808080u; vv.w ^= 0x80808080u;
                }
                *(uint4*)(smem + SM_A + SWZ(hrow * 128 + c16 * 16)) = vv;
            }
            BARG(1);

            int acc[2][8][4];
#pragma unroll
            for (int mt = 0; mt < 2; mt++)
#pragma unroll
                for (int nt = 0; nt < 8; nt++)
#pragma unroll
                    for (int q = 0; q < 4; q++) acc[mt][nt][q] = 0;

            for (int dy = 0; dy < 3; dy++)
                for (int dx = 0; dx < 3; dx++) {
                    uint32_t ab[2]; int axx[2];
#pragma unroll
                    for (int mt = 0; mt < 2; mt++) {
                        int hrow = (yym[mt] + dy) * 18 + xxm[mt] + dx;
                        ab[mt] = sb + SM_A + hrow * 128;
                        axx[mt] = (hrow & 7) * 16;
                    }
                    uint32_t wtap = (dy * 3 + dx) * 16384;
#pragma unroll
                    for (int ks = 0; ks < 4; ks++) {
                        unsigned A0[4], A1[4], B[4][4];
                        ldsm4(A0, ab[0] + ((ks * 32 + kh) ^ axx[0]));
                        ldsm4(A1, ab[1] + ((ks * 32 + kh) ^ axx[1]));
#pragma unroll
                        for (int bt = 0; bt < 4; bt++)
                            ldsm4(B[bt], wbb[bt] + wtap + ((ks * 32 + khb) ^ wxx[bt]));
#pragma unroll
                        for (int nt = 0; nt < 8; nt++) {
                            const unsigned* bp = &B[nt >> 1][(nt & 1) * 2];
                            mma_s8(acc[0][nt], A0, bp);
                            mma_s8(acc[1][nt], A1, bp);
                        }
                    }
                }

#pragma unroll
            for (int mt = 0; mt < 2; mt++)
#pragma unroll
                for (int h = 0; h < 2; h++) {
                    int px = wrb + mt * 16 + (lane >> 2) + h * 8;
#pragma unroll
                    for (int nt = 0; nt < 8; nt++) {
                        int co = wcb + nt * 8 + (lane & 3) * 2;
                        float v0 = (float)(acc[mt][nt][h * 2 + 0] + crs[co]) * inv2 + fbs[co];
                        float v1 = (float)(acc[mt][nt][h * 2 + 1] + crs[co + 1]) * inv2 + fbs[co + 1];
                        v0 = fminf(fmaxf(v0, 0.f), 10.f);
                        v1 = fminf(fmaxf(v1, 0.f), 10.f);
                        unsigned u0 = (unsigned)(int)rintf(v0 * 25.5f);
                        unsigned u1 = (unsigned)(int)rintf(v1 * 25.5f);
                        *(unsigned short*)(smem + SM_ST + px * 128 + (co ^ ((px & 7) * 16))) =
                            (unsigned short)(u0 | (u1 << 8));
                    }
                }
            BARG(1);

            for (int u = tid; u < 1024; u += 256) {
                int px = u >> 3, c16 = u & 7;
                int yy = px >> 4, xx = px & 15;
                unsigned gp = (unsigned)(n * 3136 + (y0 + yy) * 56 + (x0 + xx));
                *(uint4*)&g_act2[gp * 32 + c16 * 4] =
                    *(const uint4*)(smem + SM_ST + px * 128 + ((c16 * 16) ^ ((px & 7) * 16)));
            }
            BARG(1);
        }
    } else {
        // ===== fp32 FFMA engine =====
        int ftid = tid - 256;
        float* As = (float*)(smem + SM_FA);
        float* Ws = (float*)(smem + SM_FW);
        int tr = ftid >> 4, tc = ftid & 15;
        int co0 = tr * 8;
        int pxa = tc * 4, pxb = tc * 4 + 64;
        int apx = ftid & 127;                 // A-loader pixel
        int aci = (ftid >> 7) * 8;            // A-loader ci0 (0 or 8)
        int ay = apx >> 4, ax = apx & 15;
        int wk = ftid >> 4, wc = (ftid & 15) * 8;   // W-loader

        while (1) {
            if (ftid == 0) *(volatile int*)(smem + SM_T2) = atomicAdd(&g_tctr, 1);
            BARG(2);
            int t = *(volatile int*)(smem + SM_T2);
            if (t >= 896) break;
            int n = t / 28, r = t - n * 28;
            int y0 = (r >> 2) * 8, tx = r & 3;
            int x0 = (tx < 3) ? tx * 16 : 40;

            float acc[8][8];
#pragma unroll
            for (int j = 0; j < 8; j++)
#pragma unroll
                for (int q = 0; q < 8; q++) acc[j][q] = 0.f;

            // prefetch panel 0
            uint2 aReg; float4 wReg0, wReg1;
            {
                int gy = y0 + ay - 1, gx = x0 + ax - 1;
                aReg = make_uint2(0u, 0u);
                if (gy >= 0 && gy < 56 && gx >= 0 && gx < 56)
                    aReg = *(const uint2*)&g_act1[((unsigned)(n * 3136 + gy * 56 + gx)) * 32 + (aci >> 2)];
                const float* wp = g_w2t + (size_t)wk * 128 + wc;
                wReg0 = *(const float4*)(wp);
                wReg1 = *(const float4*)(wp + 4);
            }

            for (int p = 0; p < 72; p++) {
                BARG(2);
#pragma unroll
                for (int j = 0; j < 4; j++) {
                    As[(aci + j) * 128 + apx]     = (float)((aReg.x >> (8 * j)) & 255u);
                    As[(aci + 4 + j) * 128 + apx] = (float)((aReg.y >> (8 * j)) & 255u);
                }
                *(float4*)(Ws + wk * 128 + wc)     = wReg0;
                *(float4*)(Ws + wk * 128 + wc + 4) = wReg1;
                BARG(2);
                if (p < 71) {
                    int pn = p + 1;
                    int tap = pn >> 3, cp = pn & 7;
                    int dy = tap / 3, dx = tap - dy * 3;
                    int gy = y0 + ay + dy - 1, gx = x0 + ax + dx - 1;
                    aReg = make_uint2(0u, 0u);
                    if (gy >= 0 && gy < 56 && gx >= 0 && gx < 56)
                        aReg = *(const uint2*)&g_act1[((unsigned)(n * 3136 + gy * 56 + gx)) * 32 + cp * 4 + (aci >> 2)];
                    const float* wp = g_w2t + ((size_t)(tap * 128 + cp * 16 + wk)) * 128 + wc;
                    wReg0 = *(const float4*)(wp);
                    wReg1 = *(const float4*)(wp + 4);
                }
#pragma unroll
                for (int k = 0; k < 16; k++) {
                    float4 av0 = *(const float4*)(As + k * 128 + pxa);
                    float4 av1 = *(const float4*)(As + k * 128 + pxb);
                    float4 wv0 = *(const float4*)(Ws + k * 128 + co0);
                    float4 wv1 = *(const float4*)(Ws + k * 128 + co0 + 4);
                    float wreg[8] = {wv0.x, wv0.y, wv0.z, wv0.w, wv1.x, wv1.y, wv1.z, wv1.w};
                    float areg[8] = {av0.x, av0.y, av0.z, av0.w, av1.x, av1.y, av1.z, av1.w};
#pragma unroll
                    for (int j = 0; j < 8; j++)
#pragma unroll
                        for (int q = 0; q < 8; q++)
                            acc[j][q] += wreg[j] * areg[q];
                }
            }

#pragma unroll
            for (int q = 0; q < 8; q++) {
                int px = (q < 4 ? (pxa + q) : (pxb + q - 4));
                int py = px >> 4, pxx = px & 15;
                unsigned gp = (unsigned)(n * 3136 + (y0 + py) * 56 + (x0 + pxx));
                unsigned b0 = 0, b1 = 0;
#pragma unroll
                for (int j = 0; j < 8; j++) {
                    float vv = acc[j][q] * inv2 + fbs[co0 + j];
                    vv = fminf(fmaxf(vv, 0.f), 10.f);
                    unsigned a = (unsigned)(int)rintf(vv * 25.5f);
                    if (j < 4) b0 |= a << (8 * j); else b1 |= a << (8 * (j - 4));
                }
                *(uint2*)&g_act2[gp * 32 + tr * 2] = make_uint2(b0, b1);
            }
        }
    }
}

// ---------------- conv3: mma.sync i8, A=w3 (rows=co), B=act px, fp32 NCHW out ----------------
__global__ __launch_bounds__(256, 1) void conv3_mma(float* __restrict__ out)
{
    extern __shared__ char smem[];
    const uint32_t SM_W = 0, SM_A = 65536, SM_FB = 81920, SM_CR = 83968;
    uint32_t sb = smem_u32(smem);
    int tid = threadIdx.x, wid = tid >> 5, lane = tid & 31;
    int n = blockIdx.y, p0 = blockIdx.x * 128;

    for (int u = tid; u < 4096; u += 256) {
        uint4 wv = *(const uint4*)(g_w3q + u * 16);
        *(uint4*)(smem + SM_W + SWZ(u * 16)) = wv;
    }
    for (int u = tid; u < 1024; u += 256) {
        int pix = u >> 3, c16 = u & 7;
        int p = p0 + pix;
        uint4 vv = make_uint4(0x80808080u, 0x80808080u, 0x80808080u, 0x80808080u);
        if (p < 3136) {
            vv = *(const uint4*)&g_act2[((unsigned)(n * 3136 + p)) * 32 + c16 * 4];
            vv.x ^= 0x80808080u; vv.y ^= 0x80808080u; vv.z ^= 0x80808080u; vv.w ^= 0x80808080u;
        }
        *(uint4*)(smem + SM_A + SWZ(pix * 128 + c16 * 16)) = vv;
    }
    if (tid < 128) {
        ((float4*)(smem + SM_FB))[tid] = *(const float4*)&g_b3[tid * 4];
        ((uint4*)(smem + SM_CR))[tid]  = *(const uint4*)&g_c3[tid * 4];
    }
    __syncthreads();

    const float* fbs = (const float*)(smem + SM_FB);
    const int*   crs = (const int*)(smem + SM_CR);
    float inv3 = g_inv[1];

    int cb0 = wid * 64;
    int sub = lane >> 3, r8 = lane & 7;
    int row8 = (sub & 1) * 8, kh = (sub >> 1) * 16;
    int ntl = (sub >> 1) * 8, kb = (sub & 1) * 16;

    unsigned Af[4][4][4];
#pragma unroll
    for (int amt = 0; amt < 4; amt++) {
        int co = cb0 + amt * 16 + row8 + r8;
        uint32_t base = sb + SM_W + co * 128;
        int xx = (co & 7) * 16;
#pragma unroll
        for (int ks = 0; ks < 4; ks++)
            ldsm4(Af[amt][ks], base + ((ks * 32 + kh) ^ xx));
    }

    for (int pg = 0; pg < 4; pg++) {
        int acc[4][4][4];
#pragma unroll
        for (int a = 0; a < 4; a++)
#pragma unroll
            for (int b = 0; b < 4; b++)
#pragma unroll
                for (int q = 0; q < 4; q++) acc[a][b][q] = 0;

#pragma unroll
        for (int ks = 0; ks < 4; ks++) {
            unsigned Bf[2][4];
#pragma unroll
            for (int bq = 0; bq < 2; bq++) {
                int brow = pg * 32 + bq * 16 + ntl + r8;
                ldsm4(Bf[bq], sb + SM_A + brow * 128 + (((ks * 32 + kb)) ^ ((brow & 7) * 16)));
            }
#pragma unroll
            for (int amt = 0; amt < 4; amt++)
#pragma unroll
                for (int nt = 0; nt < 4; nt++)
                    mma_s8(acc[amt][nt], Af[amt][ks], &Bf[nt >> 1][(nt & 1) * 2]);
        }

#pragma unroll
        for (int amt = 0; amt < 4; amt++)
#pragma unroll
            for (int h = 0; h < 2; h++) {
                int co = cb0 + amt * 16 + (lane >> 2) + h * 8;
                float bj = fbs[co];
                int   cr = crs[co];
                size_t base = ((size_t)n * 512 + co) * 3136;
#pragma unroll
                for (int nt = 0; nt < 4; nt++) {
                    int px = p0 + pg * 32 + nt * 8 + (lane & 3) * 2;
                    if (px < 3136) {
                        float2 o2;
                        o2.x = (float)(acc[amt][nt][h * 2 + 0] + cr) * inv3 + bj;
                        o2.y = (float)(acc[amt][nt][h * 2 + 1] + cr) * inv3 + bj;
                        *(float2*)(out + base + px) = o2;
                    }
                }
            }
    }
}

// ---------------- launch ----------------
extern "C" void kernel_launch(void* const* d_in, const int* in_sizes, int n_in,
                              void* d_out, int out_size)
{
    const float* x   = (const float*)d_in[0];
    const float* w1  = (const float*)d_in[1];
    const float* b1  = (const float*)d_in[2];
    const float* g1  = (const float*)d_in[3];
    const float* be1 = (const float*)d_in[4];
    const float* m1  = (const float*)d_in[5];
    const float* v1  = (const float*)d_in[6];
    const float* w2  = (const float*)d_in[7];
    const float* b2  = (const float*)d_in[8];
    const float* g2  = (const float*)d_in[9];
    const float* be2 = (const float*)d_in[10];
    const float* m2  = (const float*)d_in[11];
    const float* v2  = (const float*)d_in[12];
    const float* w3  = (const float*)d_in[13];
    const float* b3  = (const float*)d_in[14];
    const float* g3  = (const float*)d_in[15];
    const float* be3 = (const float*)d_in[16];
    const float* m3  = (const float*)d_in[17];
    const float* v3  = (const float*)d_in[18];

    cudaFuncSetAttribute(conv2_hyb, cudaFuncAttributeMaxDynamicSharedMemorySize, 204800);
    cudaFuncSetAttribute(conv3_mma, cudaFuncAttributeMaxDynamicSharedMemorySize, 86016);

    prep1_kernel<<<1, 512>>>(w1, b1, g1, be1, m1, v1);
    prep2_kernel<<<1, 512>>>(w2, b2, g2, be2, m2, v2);
    prep3_kernel<<<1, 512>>>(w3, b3, g3, be3, m3, v3);

    conv1_kernel<<<dim3(25, 32), 256>>>(x);

    void* ctrAddr = nullptr;
    cudaGetSymbolAddress(&ctrAddr, g_tctr);
    cudaMemsetAsync(ctrAddr, 0, sizeof(int));

    conv2_hyb<<<152, 512, 204800>>>();
    conv3_mma<<<dim3(25, 32), 256, 86016>>>((float*)d_out);
}

// round 8
// speedup vs baseline: 1.4052x; 1.4052x over previous
#include <cuda_runtime.h>
#include <cstdint>

#define BN_EPS_F 1e-3f

__device__ __align__(16) float g_w1f[256*128];
__device__ float g_b1[128];
__device__ __align__(16) unsigned char g_w2q[9*128*128]; // [tap][co][ci] s8
__device__ float g_b2[128];
__device__ __align__(16) unsigned char g_w3q[512*128];   // [co][ci] s8
__device__ float g_b3[512];
__device__ float g_inv[2];
__device__ __align__(16) unsigned g_act1[100352*32];     // u8 NHWC
__device__ __align__(16) unsigned g_act2[100352*32];

__device__ __forceinline__ uint32_t smem_u32(const void* p){
    uint32_t a;
    asm("{ .reg .u64 t; cvta.to.shared.u64 t, %1; cvt.u32.u64 %0, t; }" : "=r"(a) : "l"(p));
    return a;
}
#define SWZ(o) ((o) ^ (((o) >> 3) & 0x70))

__device__ __forceinline__ void ldsm4(unsigned* r, uint32_t addr){
    asm volatile("ldmatrix.sync.aligned.m8n8.x4.shared.b16 {%0,%1,%2,%3}, [%4];"
        : "=r"(r[0]), "=r"(r[1]), "=r"(r[2]), "=r"(r[3]) : "r"(addr));
}
// A = u8 activations, B = s8 weights
__device__ __forceinline__ void mma_u8s8(int* d, const unsigned* a, const unsigned* b){
    asm volatile("mma.sync.aligned.m16n8k32.row.col.s32.u8.s8.s32 "
        "{%0,%1,%2,%3}, {%4,%5,%6,%7}, {%8,%9}, {%0,%1,%2,%3};"
        : "+r"(d[0]), "+r"(d[1]), "+r"(d[2]), "+r"(d[3])
        : "r"(a[0]), "r"(a[1]), "r"(a[2]), "r"(a[3]), "r"(b[0]), "r"(b[1]));
}
// A = s8 weights, B = u8 activations
__device__ __forceinline__ void mma_s8u8(int* d, const unsigned* a, const unsigned* b){
    asm volatile("mma.sync.aligned.m16n8k32.row.col.s32.s8.u8.s32 "
        "{%0,%1,%2,%3}, {%4,%5,%6,%7}, {%8,%9}, {%0,%1,%2,%3};"
        : "+r"(d[0]), "+r"(d[1]), "+r"(d[2]), "+r"(d[3])
        : "r"(a[0]), "r"(a[1]), "r"(a[2]), "r"(a[3]), "r"(b[0]), "r"(b[1]));
}
#define CPA(dst, src, sz) asm volatile("cp.async.cg.shared.global [%0], [%1], 16, %2;" :: "r"(dst), "l"(src), "r"(sz) : "memory")
#define CPC()  asm volatile("cp.async.commit_group;" ::: "memory")
#define CPW(n) asm volatile("cp.async.wait_group %0;" :: "n"(n) : "memory")

// ---------------- prep ----------------
__global__ __launch_bounds__(512) void prep1_kernel(
    const float* __restrict__ w, const float* __restrict__ b,
    const float* __restrict__ g, const float* __restrict__ be,
    const float* __restrict__ m, const float* __restrict__ v)
{
    __shared__ float sc[128]; __shared__ float red[512];
    int tid = threadIdx.x;
    if (tid < 128) sc[tid] = __fdiv_rn(g[tid], __fsqrt_rn(__fadd_rn(v[tid], BN_EPS_F)));
    __syncthreads();
    float lmax = 0.f;
    for (int i = tid; i < 32768; i += 512) lmax = fmaxf(lmax, fabsf(__fmul_rn(w[i], sc[i>>8])));
    red[tid] = lmax; __syncthreads();
    for (int s = 256; s > 0; s >>= 1) { if (tid < s) red[tid] = fmaxf(red[tid], red[tid+s]); __syncthreads(); }
    float sw = __fdiv_rn(127.f, fmaxf(red[0], 1e-8f));
    __syncthreads();
    for (int i = tid; i < 32768; i += 512) {
        float wf = __fmul_rn(w[i], sc[i>>8]);
        g_w1f[(i & 255) * 128 + (i >> 8)] = __fdiv_rn(rintf(__fmul_rn(wf, sw)), sw);
    }
    float bf = 0.f;
    if (tid < 128) bf = __fadd_rn(__fmul_rn(__fsub_rn(b[tid], m[tid]), sc[tid]), be[tid]);
    red[tid] = fabsf(bf); __syncthreads();
    for (int s = 256; s > 0; s >>= 1) { if (tid < s) red[tid] = fmaxf(red[tid], red[tid+s]); __syncthreads(); }
    float sb = __fdiv_rn(32767.f, fmaxf(red[0], 1e-8f));
    if (tid < 128) g_b1[tid] = __fdiv_rn(rintf(__fmul_rn(bf, sb)), sb);
}

__global__ __launch_bounds__(512) void prep2_kernel(
    const float* __restrict__ w, const float* __restrict__ b,
    const float* __restrict__ g, const float* __restrict__ be,
    const float* __restrict__ m, const float* __restrict__ v)
{
    __shared__ float sc[128]; __shared__ float red[512];
    int tid = threadIdx.x;
    if (tid < 128) sc[tid] = __fdiv_rn(g[tid], __fsqrt_rn(__fadd_rn(v[tid], BN_EPS_F)));
    __syncthreads();
    float lmax = 0.f;
    for (int i = tid; i < 147456; i += 512) lmax = fmaxf(lmax, fabsf(__fmul_rn(w[i], sc[i/1152])));
    red[tid] = lmax; __syncthreads();
    for (int s = 256; s > 0; s >>= 1) { if (tid < s) red[tid] = fmaxf(red[tid], red[tid+s]); __syncthreads(); }
    float sw = __fdiv_rn(127.f, fmaxf(red[0], 1e-8f));
    __syncthreads();
    for (int i = tid; i < 147456; i += 512) {
        int o = i / 1152, rem = i - o * 1152, ci = rem / 9, t = rem - ci * 9;
        int q = (int)rintf(__fmul_rn(__fmul_rn(w[i], sc[o]), sw));
        ((signed char*)g_w2q)[(t * 128 + o) * 128 + ci] = (signed char)q;
    }
    float bf = 0.f;
    if (tid < 128) bf = __fadd_rn(__fmul_rn(__fsub_rn(b[tid], m[tid]), sc[tid]), be[tid]);
    red[tid] = fabsf(bf); __syncthreads();
    for (int s = 256; s > 0; s >>= 1) { if (tid < s) red[tid] = fmaxf(red[tid], red[tid+s]); __syncthreads(); }
    float sb = __fdiv_rn(32767.f, fmaxf(red[0], 1e-8f));
    if (tid < 128) g_b2[tid] = __fdiv_rn(rintf(__fmul_rn(bf, sb)), sb);
    if (tid == 0)  g_inv[0] = __fdiv_rn(1.f, __fmul_rn(sw, 25.5f));
}

__global__ __launch_bounds__(512) void prep3_kernel(
    const float* __restrict__ w, const float* __restrict__ b,
    const float* __restrict__ g, const float* __restrict__ be,
    const float* __restrict__ m, const float* __restrict__ v)
{
    __shared__ float sc[512]; __shared__ float red[512];
    int tid = threadIdx.x;
    sc[tid] = __fdiv_rn(g[tid], __fsqrt_rn(__fadd_rn(v[tid], BN_EPS_F)));
    __syncthreads();
    float lmax = 0.f;
    for (int i = tid; i < 65536; i += 512) lmax = fmaxf(lmax, fabsf(__fmul_rn(w[i], sc[i>>7])));
    red[tid] = lmax; __syncthreads();
    for (int s = 256; s > 0; s >>= 1) { if (tid < s) red[tid] = fmaxf(red[tid], red[tid+s]); __syncthreads(); }
    float sw = __fdiv_rn(127.f, fmaxf(red[0], 1e-8f));
    __syncthreads();
    for (int i = tid; i < 65536; i += 512)
        ((signed char*)g_w3q)[i] = (signed char)(int)rintf(__fmul_rn(__fmul_rn(w[i], sc[i>>7]), sw));
    float bf = __fadd_rn(__fmul_rn(__fsub_rn(b[tid], m[tid]), sc[tid]), be[tid]);
    red[tid] = fabsf(bf); __syncthreads();
    for (int s = 256; s > 0; s >>= 1) { if (tid < s) red[tid] = fmaxf(red[tid], red[tid+s]); __syncthreads(); }
    float sb = __fdiv_rn(32767.f, fmaxf(red[0], 1e-8f));
    g_b3[tid] = __fdiv_rn(rintf(__fmul_rn(bf, sb)), sb);
    if (tid == 0) g_inv[1] = __fdiv_rn(1.f, __fmul_rn(sw, 25.5f));
}

// ---------------- conv1: fp32 GEMM, double-buffered smem (1 sync/panel) ----------------
__global__ __launch_bounds__(256, 2) void conv1_kernel(const float* __restrict__ x)
{
    __shared__ float As[2][16 * 128];
    __shared__ float Ws[2][16 * 128];
    int n  = blockIdx.y;
    int p0 = blockIdx.x * 128;
    int tid = threadIdx.x;
    int tr = tid >> 4, tc = tid & 15;
    int co0 = tr * 8;
    int pxa = tc * 4, pxb = tc * 4 + 64;

    float acc[8][8];
#pragma unroll
    for (int j = 0; j < 8; j++)
#pragma unroll
        for (int q = 0; q < 8; q++) acc[j][q] = 0.f;

    const float* xn = x + ((size_t)n * 256) * 3136;
    int lr = tid >> 4;
    int lc1 = (tid & 15) * 4, lc2 = lc1 + 64;
    int pc1 = min(p0 + lc1, 3132), pc2 = min(p0 + lc2, 3132);

    float4 a1 = *(const float4*)(xn + (size_t)lr * 3136 + pc1);
    float4 a2 = *(const float4*)(xn + (size_t)lr * 3136 + pc2);
    float4 w1 = *(const float4*)(g_w1f + lr * 128 + lc1);
    float4 w2 = *(const float4*)(g_w1f + lr * 128 + lc2);
    *(float4*)(As[0] + lr * 128 + lc1) = a1;
    *(float4*)(As[0] + lr * 128 + lc2) = a2;
    *(float4*)(Ws[0] + lr * 128 + lc1) = w1;
    *(float4*)(Ws[0] + lr * 128 + lc2) = w2;
    __syncthreads();

    for (int p = 0; p < 16; p++) {
        int cur = p & 1;
        if (p < 15) {
            int kr = (p + 1) * 16 + lr;
            a1 = *(const float4*)(xn + (size_t)kr * 3136 + pc1);
            a2 = *(const float4*)(xn + (size_t)kr * 3136 + pc2);
            w1 = *(const float4*)(g_w1f + kr * 128 + lc1);
            w2 = *(const float4*)(g_w1f + kr * 128 + lc2);
        }
#pragma unroll
        for (int k = 0; k < 16; k++) {
            float4 av0 = *(const float4*)(As[cur] + k * 128 + pxa);
            float4 av1 = *(const float4*)(As[cur] + k * 128 + pxb);
            float4 wv0 = *(const float4*)(Ws[cur] + k * 128 + co0);
            float4 wv1 = *(const float4*)(Ws[cur] + k * 128 + co0 + 4);
            float wreg[8] = {wv0.x, wv0.y, wv0.z, wv0.w, wv1.x, wv1.y, wv1.z, wv1.w};
            float areg[8] = {av0.x, av0.y, av0.z, av0.w, av1.x, av1.y, av1.z, av1.w};
#pragma unroll
            for (int j = 0; j < 8; j++)
#pragma unroll
                for (int q = 0; q < 8; q++)
                    acc[j][q] += wreg[j] * areg[q];
        }
        if (p < 15) {
            int nxt = 1 - cur;
            *(float4*)(As[nxt] + lr * 128 + lc1) = a1;
            *(float4*)(As[nxt] + lr * 128 + lc2) = a2;
            *(float4*)(Ws[nxt] + lr * 128 + lc1) = w1;
            *(float4*)(Ws[nxt] + lr * 128 + lc2) = w2;
            __syncthreads();
        }
    }

    float bias[8];
#pragma unroll
    for (int j = 0; j < 8; j++) bias[j] = g_b1[co0 + j];
#pragma unroll
    for (int q = 0; q < 8; q++) {
        int p = p0 + (q < 4 ? (pxa + q) : (pxb + q - 4));
        if (p >= 3136) continue;
        unsigned b0 = 0, b1 = 0;
#pragma unroll
        for (int j = 0; j < 8; j++) {
            float vv = acc[j][q] + bias[j];
            vv = fminf(fmaxf(vv, 0.f), 10.f);
            unsigned a = (unsigned)(int)rintf(vv * 25.5f);
            if (j < 4) b0 |= a << (8 * j); else b1 |= a << (8 * (j - 4));
        }
        *(uint2*)&g_act1[((unsigned)(n * 3136 + p)) * 32 + tr * 2] = make_uint2(b0, b1);
    }
}

// ---------------- conv2: mma u8.s8, persistent, cp.async double-buffered halos ----------------
__global__ __launch_bounds__(256, 1) void conv2_mma()
{
    extern __shared__ char smem[];
    const uint32_t SM_W = 0, SM_A0 = 147456, SM_A1 = 170496, SM_ST = 193536, SM_FB = 209920;
    uint32_t sb = smem_u32(smem);
    int tid = threadIdx.x, wid = tid >> 5, lane = tid & 31;

    for (int u = tid; u < 9216; u += 256) {
        uint4 wv = *(const uint4*)(g_w2q + u * 16);
        *(uint4*)(smem + SM_W + SWZ(u * 16)) = wv;
    }
    if (tid < 128) ((float*)(smem + SM_FB))[tid] = g_b2[tid];
    __syncthreads();
    const float* fbs = (const float*)(smem + SM_FB);
    float inv2 = g_inv[0];

    int wrb = (wid & 3) * 32, wcb = (wid >> 2) * 64;
    int sub = lane >> 3, r8 = lane & 7;
    int row8 = (sub & 1) * 8, kh = (sub >> 1) * 16;
    int rowb = (sub >> 1) * 8, khb = (sub & 1) * 16;

    int yym[2], xxm[2];
#pragma unroll
    for (int mt = 0; mt < 2; mt++) {
        int px = wrb + mt * 16 + row8 + r8;
        yym[mt] = px >> 4; xxm[mt] = px & 15;
    }
    uint32_t wbb[4]; int wxx[4];
#pragma unroll
    for (int bt = 0; bt < 4; bt++) {
        int co = wcb + bt * 16 + rowb + r8;
        wbb[bt] = sb + SM_W + co * 128;
        wxx[bt] = (co & 7) * 16;
    }

    // halo prefetch helper (inlined twice)
#define HALO_LOAD(DSTBASE, N_, Y0_, X0_) do { \
    for (int u = tid; u < 1440; u += 256) { \
        int hrow = u >> 3, c16 = u & 7; \
        int iy = hrow / 18, ix = hrow - iy * 18; \
        int gy = (Y0_) + iy - 1, gx = (X0_) + ix - 1; \
        bool ok = (gy >= 0 && gy < 56 && gx >= 0 && gx < 56); \
        const void* src = ok ? (const void*)&g_act1[((unsigned)((N_) * 3136 + gy * 56 + gx)) * 32 + c16 * 4] \
                             : (const void*)g_act1; \
        CPA((DSTBASE) + SWZ(hrow * 128 + c16 * 16), src, ok ? 16u : 0u); \
    } } while (0)

    // prefetch tile 0
    {
        int t = blockIdx.x;
        int n = t / 28, r = t - n * 28;
        int y0 = (r >> 2) * 8, tx = r & 3;
        int x0 = (tx < 3) ? tx * 16 : 40;
        HALO_LOAD(sb + SM_A0, n, y0, x0);
        CPC();
    }

    for (int it = 0; it < 7; it++) {
        int t = it * 128 + blockIdx.x;
        int n = t / 28, r = t - n * 28;
        int y0 = (r >> 2) * 8, tx = r & 3;
        int x0 = (tx < 3) ? tx * 16 : 40;
        uint32_t aBase = sb + ((it & 1) ? SM_A1 : SM_A0);

        if (it < 6) {
            int t2 = (it + 1) * 128 + blockIdx.x;
            int n2 = t2 / 28, r2n = t2 - n2 * 28;
            int y2 = (r2n >> 2) * 8, tx2 = r2n & 3;
            int x2 = (tx2 < 3) ? tx2 * 16 : 40;
            uint32_t nBase = sb + ((it & 1) ? SM_A0 : SM_A1);
            HALO_LOAD(nBase, n2, y2, x2);
            CPC();
            CPW(1);
        } else {
            CPW(0);
        }
        __syncthreads();

        int acc[2][8][4];
#pragma unroll
        for (int mt = 0; mt < 2; mt++)
#pragma unroll
            for (int nt = 0; nt < 8; nt++)
#pragma unroll
                for (int q = 0; q < 4; q++) acc[mt][nt][q] = 0;

        for (int dy = 0; dy < 3; dy++)
            for (int dx = 0; dx < 3; dx++) {
                uint32_t ab[2]; int axx[2];
#pragma unroll
                for (int mt = 0; mt < 2; mt++) {
                    int hrow = (yym[mt] + dy) * 18 + xxm[mt] + dx;
                    ab[mt] = aBase + hrow * 128;
                    axx[mt] = (hrow & 7) * 16;
                }
                uint32_t wtap = (dy * 3 + dx) * 16384;
#pragma unroll
                for (int ks = 0; ks < 4; ks++) {
                    unsigned A0[4], A1[4], B[4][4];
                    ldsm4(A0, ab[0] + ((ks * 32 + kh) ^ axx[0]));
                    ldsm4(A1, ab[1] + ((ks * 32 + kh) ^ axx[1]));
#pragma unroll
                    for (int bt = 0; bt < 4; bt++)
                        ldsm4(B[bt], wbb[bt] + wtap + ((ks * 32 + khb) ^ wxx[bt]));
#pragma unroll
                    for (int nt = 0; nt < 8; nt++) {
                        const unsigned* bp = &B[nt >> 1][(nt & 1) * 2];
                        mma_u8s8(acc[0][nt], A0, bp);
                        mma_u8s8(acc[1][nt], A1, bp);
                    }
                }
            }

#pragma unroll
        for (int mt = 0; mt < 2; mt++)
#pragma unroll
            for (int h = 0; h < 2; h++) {
                int px = wrb + mt * 16 + (lane >> 2) + h * 8;
#pragma unroll
                for (int nt = 0; nt < 8; nt++) {
                    int co = wcb + nt * 8 + (lane & 3) * 2;
                    float v0 = (float)acc[mt][nt][h * 2 + 0] * inv2 + fbs[co];
                    float v1 = (float)acc[mt][nt][h * 2 + 1] * inv2 + fbs[co + 1];
                    v0 = fminf(fmaxf(v0, 0.f), 10.f);
                    v1 = fminf(fmaxf(v1, 0.f), 10.f);
                    unsigned u0 = (unsigned)(int)rintf(v0 * 25.5f);
                    unsigned u1 = (unsigned)(int)rintf(v1 * 25.5f);
                    *(unsigned short*)(smem + SM_ST + px * 128 + (co ^ ((px & 7) * 16))) =
                        (unsigned short)(u0 | (u1 << 8));
                }
            }
        __syncthreads();

        for (int u = tid; u < 1024; u += 256) {
            int px = u >> 3, c16 = u & 7;
            int yy = px >> 4, xx = px & 15;
            unsigned gp = (unsigned)(n * 3136 + (y0 + yy) * 56 + (x0 + xx));
            *(uint4*)&g_act2[gp * 32 + c16 * 4] =
                *(const uint4*)(smem + SM_ST + px * 128 + ((c16 * 16) ^ ((px & 7) * 16)));
        }
        __syncthreads();
    }
#undef HALO_LOAD
}

// ---------------- conv3: mma s8.u8, A=w3 (rows=co), B=act u8, fp32 NCHW out ----------------
__global__ __launch_bounds__(256, 1) void conv3_mma(float* __restrict__ out)
{
    extern __shared__ char smem[];
    const uint32_t SM_W = 0, SM_A = 65536, SM_FB = 81920;
    uint32_t sb = smem_u32(smem);
    int tid = threadIdx.x, wid = tid >> 5, lane = tid & 31;
    int n = blockIdx.y, p0 = blockIdx.x * 128;

    for (int u = tid; u < 4096; u += 256) {
        uint4 wv = *(const uint4*)(g_w3q + u * 16);
        *(uint4*)(smem + SM_W + SWZ(u * 16)) = wv;
    }
    for (int u = tid; u < 1024; u += 256) {
        int pix = u >> 3, c16 = u & 7;
        int p = p0 + pix;
        uint4 vv = make_uint4(0u, 0u, 0u, 0u);
        if (p < 3136)
            vv = *(const uint4*)&g_act2[((unsigned)(n * 3136 + p)) * 32 + c16 * 4];
        *(uint4*)(smem + SM_A + SWZ(pix * 128 + c16 * 16)) = vv;
    }
    if (tid < 128) ((float4*)(smem + SM_FB))[tid] = *(const float4*)&g_b3[tid * 4];
    __syncthreads();

    const float* fbs = (const float*)(smem + SM_FB);
    float inv3 = g_inv[1];

    int cb0 = wid * 64;
    int sub = lane >> 3, r8 = lane & 7;
    int row8 = (sub & 1) * 8, kh = (sub >> 1) * 16;
    int ntl = (sub >> 1) * 8, kb = (sub & 1) * 16;

    unsigned Af[4][4][4];
#pragma unroll
    for (int amt = 0; amt < 4; amt++) {
        int co = cb0 + amt * 16 + row8 + r8;
        uint32_t base = sb + SM_W + co * 128;
        int xx = (co & 7) * 16;
#pragma unroll
        for (int ks = 0; ks < 4; ks++)
            ldsm4(Af[amt][ks], base + ((ks * 32 + kh) ^ xx));
    }

    for (int pg = 0; pg < 4; pg++) {
        int acc[4][4][4];
#pragma unroll
        for (int a = 0; a < 4; a++)
#pragma unroll
            for (int b = 0; b < 4; b++)
#pragma unroll
                for (int q = 0; q < 4; q++) acc[a][b][q] = 0;

#pragma unroll
        for (int ks = 0; ks < 4; ks++) {
            unsigned Bf[2][4];
#pragma unroll
            for (int bq = 0; bq < 2; bq++) {
                int brow = pg * 32 + bq * 16 + ntl + r8;
                ldsm4(Bf[bq], sb + SM_A + brow * 128 + (((ks * 32 + kb)) ^ ((brow & 7) * 16)));
            }
#pragma unroll
            for (int amt = 0; amt < 4; amt++)
#pragma unroll
                for (int nt = 0; nt < 4; nt++)
                    mma_s8u8(acc[amt][nt], Af[amt][ks], &Bf[nt >> 1][(nt & 1) * 2]);
        }

#pragma unroll
        for (int amt = 0; amt < 4; amt++)
#pragma unroll
            for (int h = 0; h < 2; h++) {
                int co = cb0 + amt * 16 + (lane >> 2) + h * 8;
                float bj = fbs[co];
                size_t base = ((size_t)n * 512 + co) * 3136;
#pragma unroll
                for (int nt = 0; nt < 4; nt++) {
                    int px = p0 + pg * 32 + nt * 8 + (lane & 3) * 2;
                    if (px < 3136) {
                        float2 o2;
                        o2.x = (float)acc[amt][nt][h * 2 + 0] * inv3 + bj;
                        o2.y = (float)acc[amt][nt][h * 2 + 1] * inv3 + bj;
                        *(float2*)(out + base + px) = o2;
                    }
                }
            }
    }
}

// ---------------- launch ----------------
extern "C" void kernel_launch(void* const* d_in, const int* in_sizes, int n_in,
                              void* d_out, int out_size)
{
    const float* x   = (const float*)d_in[0];
    const float* w1  = (const float*)d_in[1];
    const float* b1  = (const float*)d_in[2];
    const float* g1  = (const float*)d_in[3];
    const float* be1 = (const float*)d_in[4];
    const float* m1  = (const float*)d_in[5];
    const float* v1  = (const float*)d_in[6];
    const float* w2  = (const float*)d_in[7];
    const float* b2  = (const float*)d_in[8];
    const float* g2  = (const float*)d_in[9];
    const float* be2 = (const float*)d_in[10];
    const float* m2  = (const float*)d_in[11];
    const float* v2  = (const float*)d_in[12];
    const float* w3  = (const float*)d_in[13];
    const float* b3  = (const float*)d_in[14];
    const float* g3  = (const float*)d_in[15];
    const float* be3 = (const float*)d_in[16];
    const float* m3  = (const float*)d_in[17];
    const float* v3  = (const float*)d_in[18];

    cudaFuncSetAttribute(conv2_mma, cudaFuncAttributeMaxDynamicSharedMemorySize, 210432);
    cudaFuncSetAttribute(conv3_mma, cudaFuncAttributeMaxDynamicSharedMemorySize, 84480);

    prep1_kernel<<<1, 512>>>(w1, b1, g1, be1, m1, v1);
    prep2_kernel<<<1, 512>>>(w2, b2, g2, be2, m2, v2);
    prep3_kernel<<<1, 512>>>(w3, b3, g3, be3, m3, v3);

    conv1_kernel<<<dim3(25, 32), 256>>>(x);
    conv2_mma<<<128, 256, 210432>>>();
    conv3_mma<<<dim3(25, 32), 256, 84480>>>((float*)d_out);
}

// round 9
// speedup vs baseline: 1.4958x; 1.0645x over previous
#include <cuda_runtime.h>
#include <cstdint>

#define BN_EPS_F 1e-3f

__device__ __align__(16) float g_w1f[256*128];
__device__ float g_b1[128];
__device__ __align__(16) unsigned char g_w2q[9*128*128]; // [tap][co][ci] s8
__device__ float g_b2[128];
__device__ __align__(16) unsigned char g_w3q[512*128];   // [co][ci] s8
__device__ float g_b3[512];
__device__ float g_inv[2];
__device__ int   g_sync[33];                             // [0]=tile ctr, [1..32]=done[n]
__device__ __align__(16) unsigned g_act1[100352*32];     // u8 NHWC
__device__ __align__(16) unsigned g_act2[100352*32];

__device__ __forceinline__ uint32_t smem_u32(const void* p){
    uint32_t a;
    asm("{ .reg .u64 t; cvta.to.shared.u64 t, %1; cvt.u32.u64 %0, t; }" : "=r"(a) : "l"(p));
    return a;
}
#define SWZ(o) ((o) ^ (((o) >> 3) & 0x70))

__device__ __forceinline__ void ldsm4(unsigned* r, uint32_t addr){
    asm volatile("ldmatrix.sync.aligned.m8n8.x4.shared.b16 {%0,%1,%2,%3}, [%4];"
        : "=r"(r[0]), "=r"(r[1]), "=r"(r[2]), "=r"(r[3]) : "r"(addr));
}
__device__ __forceinline__ void mma_u8s8(int* d, const unsigned* a, const unsigned* b){
    asm volatile("mma.sync.aligned.m16n8k32.row.col.s32.u8.s8.s32 "
        "{%0,%1,%2,%3}, {%4,%5,%6,%7}, {%8,%9}, {%0,%1,%2,%3};"
        : "+r"(d[0]), "+r"(d[1]), "+r"(d[2]), "+r"(d[3])
        : "r"(a[0]), "r"(a[1]), "r"(a[2]), "r"(a[3]), "r"(b[0]), "r"(b[1]));
}
__device__ __forceinline__ void mma_s8u8(int* d, const unsigned* a, const unsigned* b){
    asm volatile("mma.sync.aligned.m16n8k32.row.col.s32.s8.u8.s32 "
        "{%0,%1,%2,%3}, {%4,%5,%6,%7}, {%8,%9}, {%0,%1,%2,%3};"
        : "+r"(d[0]), "+r"(d[1]), "+r"(d[2]), "+r"(d[3])
        : "r"(a[0]), "r"(a[1]), "r"(a[2]), "r"(a[3]), "r"(b[0]), "r"(b[1]));
}
#define CPA(dst, src, sz) asm volatile("cp.async.cg.shared.global [%0], [%1], 16, %2;" :: "r"(dst), "l"(src), "r"(sz) : "memory")
#define CPC()  asm volatile("cp.async.commit_group;" ::: "memory")
#define CPW(n) asm volatile("cp.async.wait_group %0;" :: "n"(n) : "memory")

// ---------------- prep ----------------
__global__ __launch_bounds__(512) void prep1_kernel(
    const float* __restrict__ w, const float* __restrict__ b,
    const float* __restrict__ g, const float* __restrict__ be,
    const float* __restrict__ m, const float* __restrict__ v)
{
    __shared__ float sc[128]; __shared__ float red[512];
    int tid = threadIdx.x;
    if (tid < 128) sc[tid] = __fdiv_rn(g[tid], __fsqrt_rn(__fadd_rn(v[tid], BN_EPS_F)));
    __syncthreads();
    float lmax = 0.f;
    for (int i = tid; i < 32768; i += 512) lmax = fmaxf(lmax, fabsf(__fmul_rn(w[i], sc[i>>8])));
    red[tid] = lmax; __syncthreads();
    for (int s = 256; s > 0; s >>= 1) { if (tid < s) red[tid] = fmaxf(red[tid], red[tid+s]); __syncthreads(); }
    float sw = __fdiv_rn(127.f, fmaxf(red[0], 1e-8f));
    __syncthreads();
    for (int i = tid; i < 32768; i += 512) {
        float wf = __fmul_rn(w[i], sc[i>>8]);
        g_w1f[(i & 255) * 128 + (i >> 8)] = __fdiv_rn(rintf(__fmul_rn(wf, sw)), sw);
    }
    float bf = 0.f;
    if (tid < 128) bf = __fadd_rn(__fmul_rn(__fsub_rn(b[tid], m[tid]), sc[tid]), be[tid]);
    red[tid] = fabsf(bf); __syncthreads();
    for (int s = 256; s > 0; s >>= 1) { if (tid < s) red[tid] = fmaxf(red[tid], red[tid+s]); __syncthreads(); }
    float sb = __fdiv_rn(32767.f, fmaxf(red[0], 1e-8f));
    if (tid < 128) g_b1[tid] = __fdiv_rn(rintf(__fmul_rn(bf, sb)), sb);
}

__global__ __launch_bounds__(512) void prep2_kernel(
    const float* __restrict__ w, const float* __restrict__ b,
    const float* __restrict__ g, const float* __restrict__ be,
    const float* __restrict__ m, const float* __restrict__ v)
{
    __shared__ float sc[128]; __shared__ float red[512];
    int tid = threadIdx.x;
    if (tid < 128) sc[tid] = __fdiv_rn(g[tid], __fsqrt_rn(__fadd_rn(v[tid], BN_EPS_F)));
    __syncthreads();
    float lmax = 0.f;
    for (int i = tid; i < 147456; i += 512) lmax = fmaxf(lmax, fabsf(__fmul_rn(w[i], sc[i/1152])));
    red[tid] = lmax; __syncthreads();
    for (int s = 256; s > 0; s >>= 1) { if (tid < s) red[tid] = fmaxf(red[tid], red[tid+s]); __syncthreads(); }
    float sw = __fdiv_rn(127.f, fmaxf(red[0], 1e-8f));
    __syncthreads();
    for (int i = tid; i < 147456; i += 512) {
        int o = i / 1152, rem = i - o * 1152, ci = rem / 9, t = rem - ci * 9;
        int q = (int)rintf(__fmul_rn(__fmul_rn(w[i], sc[o]), sw));
        ((signed char*)g_w2q)[(t * 128 + o) * 128 + ci] = (signed char)q;
    }
    float bf = 0.f;
    if (tid < 128) bf = __fadd_rn(__fmul_rn(__fsub_rn(b[tid], m[tid]), sc[tid]), be[tid]);
    red[tid] = fabsf(bf); __syncthreads();
    for (int s = 256; s > 0; s >>= 1) { if (tid < s) red[tid] = fmaxf(red[tid], red[tid+s]); __syncthreads(); }
    float sb = __fdiv_rn(32767.f, fmaxf(red[0], 1e-8f));
    if (tid < 128) g_b2[tid] = __fdiv_rn(rintf(__fmul_rn(bf, sb)), sb);
    if (tid == 0)  g_inv[0] = __fdiv_rn(1.f, __fmul_rn(sw, 25.5f));
}

__global__ __launch_bounds__(512) void prep3_kernel(
    const float* __restrict__ w, const float* __restrict__ b,
    const float* __restrict__ g, const float* __restrict__ be,
    const float* __restrict__ m, const float* __restrict__ v)
{
    __shared__ float sc[512]; __shared__ float red[512];
    int tid = threadIdx.x;
    sc[tid] = __fdiv_rn(g[tid], __fsqrt_rn(__fadd_rn(v[tid], BN_EPS_F)));
    __syncthreads();
    float lmax = 0.f;
    for (int i = tid; i < 65536; i += 512) lmax = fmaxf(lmax, fabsf(__fmul_rn(w[i], sc[i>>7])));
    red[tid] = lmax; __syncthreads();
    for (int s = 256; s > 0; s >>= 1) { if (tid < s) red[tid] = fmaxf(red[tid], red[tid+s]); __syncthreads(); }
    float sw = __fdiv_rn(127.f, fmaxf(red[0], 1e-8f));
    __syncthreads();
    for (int i = tid; i < 65536; i += 512)
        ((signed char*)g_w3q)[i] = (signed char)(int)rintf(__fmul_rn(__fmul_rn(w[i], sc[i>>7]), sw));
    float bf = __fadd_rn(__fmul_rn(__fsub_rn(b[tid], m[tid]), sc[tid]), be[tid]);
    red[tid] = fabsf(bf); __syncthreads();
    for (int s = 256; s > 0; s >>= 1) { if (tid < s) red[tid] = fmaxf(red[tid], red[tid+s]); __syncthreads(); }
    float sb = __fdiv_rn(32767.f, fmaxf(red[0], 1e-8f));
    g_b3[tid] = __fdiv_rn(rintf(__fmul_rn(bf, sb)), sb);
    if (tid == 0) g_inv[1] = __fdiv_rn(1.f, __fmul_rn(sw, 25.5f));
}

// ---------------- conv1: fp32 GEMM (unchanged, known good) ----------------
__global__ __launch_bounds__(256, 2) void conv1_kernel(const float* __restrict__ x)
{
    __shared__ float As[2][16 * 128];
    __shared__ float Ws[2][16 * 128];
    int n  = blockIdx.y;
    int p0 = blockIdx.x * 128;
    int tid = threadIdx.x;
    int tr = tid >> 4, tc = tid & 15;
    int co0 = tr * 8;
    int pxa = tc * 4, pxb = tc * 4 + 64;

    float acc[8][8];
#pragma unroll
    for (int j = 0; j < 8; j++)
#pragma unroll
        for (int q = 0; q < 8; q++) acc[j][q] = 0.f;

    const float* xn = x + ((size_t)n * 256) * 3136;
    int lr = tid >> 4;
    int lc1 = (tid & 15) * 4, lc2 = lc1 + 64;
    int pc1 = min(p0 + lc1, 3132), pc2 = min(p0 + lc2, 3132);

    float4 a1 = *(const float4*)(xn + (size_t)lr * 3136 + pc1);
    float4 a2 = *(const float4*)(xn + (size_t)lr * 3136 + pc2);
    float4 w1 = *(const float4*)(g_w1f + lr * 128 + lc1);
    float4 w2 = *(const float4*)(g_w1f + lr * 128 + lc2);
    *(float4*)(As[0] + lr * 128 + lc1) = a1;
    *(float4*)(As[0] + lr * 128 + lc2) = a2;
    *(float4*)(Ws[0] + lr * 128 + lc1) = w1;
    *(float4*)(Ws[0] + lr * 128 + lc2) = w2;
    __syncthreads();

    for (int p = 0; p < 16; p++) {
        int cur = p & 1;
        if (p < 15) {
            int kr = (p + 1) * 16 + lr;
            a1 = *(const float4*)(xn + (size_t)kr * 3136 + pc1);
            a2 = *(const float4*)(xn + (size_t)kr * 3136 + pc2);
            w1 = *(const float4*)(g_w1f + kr * 128 + lc1);
            w2 = *(const float4*)(g_w1f + kr * 128 + lc2);
        }
#pragma unroll
        for (int k = 0; k < 16; k++) {
            float4 av0 = *(const float4*)(As[cur] + k * 128 + pxa);
            float4 av1 = *(const float4*)(As[cur] + k * 128 + pxb);
            float4 wv0 = *(const float4*)(Ws[cur] + k * 128 + co0);
            float4 wv1 = *(const float4*)(Ws[cur] + k * 128 + co0 + 4);
            float wreg[8] = {wv0.x, wv0.y, wv0.z, wv0.w, wv1.x, wv1.y, wv1.z, wv1.w};
            float areg[8] = {av0.x, av0.y, av0.z, av0.w, av1.x, av1.y, av1.z, av1.w};
#pragma unroll
            for (int j = 0; j < 8; j++)
#pragma unroll
                for (int q = 0; q < 8; q++)
                    acc[j][q] += wreg[j] * areg[q];
        }
        if (p < 15) {
            int nxt = 1 - cur;
            *(float4*)(As[nxt] + lr * 128 + lc1) = a1;
            *(float4*)(As[nxt] + lr * 128 + lc2) = a2;
            *(float4*)(Ws[nxt] + lr * 128 + lc1) = w1;
            *(float4*)(Ws[nxt] + lr * 128 + lc2) = w2;
            __syncthreads();
        }
    }

    float bias[8];
#pragma unroll
    for (int j = 0; j < 8; j++) bias[j] = g_b1[co0 + j];
#pragma unroll
    for (int q = 0; q < 8; q++) {
        int p = p0 + (q < 4 ? (pxa + q) : (pxb + q - 4));
        if (p >= 3136) continue;
        unsigned b0 = 0, b1 = 0;
#pragma unroll
        for (int j = 0; j < 8; j++) {
            float vv = acc[j][q] + bias[j];
            vv = fminf(fmaxf(vv, 0.f), 10.f);
            unsigned a = (unsigned)(int)rintf(vv * 25.5f);
            if (j < 4) b0 |= a << (8 * j); else b1 |= a << (8 * (j - 4));
        }
        *(uint2*)&g_act1[((unsigned)(n * 3136 + p)) * 32 + tr * 2] = make_uint2(b0, b1);
    }
}

// ---------------- fused conv2+conv3: persistent, atomic tile counter ----------------
// tiles [0,896): conv2 128px x 128co; tiles [896,2464): conv3 64px x 512co (gated on done[n]==28)
__global__ __launch_bounds__(256, 1) void conv23_mma(float* __restrict__ out)
{
    extern __shared__ char smem[];
    const uint32_t SM_W = 0, SM_A0 = 147456, SM_A1 = 170496, SM_ST = 193536, SM_FB = 209920;
    __shared__ int s_next;
    uint32_t sb = smem_u32(smem);
    int tid = threadIdx.x, wid = tid >> 5, lane = tid & 31;

    // load conv2 weights
    for (int u = tid; u < 9216; u += 256) {
        uint4 wv = *(const uint4*)(g_w2q + u * 16);
        *(uint4*)(smem + SM_W + SWZ(u * 16)) = wv;
    }
    if (tid < 128) ((float*)(smem + SM_FB))[tid] = g_b2[tid];
    float inv2 = g_inv[0];
    float inv3 = g_inv[1];

    int wrb = (wid & 3) * 32, wcb = (wid >> 2) * 64;
    int sub = lane >> 3, r8 = lane & 7;
    int row8 = (sub & 1) * 8, kh = (sub >> 1) * 16;
    int rowb = (sub >> 1) * 8, khb = (sub & 1) * 16;

    int yym[2], xxm[2];
#pragma unroll
    for (int mt = 0; mt < 2; mt++) {
        int px = wrb + mt * 16 + row8 + r8;
        yym[mt] = px >> 4; xxm[mt] = px & 15;
    }
    uint32_t wbb[4]; int wxx[4];
#pragma unroll
    for (int bt = 0; bt < 4; bt++) {
        int co = wcb + bt * 16 + rowb + r8;
        wbb[bt] = sb + SM_W + co * 128;
        wxx[bt] = (co & 7) * 16;
    }

#define HALO_LOAD(DSTBASE, N_, Y0_, X0_) do { \
    for (int u = tid; u < 1440; u += 256) { \
        int hrow = u >> 3, c16 = u & 7; \
        int iy = hrow / 18, ix = hrow - iy * 18; \
        int gy = (Y0_) + iy - 1, gx = (X0_) + ix - 1; \
        bool ok = (gy >= 0 && gy < 56 && gx >= 0 && gx < 56); \
        const void* src = ok ? (const void*)&g_act1[((unsigned)((N_) * 3136 + gy * 56 + gx)) * 32 + c16 * 4] \
                             : (const void*)g_act1; \
        CPA((DSTBASE) + SWZ(hrow * 128 + c16 * 16), src, ok ? 16u : 0u); \
    } } while (0)

    // first grab + prefetch
    if (tid == 0) s_next = atomicAdd(&g_sync[0], 1);
    __syncthreads();
    int t = s_next;
    int buf = 0;
    if (t < 896) {
        int n = t / 28, r = t - n * 28;
        int y0 = (r >> 2) * 8, tx = r & 3;
        int x0 = (tx < 3) ? tx * 16 : 40;
        HALO_LOAD(sb + SM_A0, n, y0, x0);
        CPC();
    }

    // ===== conv2 phase =====
    while (t < 896) {
        int n = t / 28, r = t - n * 28;
        int y0 = (r >> 2) * 8, tx = r & 3;
        int x0 = (tx < 3) ? tx * 16 : 40;
        uint32_t aBase = sb + (buf ? SM_A1 : SM_A0);

        if (tid == 0) s_next = atomicAdd(&g_sync[0], 1);
        __syncthreads();
        int t2 = s_next;
        if (t2 < 896) {
            int n2 = t2 / 28, r2n = t2 - n2 * 28;
            int y2 = (r2n >> 2) * 8, tx2 = r2n & 3;
            int x2 = (tx2 < 3) ? tx2 * 16 : 40;
            HALO_LOAD(sb + (buf ? SM_A0 : SM_A1), n2, y2, x2);
            CPC();
            CPW(1);
        } else {
            CPW(0);
        }
        __syncthreads();

        int acc[2][8][4];
#pragma unroll
        for (int mt = 0; mt < 2; mt++)
#pragma unroll
            for (int nt = 0; nt < 8; nt++)
#pragma unroll
                for (int q = 0; q < 4; q++) acc[mt][nt][q] = 0;

        for (int dy = 0; dy < 3; dy++)
            for (int dx = 0; dx < 3; dx++) {
                uint32_t ab[2]; int axx[2];
#pragma unroll
                for (int mt = 0; mt < 2; mt++) {
                    int hrow = (yym[mt] + dy) * 18 + xxm[mt] + dx;
                    ab[mt] = aBase + hrow * 128;
                    axx[mt] = (hrow & 7) * 16;
                }
                uint32_t wtap = (dy * 3 + dx) * 16384;
#pragma unroll
                for (int ks = 0; ks < 4; ks++) {
                    unsigned A0[4], A1[4], B[4][4];
                    ldsm4(A0, ab[0] + ((ks * 32 + kh) ^ axx[0]));
                    ldsm4(A1, ab[1] + ((ks * 32 + kh) ^ axx[1]));
#pragma unroll
                    for (int bt = 0; bt < 4; bt++)
                        ldsm4(B[bt], wbb[bt] + wtap + ((ks * 32 + khb) ^ wxx[bt]));
#pragma unroll
                    for (int nt = 0; nt < 8; nt++) {
                        const unsigned* bp = &B[nt >> 1][(nt & 1) * 2];
                        mma_u8s8(acc[0][nt], A0, bp);
                        mma_u8s8(acc[1][nt], A1, bp);
                    }
                }
            }

        const float* fbs = (const float*)(smem + SM_FB);
#pragma unroll
        for (int mt = 0; mt < 2; mt++)
#pragma unroll
            for (int h = 0; h < 2; h++) {
                int px = wrb + mt * 16 + (lane >> 2) + h * 8;
#pragma unroll
                for (int nt = 0; nt < 8; nt++) {
                    int co = wcb + nt * 8 + (lane & 3) * 2;
                    float v0 = (float)acc[mt][nt][h * 2 + 0] * inv2 + fbs[co];
                    float v1 = (float)acc[mt][nt][h * 2 + 1] * inv2 + fbs[co + 1];
                    v0 = fminf(fmaxf(v0, 0.f), 10.f);
                    v1 = fminf(fmaxf(v1, 0.f), 10.f);
                    unsigned u0 = (unsigned)(int)rintf(v0 * 25.5f);
                    unsigned u1 = (unsigned)(int)rintf(v1 * 25.5f);
                    *(unsigned short*)(smem + SM_ST + px * 128 + (co ^ ((px & 7) * 16))) =
                        (unsigned short)(u0 | (u1 << 8));
                }
            }
        __syncthreads();

        for (int u = tid; u < 1024; u += 256) {
            int px = u >> 3, c16 = u & 7;
            int yy = px >> 4, xx = px & 15;
            unsigned gp = (unsigned)(n * 3136 + (y0 + yy) * 56 + (x0 + xx));
            *(uint4*)&g_act2[gp * 32 + c16 * 4] =
                *(const uint4*)(smem + SM_ST + px * 128 + ((c16 * 16) ^ ((px & 7) * 16)));
        }
        __threadfence();
        __syncthreads();
        if (tid == 0) atomicAdd(&g_sync[1 + n], 1);

        t = t2; buf ^= 1;
    }
#undef HALO_LOAD

    // ===== conv3 phase =====
    __syncthreads();
    for (int u = tid; u < 4096; u += 256) {       // 512 co rows x 128B
        uint4 wv = *(const uint4*)(g_w3q + u * 16);
        *(uint4*)(smem + SM_W + SWZ(u * 16)) = wv;
    }
    if (tid < 128) ((float4*)(smem + SM_ST))[tid] = *(const float4*)&g_b3[tid * 4];
    __syncthreads();

    const float* fb3 = (const float*)(smem + SM_ST);
    int cb0 = wid * 64;
    int ntl = (sub >> 1) * 8, kb = (sub & 1) * 16;

    unsigned Af[4][4][4];
#pragma unroll
    for (int amt = 0; amt < 4; amt++) {
        int co = cb0 + amt * 16 + row8 + r8;
        uint32_t base = sb + SM_W + co * 128;
        int xx = (co & 7) * 16;
#pragma unroll
        for (int ks = 0; ks < 4; ks++)
            ldsm4(Af[amt][ks], base + ((ks * 32 + kh) ^ xx));
    }

    while (t < 2464) {
        int tt = t - 896;
        int n = tt / 49, p0 = (tt - n * 49) * 64;

        if (tid == 0) { while (((volatile int*)g_sync)[1 + n] < 28) { } }
        __syncthreads();
        __threadfence();

        for (int u = tid; u < 512; u += 256) {    // 64 px rows x 128B
            int pix = u >> 3, c16 = u & 7;
            uint4 vv = *(const uint4*)&g_act2[((unsigned)(n * 3136 + p0 + pix)) * 32 + c16 * 4];
            *(uint4*)(smem + SM_A0 + SWZ(pix * 128 + c16 * 16)) = vv;
        }
        __syncthreads();

        for (int pg = 0; pg < 2; pg++) {
            int acc[4][4][4];
#pragma unroll
            for (int a = 0; a < 4; a++)
#pragma unroll
                for (int b = 0; b < 4; b++)
#pragma unroll
                    for (int q = 0; q < 4; q++) acc[a][b][q] = 0;

#pragma unroll
            for (int ks = 0; ks < 4; ks++) {
                unsigned Bf[2][4];
#pragma unroll
                for (int bq = 0; bq < 2; bq++) {
                    int brow = pg * 32 + bq * 16 + ntl + r8;
                    ldsm4(Bf[bq], sb + SM_A0 + brow * 128 + (((ks * 32 + kb)) ^ ((brow & 7) * 16)));
                }
#pragma unroll
                for (int amt = 0; amt < 4; amt++)
#pragma unroll
                    for (int nt = 0; nt < 4; nt++)
                        mma_s8u8(acc[amt][nt], Af[amt][ks], &Bf[nt >> 1][(nt & 1) * 2]);
            }

#pragma unroll
            for (int amt = 0; amt < 4; amt++)
#pragma unroll
                for (int h = 0; h < 2; h++) {
                    int co = cb0 + amt * 16 + (lane >> 2) + h * 8;
                    float bj = fb3[co];
                    size_t base = ((size_t)n * 512 + co) * 3136;
#pragma unroll
                    for (int nt = 0; nt < 4; nt++) {
                        int px = p0 + pg * 32 + nt * 8 + (lane & 3) * 2;
                        float2 o2;
                        o2.x = (float)acc[amt][nt][h * 2 + 0] * inv3 + bj;
                        o2.y = (float)acc[amt][nt][h * 2 + 1] * inv3 + bj;
                        *(float2*)(out + base + px) = o2;
                    }
                }
        }

        if (tid == 0) s_next = atomicAdd(&g_sync[0], 1);
        __syncthreads();
        t = s_next;
    }
}

// ---------------- launch ----------------
extern "C" void kernel_launch(void* const* d_in, const int* in_sizes, int n_in,
                              void* d_out, int out_size)
{
    const float* x   = (const float*)d_in[0];
    const float* w1  = (const float*)d_in[1];
    const float* b1  = (const float*)d_in[2];
    const float* g1  = (const float*)d_in[3];
    const float* be1 = (const float*)d_in[4];
    const float* m1  = (const float*)d_in[5];
    const float* v1  = (const float*)d_in[6];
    const float* w2  = (const float*)d_in[7];
    const float* b2  = (const float*)d_in[8];
    const float* g2  = (const float*)d_in[9];
    const float* be2 = (const float*)d_in[10];
    const float* m2  = (const float*)d_in[11];
    const float* v2  = (const float*)d_in[12];
    const float* w3  = (const float*)d_in[13];
    const float* b3  = (const float*)d_in[14];
    const float* g3  = (const float*)d_in[15];
    const float* be3 = (const float*)d_in[16];
    const float* m3  = (const float*)d_in[17];
    const float* v3  = (const float*)d_in[18];

    cudaFuncSetAttribute(conv23_mma, cudaFuncAttributeMaxDynamicSharedMemorySize, 210432);

    void* syncAddr = nullptr;
    cudaGetSymbolAddress(&syncAddr, g_sync);
    cudaMemsetAsync(syncAddr, 0, 33 * sizeof(int));

    prep1_kernel<<<1, 512>>>(w1, b1, g1, be1, m1, v1);
    prep2_kernel<<<1, 512>>>(w2, b2, g2, be2, m2, v2);
    prep3_kernel<<<1, 512>>>(w3, b3, g3, be3, m3, v3);

    conv1_kernel<<<dim3(25, 32), 256>>>(x);
    conv23_mma<<<152, 256, 210432>>>((float*)d_out);
}

// round 10
// speedup vs baseline: 1.5509x; 1.0368x over previous
#include <cuda_runtime.h>
#include <cstdint>

#define BN_EPS_F 1e-3f

__device__ __align__(16) float g_w1f[256*128];
__device__ float g_b1[128];
__device__ __align__(16) unsigned char g_w2q[9*128*128]; // [tap][co][ci] s8
__device__ float g_b2[128];
__device__ __align__(16) unsigned char g_w3q[512*128];   // [co][ci] s8
__device__ float g_b3[512];
__device__ float g_inv[2];
__device__ int   g_sync[65];   // [0]=ctr, [1..32]=done1[n], [33..64]=done2[n]
__device__ __align__(16) unsigned g_act1[100352*32];
__device__ __align__(16) unsigned g_act2[100352*32];

__device__ __forceinline__ uint32_t smem_u32(const void* p){
    uint32_t a;
    asm("{ .reg .u64 t; cvta.to.shared.u64 t, %1; cvt.u32.u64 %0, t; }" : "=r"(a) : "l"(p));
    return a;
}
#define SWZ(o) ((o) ^ (((o) >> 3) & 0x70))

__device__ __forceinline__ void ldsm4(unsigned* r, uint32_t addr){
    asm volatile("ldmatrix.sync.aligned.m8n8.x4.shared.b16 {%0,%1,%2,%3}, [%4];"
        : "=r"(r[0]), "=r"(r[1]), "=r"(r[2]), "=r"(r[3]) : "r"(addr));
}
__device__ __forceinline__ void mma_u8s8(int* d, const unsigned* a, const unsigned* b){
    asm volatile("mma.sync.aligned.m16n8k32.row.col.s32.u8.s8.s32 "
        "{%0,%1,%2,%3}, {%4,%5,%6,%7}, {%8,%9}, {%0,%1,%2,%3};"
        : "+r"(d[0]), "+r"(d[1]), "+r"(d[2]), "+r"(d[3])
        : "r"(a[0]), "r"(a[1]), "r"(a[2]), "r"(a[3]), "r"(b[0]), "r"(b[1]));
}
__device__ __forceinline__ void mma_s8u8(int* d, const unsigned* a, const unsigned* b){
    asm volatile("mma.sync.aligned.m16n8k32.row.col.s32.s8.u8.s32 "
        "{%0,%1,%2,%3}, {%4,%5,%6,%7}, {%8,%9}, {%0,%1,%2,%3};"
        : "+r"(d[0]), "+r"(d[1]), "+r"(d[2]), "+r"(d[3])
        : "r"(a[0]), "r"(a[1]), "r"(a[2]), "r"(a[3]), "r"(b[0]), "r"(b[1]));
}
#define CPA(dst, src, sz) asm volatile("cp.async.cg.shared.global [%0], [%1], 16, %2;" :: "r"(dst), "l"(src), "r"(sz) : "memory")
#define CPC()  asm volatile("cp.async.commit_group;" ::: "memory")
#define CPW(n) asm volatile("cp.async.wait_group %0;" :: "n"(n) : "memory")

// ---------------- prep: all three in one kernel (block = role) ----------------
__global__ __launch_bounds__(512) void prep_all(
    const float* __restrict__ w1, const float* __restrict__ b1,
    const float* __restrict__ g1, const float* __restrict__ be1,
    const float* __restrict__ m1, const float* __restrict__ v1,
    const float* __restrict__ w2, const float* __restrict__ b2,
    const float* __restrict__ g2, const float* __restrict__ be2,
    const float* __restrict__ m2, const float* __restrict__ v2,
    const float* __restrict__ w3, const float* __restrict__ b3,
    const float* __restrict__ g3, const float* __restrict__ be3,
    const float* __restrict__ m3, const float* __restrict__ v3)
{
    __shared__ float sc[512]; __shared__ float red[512];
    int tid = threadIdx.x;
    if (blockIdx.x == 0) {
        if (tid < 128) sc[tid] = __fdiv_rn(g1[tid], __fsqrt_rn(__fadd_rn(v1[tid], BN_EPS_F)));
        __syncthreads();
        float lmax = 0.f;
        for (int i = tid; i < 32768; i += 512) lmax = fmaxf(lmax, fabsf(__fmul_rn(w1[i], sc[i>>8])));
        red[tid] = lmax; __syncthreads();
        for (int s = 256; s > 0; s >>= 1) { if (tid < s) red[tid] = fmaxf(red[tid], red[tid+s]); __syncthreads(); }
        float sw = __fdiv_rn(127.f, fmaxf(red[0], 1e-8f));
        __syncthreads();
        for (int i = tid; i < 32768; i += 512) {
            float wf = __fmul_rn(w1[i], sc[i>>8]);
            g_w1f[(i & 255) * 128 + (i >> 8)] = __fdiv_rn(rintf(__fmul_rn(wf, sw)), sw);
        }
        float bf = 0.f;
        if (tid < 128) bf = __fadd_rn(__fmul_rn(__fsub_rn(b1[tid], m1[tid]), sc[tid]), be1[tid]);
        red[tid] = fabsf(bf); __syncthreads();
        for (int s = 256; s > 0; s >>= 1) { if (tid < s) red[tid] = fmaxf(red[tid], red[tid+s]); __syncthreads(); }
        float sb = __fdiv_rn(32767.f, fmaxf(red[0], 1e-8f));
        if (tid < 128) g_b1[tid] = __fdiv_rn(rintf(__fmul_rn(bf, sb)), sb);
    } else if (blockIdx.x == 1) {
        if (tid < 128) sc[tid] = __fdiv_rn(g2[tid], __fsqrt_rn(__fadd_rn(v2[tid], BN_EPS_F)));
        __syncthreads();
        float lmax = 0.f;
        for (int i = tid; i < 147456; i += 512) lmax = fmaxf(lmax, fabsf(__fmul_rn(w2[i], sc[i/1152])));
        red[tid] = lmax; __syncthreads();
        for (int s = 256; s > 0; s >>= 1) { if (tid < s) red[tid] = fmaxf(red[tid], red[tid+s]); __syncthreads(); }
        float sw = __fdiv_rn(127.f, fmaxf(red[0], 1e-8f));
        __syncthreads();
        for (int i = tid; i < 147456; i += 512) {
            int o = i / 1152, rem = i - o * 1152, ci = rem / 9, t = rem - ci * 9;
            int q = (int)rintf(__fmul_rn(__fmul_rn(w2[i], sc[o]), sw));
            ((signed char*)g_w2q)[(t * 128 + o) * 128 + ci] = (signed char)q;
        }
        float bf = 0.f;
        if (tid < 128) bf = __fadd_rn(__fmul_rn(__fsub_rn(b2[tid], m2[tid]), sc[tid]), be2[tid]);
        red[tid] = fabsf(bf); __syncthreads();
        for (int s = 256; s > 0; s >>= 1) { if (tid < s) red[tid] = fmaxf(red[tid], red[tid+s]); __syncthreads(); }
        float sb = __fdiv_rn(32767.f, fmaxf(red[0], 1e-8f));
        if (tid < 128) g_b2[tid] = __fdiv_rn(rintf(__fmul_rn(bf, sb)), sb);
        if (tid == 0)  g_inv[0] = __fdiv_rn(1.f, __fmul_rn(sw, 25.5f));
    } else {
        sc[tid] = __fdiv_rn(g3[tid], __fsqrt_rn(__fadd_rn(v3[tid], BN_EPS_F)));
        __syncthreads();
        float lmax = 0.f;
        for (int i = tid; i < 65536; i += 512) lmax = fmaxf(lmax, fabsf(__fmul_rn(w3[i], sc[i>>7])));
        red[tid] = lmax; __syncthreads();
        for (int s = 256; s > 0; s >>= 1) { if (tid < s) red[tid] = fmaxf(red[tid], red[tid+s]); __syncthreads(); }
        float sw = __fdiv_rn(127.f, fmaxf(red[0], 1e-8f));
        __syncthreads();
        for (int i = tid; i < 65536; i += 512)
            ((signed char*)g_w3q)[i] = (signed char)(int)rintf(__fmul_rn(__fmul_rn(w3[i], sc[i>>7]), sw));
        float bf = __fadd_rn(__fmul_rn(__fsub_rn(b3[tid], m3[tid]), sc[tid]), be3[tid]);
        red[tid] = fabsf(bf); __syncthreads();
        for (int s = 256; s > 0; s >>= 1) { if (tid < s) red[tid] = fmaxf(red[tid], red[tid+s]); __syncthreads(); }
        float sb = __fdiv_rn(32767.f, fmaxf(red[0], 1e-8f));
        g_b3[tid] = __fdiv_rn(rintf(__fmul_rn(bf, sb)), sb);
        if (tid == 0) g_inv[1] = __fdiv_rn(1.f, __fmul_rn(sw, 25.5f));
    }
}

// ---------------- fully fused persistent kernel: conv1 -> conv2 -> conv3 ----------------
// tiles [0,800): conv1 128px; [800,1696): conv2 128px (gate done1[n]==25);
// [1696,3264): conv3 64px (gate done2[n]==28)
__global__ __launch_bounds__(256, 1) void conv_fused(const float* __restrict__ x,
                                                     float* __restrict__ out)
{
    extern __shared__ char smem[];
    const uint32_t SM_W = 0, SM_A0 = 147456, SM_A1 = 170496, SM_FB = 193536;
    __shared__ int s_next;
    uint32_t sb = smem_u32(smem);
    int tid = threadIdx.x, wid = tid >> 5, lane = tid & 31;

    // conv2 weights + b2
    for (int u = tid; u < 9216; u += 256) {
        uint4 wv = *(const uint4*)(g_w2q + u * 16);
        *(uint4*)(smem + SM_W + SWZ(u * 16)) = wv;
    }
    if (tid < 128) ((float*)(smem + SM_FB))[tid] = g_b2[tid];
    float inv2 = g_inv[0], inv3 = g_inv[1];

    // fragment lane mappings (conv2/conv3)
    int wrb = (wid & 3) * 32, wcb = (wid >> 2) * 64;
    int sub = lane >> 3, r8 = lane & 7;
    int row8 = (sub & 1) * 8, kh = (sub >> 1) * 16;
    int rowb = (sub >> 1) * 8, khb = (sub & 1) * 16;

    int yym[2], xxm[2];
#pragma unroll
    for (int mt = 0; mt < 2; mt++) {
        int px = wrb + mt * 16 + row8 + r8;
        yym[mt] = px >> 4; xxm[mt] = px & 15;
    }
    uint32_t wbb[4]; int wxx[4];
#pragma unroll
    for (int bt = 0; bt < 4; bt++) {
        int co = wcb + bt * 16 + rowb + r8;
        wbb[bt] = sb + SM_W + co * 128;
        wxx[bt] = (co & 7) * 16;
    }

    if (tid == 0) s_next = atomicAdd(&g_sync[0], 1);
    __syncthreads();
    int t = s_next;

    // ================= phase 1: conv1 (fp32 FFMA) =================
    {
        float* Asb = (float*)(smem + SM_A0);   // 2 x 2048 floats
        float* Wsb = Asb + 4096;               // 2 x 2048 floats
        int tr = tid >> 4, tc = tid & 15;
        int co0 = tr * 8;
        int pxa = tc * 4, pxb = tc * 4 + 64;
        int lr = tid >> 4;
        int lc1 = (tid & 15) * 4, lc2 = lc1 + 64;

        while (t < 800) {
            int n = t / 25, p0 = (t - n * 25) * 128;
            const float* xn = x + ((size_t)n * 256) * 3136;
            int pc1 = min(p0 + lc1, 3132), pc2 = min(p0 + lc2, 3132);

            float acc[8][8];
#pragma unroll
            for (int j = 0; j < 8; j++)
#pragma unroll
                for (int q = 0; q < 8; q++) acc[j][q] = 0.f;

            float4 a1 = *(const float4*)(xn + (size_t)lr * 3136 + pc1);
            float4 a2 = *(const float4*)(xn + (size_t)lr * 3136 + pc2);
            float4 w1 = *(const float4*)(g_w1f + lr * 128 + lc1);
            float4 w2 = *(const float4*)(g_w1f + lr * 128 + lc2);
            *(float4*)(Asb + lr * 128 + lc1) = a1;
            *(float4*)(Asb + lr * 128 + lc2) = a2;
            *(float4*)(Wsb + lr * 128 + lc1) = w1;
            *(float4*)(Wsb + lr * 128 + lc2) = w2;
            __syncthreads();

            for (int p = 0; p < 16; p++) {
                int cu = (p & 1) * 2048;
                if (p < 15) {
                    int kr = (p + 1) * 16 + lr;
                    a1 = *(const float4*)(xn + (size_t)kr * 3136 + pc1);
                    a2 = *(const float4*)(xn + (size_t)kr * 3136 + pc2);
                    w1 = *(const float4*)(g_w1f + kr * 128 + lc1);
                    w2 = *(const float4*)(g_w1f + kr * 128 + lc2);
                }
#pragma unroll
                for (int k = 0; k < 16; k++) {
                    float4 av0 = *(const float4*)(Asb + cu + k * 128 + pxa);
                    float4 av1 = *(const float4*)(Asb + cu + k * 128 + pxb);
                    float4 wv0 = *(const float4*)(Wsb + cu + k * 128 + co0);
                    float4 wv1 = *(const float4*)(Wsb + cu + k * 128 + co0 + 4);
                    float wreg[8] = {wv0.x, wv0.y, wv0.z, wv0.w, wv1.x, wv1.y, wv1.z, wv1.w};
                    float areg[8] = {av0.x, av0.y, av0.z, av0.w, av1.x, av1.y, av1.z, av1.w};
#pragma unroll
                    for (int j = 0; j < 8; j++)
#pragma unroll
                        for (int q = 0; q < 8; q++)
                            acc[j][q] += wreg[j] * areg[q];
                }
                if (p < 15) {
                    int nx = ((p + 1) & 1) * 2048;
                    *(float4*)(Asb + nx + lr * 128 + lc1) = a1;
                    *(float4*)(Asb + nx + lr * 128 + lc2) = a2;
                    *(float4*)(Wsb + nx + lr * 128 + lc1) = w1;
                    *(float4*)(Wsb + nx + lr * 128 + lc2) = w2;
                    __syncthreads();
                }
            }

            float bias[8];
#pragma unroll
            for (int j = 0; j < 8; j++) bias[j] = g_b1[co0 + j];
#pragma unroll
            for (int q = 0; q < 8; q++) {
                int p = p0 + (q < 4 ? (pxa + q) : (pxb + q - 4));
                if (p >= 3136) continue;
                unsigned b0 = 0, b1v = 0;
#pragma unroll
                for (int j = 0; j < 8; j++) {
                    float vv = acc[j][q] + bias[j];
                    vv = fminf(fmaxf(vv, 0.f), 10.f);
                    unsigned a = (unsigned)(int)rintf(vv * 25.5f);
                    if (j < 4) b0 |= a << (8 * j); else b1v |= a << (8 * (j - 4));
                }
                *(uint2*)&g_act1[((unsigned)(n * 3136 + p)) * 32 + tr * 2] = make_uint2(b0, b1v);
            }
            __threadfence();
            __syncthreads();
            if (tid == 0) { atomicAdd(&g_sync[1 + n], 1); s_next = atomicAdd(&g_sync[0], 1); }
            __syncthreads();
            t = s_next;
        }
    }

#define HALO_LOAD(DSTBASE, N_, Y0_, X0_) do { \
    for (int u = tid; u < 1440; u += 256) { \
        int hrow = u >> 3, c16 = u & 7; \
        int iy = hrow / 18, ix = hrow - iy * 18; \
        int gy = (Y0_) + iy - 1, gx = (X0_) + ix - 1; \
        bool ok = (gy >= 0 && gy < 56 && gx >= 0 && gx < 56); \
        const void* src = ok ? (const void*)&g_act1[((unsigned)((N_) * 3136 + gy * 56 + gx)) * 32 + c16 * 4] \
                             : (const void*)g_act1; \
        CPA((DSTBASE) + SWZ(hrow * 128 + c16 * 16), src, ok ? 16u : 0u); \
    } } while (0)

    // ================= phase 2: conv2 (int8 mma) =================
    if (t < 1696) {
        int buf = 0;
        {   // gate + prefetch first tile
            int q = t - 800, n = q / 28, r = q - n * 28;
            if (tid == 0) { while (((volatile int*)g_sync)[1 + n] < 25) {} }
            __syncthreads(); __threadfence();
            int y0 = (r >> 2) * 8, tx = r & 3;
            int x0 = (tx < 3) ? tx * 16 : 40;
            HALO_LOAD(sb + SM_A0, n, y0, x0);
            CPC();
        }
        while (t < 1696) {
            int q = t - 800, n = q / 28, r = q - n * 28;
            int y0 = (r >> 2) * 8, tx = r & 3;
            int x0 = (tx < 3) ? tx * 16 : 40;
            uint32_t aBase = sb + (buf ? SM_A1 : SM_A0);
            char* stg = smem + (buf ? SM_A1 : SM_A0);

            if (tid == 0) s_next = atomicAdd(&g_sync[0], 1);
            __syncthreads();
            int t2 = s_next;
            if (t2 < 1696) {
                int q2 = t2 - 800, n2 = q2 / 28, r2n = q2 - n2 * 28;
                if (tid == 0) { while (((volatile int*)g_sync)[1 + n2] < 25) {} }
                __syncthreads(); __threadfence();
                int y2 = (r2n >> 2) * 8, tx2 = r2n & 3;
                int x2 = (tx2 < 3) ? tx2 * 16 : 40;
                HALO_LOAD(sb + (buf ? SM_A0 : SM_A1), n2, y2, x2);
                CPC(); CPW(1);
            } else {
                CPW(0);
            }
            __syncthreads();

            int acc[2][8][4];
#pragma unroll
            for (int mt = 0; mt < 2; mt++)
#pragma unroll
                for (int nt = 0; nt < 8; nt++)
#pragma unroll
                    for (int qq = 0; qq < 4; qq++) acc[mt][nt][qq] = 0;

            for (int dy = 0; dy < 3; dy++)
                for (int dx = 0; dx < 3; dx++) {
                    uint32_t ab[2]; int axx[2];
#pragma unroll
                    for (int mt = 0; mt < 2; mt++) {
                        int hrow = (yym[mt] + dy) * 18 + xxm[mt] + dx;
                        ab[mt] = aBase + hrow * 128;
                        axx[mt] = (hrow & 7) * 16;
                    }
                    uint32_t wtap = (dy * 3 + dx) * 16384;
#pragma unroll
                    for (int ks = 0; ks < 4; ks++) {
                        unsigned A0[4], A1[4], B[4][4];
                        ldsm4(A0, ab[0] + ((ks * 32 + kh) ^ axx[0]));
                        ldsm4(A1, ab[1] + ((ks * 32 + kh) ^ axx[1]));
#pragma unroll
                        for (int bt = 0; bt < 4; bt++)
                            ldsm4(B[bt], wbb[bt] + wtap + ((ks * 32 + khb) ^ wxx[bt]));
#pragma unroll
                        for (int nt = 0; nt < 8; nt++) {
                            const unsigned* bp = &B[nt >> 1][(nt & 1) * 2];
                            mma_u8s8(acc[0][nt], A0, bp);
                            mma_u8s8(acc[1][nt], A1, bp);
                        }
                    }
                }

            __syncthreads();   // all halo reads done before reusing the buffer as staging
            const float* fbs = (const float*)(smem + SM_FB);
#pragma unroll
            for (int mt = 0; mt < 2; mt++)
#pragma unroll
                for (int h = 0; h < 2; h++) {
                    int px = wrb + mt * 16 + (lane >> 2) + h * 8;
#pragma unroll
                    for (int nt = 0; nt < 8; nt++) {
                        int co = wcb + nt * 8 + (lane & 3) * 2;
                        float v0 = (float)acc[mt][nt][h * 2 + 0] * inv2 + fbs[co];
                        float v1 = (float)acc[mt][nt][h * 2 + 1] * inv2 + fbs[co + 1];
                        v0 = fminf(fmaxf(v0, 0.f), 10.f);
                        v1 = fminf(fmaxf(v1, 0.f), 10.f);
                        unsigned u0 = (unsigned)(int)rintf(v0 * 25.5f);
                        unsigned u1 = (unsigned)(int)rintf(v1 * 25.5f);
                        *(unsigned short*)(stg + px * 128 + (co ^ ((px & 7) * 16))) =
                            (unsigned short)(u0 | (u1 << 8));
                    }
                }
            __syncthreads();

            for (int u = tid; u < 1024; u += 256) {
                int px = u >> 3, c16 = u & 7;
                int yy = px >> 4, xx = px & 15;
                unsigned gp = (unsigned)(n * 3136 + (y0 + yy) * 56 + (x0 + xx));
                *(uint4*)&g_act2[gp * 32 + c16 * 4] =
                    *(const uint4*)(stg + px * 128 + ((c16 * 16) ^ ((px & 7) * 16)));
            }
            __threadfence();
            __syncthreads();
            if (tid == 0) atomicAdd(&g_sync[33 + n], 1);

            t = t2; buf ^= 1;
        }
    }
#undef HALO_LOAD

    // ================= phase 3: conv3 (int8 mma) =================
    if (t < 3264) {
        __syncthreads();
        for (int u = tid; u < 4096; u += 256) {       // W3: 512 co x 128B
            uint4 wv = *(const uint4*)(g_w3q + u * 16);
            *(uint4*)(smem + SM_W + SWZ(u * 16)) = wv;
        }
        if (tid < 128) ((float4*)(smem + SM_FB + 512))[tid] = *(const float4*)&g_b3[tid * 4];
        __syncthreads();

        const float* fb3 = (const float*)(smem + SM_FB + 512);
        int cb0 = wid * 64;
        int ntl = (sub >> 1) * 8, kb = (sub & 1) * 16;

        unsigned Af[4][4][4];
#pragma unroll
        for (int amt = 0; amt < 4; amt++) {
            int co = cb0 + amt * 16 + row8 + r8;
            uint32_t base = sb + SM_W + co * 128;
            int xx = (co & 7) * 16;
#pragma unroll
            for (int ks = 0; ks < 4; ks++)
                ldsm4(Af[amt][ks], base + ((ks * 32 + kh) ^ xx));
        }

        while (t < 3264) {
            int u0 = t - 1696;
            int n = u0 / 49, p0 = (u0 - n * 49) * 64;

            if (tid == 0) { while (((volatile int*)g_sync)[33 + n] < 28) {} }
            __syncthreads();
            __threadfence();

            for (int u = tid; u < 512; u += 256) {
                int pix = u >> 3, c16 = u & 7;
                uint4 vv = *(const uint4*)&g_act2[((unsigned)(n * 3136 + p0 + pix)) * 32 + c16 * 4];
                *(uint4*)(smem + SM_A0 + SWZ(pix * 128 + c16 * 16)) = vv;
            }
            __syncthreads();

            for (int pg = 0; pg < 2; pg++) {
                int acc[4][4][4];
#pragma unroll
                for (int a = 0; a < 4; a++)
#pragma unroll
                    for (int b = 0; b < 4; b++)
#pragma unroll
                        for (int qq = 0; qq < 4; qq++) acc[a][b][qq] = 0;

#pragma unroll
                for (int ks = 0; ks < 4; ks++) {
                    unsigned Bf[2][4];
#pragma unroll
                    for (int bq = 0; bq < 2; bq++) {
                        int brow = pg * 32 + bq * 16 + ntl + r8;
                        ldsm4(Bf[bq], sb + SM_A0 + brow * 128 + (((ks * 32 + kb)) ^ ((brow & 7) * 16)));
                    }
#pragma unroll
                    for (int amt = 0; amt < 4; amt++)
#pragma unroll
                        for (int nt = 0; nt < 4; nt++)
                            mma_s8u8(acc[amt][nt], Af[amt][ks], &Bf[nt >> 1][(nt & 1) * 2]);
                }

#pragma unroll
                for (int amt = 0; amt < 4; amt++)
#pragma unroll
                    for (int h = 0; h < 2; h++) {
                        int co = cb0 + amt * 16 + (lane >> 2) + h * 8;
                        float bj = fb3[co];
                        size_t base = ((size_t)n * 512 + co) * 3136;
#pragma unroll
                        for (int nt = 0; nt < 4; nt++) {
                            int px = p0 + pg * 32 + nt * 8 + (lane & 3) * 2;
                            float2 o2;
                            o2.x = (float)acc[amt][nt][h * 2 + 0] * inv3 + bj;
                            o2.y = (float)acc[amt][nt][h * 2 + 1] * inv3 + bj;
                            *(float2*)(out + base + px) = o2;
                        }
                    }
            }

            if (tid == 0) s_next = atomicAdd(&g_sync[0], 1);
            __syncthreads();
            __syncthreads();   // keep SM_A0 stable until all consumed (paranoia vs next-iter overwrite)
            t = s_next;
        }
    }
}

// ---------------- launch ----------------
extern "C" void kernel_launch(void* const* d_in, const int* in_sizes, int n_in,
                              void* d_out, int out_size)
{
    const float* x   = (const float*)d_in[0];
    const float* w1  = (const float*)d_in[1];
    const float* b1  = (const float*)d_in[2];
    const float* g1  = (const float*)d_in[3];
    const float* be1 = (const float*)d_in[4];
    const float* m1  = (const float*)d_in[5];
    const float* v1  = (const float*)d_in[6];
    const float* w2  = (const float*)d_in[7];
    const float* b2  = (const float*)d_in[8];
    const float* g2  = (const float*)d_in[9];
    const float* be2 = (const float*)d_in[10];
    const float* m2  = (const float*)d_in[11];
    const float* v2  = (const float*)d_in[12];
    const float* w3  = (const float*)d_in[13];
    const float* b3  = (const float*)d_in[14];
    const float* g3  = (const float*)d_in[15];
    const float* be3 = (const float*)d_in[16];
    const float* m3  = (const float*)d_in[17];
    const float* v3  = (const float*)d_in[18];

    cudaFuncSetAttribute(conv_fused, cudaFuncAttributeMaxDynamicSharedMemorySize, 196096);

    void* syncAddr = nullptr;
    cudaGetSymbolAddress(&syncAddr, g_sync);
    cudaMemsetAsync(syncAddr, 0, 65 * sizeof(int));

    prep_all<<<3, 512>>>(w1, b1, g1, be1, m1, v1,
                         w2, b2, g2, be2, m2, v2,
                         w3, b3, g3, be3, m3, v3);

    conv_fused<<<152, 256, 196096>>>(x, (float*)d_out);
}

// round 11
// speedup vs baseline: 1.6898x; 1.0896x over previous
#include <cuda_runtime.h>
#include <cstdint>

#define BN_EPS_F 1e-3f

__device__ __align__(16) float g_w1f[256*128];
__device__ float g_b1[128];
__device__ __align__(16) unsigned char g_w2q[9*128*128]; // [tap][co][ci] s8
__device__ float g_b2[128];
__device__ __align__(16) unsigned char g_w3q[512*128];   // [co][ci] s8
__device__ float g_b3[512];
__device__ float g_inv[2];
__device__ int   g_sync[65];   // [0]=ctr, [1..32]=done1[n], [33..64]=done2[n]
__device__ __align__(16) unsigned g_act1[100352*32];
__device__ __align__(16) unsigned g_act2[100352*32];

__device__ __forceinline__ uint32_t smem_u32(const void* p){
    uint32_t a;
    asm("{ .reg .u64 t; cvta.to.shared.u64 t, %1; cvt.u32.u64 %0, t; }" : "=r"(a) : "l"(p));
    return a;
}
#define SWZ(o) ((o) ^ (((o) >> 3) & 0x70))

__device__ __forceinline__ void ldsm4(unsigned* r, uint32_t addr){
    asm volatile("ldmatrix.sync.aligned.m8n8.x4.shared.b16 {%0,%1,%2,%3}, [%4];"
        : "=r"(r[0]), "=r"(r[1]), "=r"(r[2]), "=r"(r[3]) : "r"(addr));
}
__device__ __forceinline__ void mma_u8s8(int* d, const unsigned* a, const unsigned* b){
    asm volatile("mma.sync.aligned.m16n8k32.row.col.s32.u8.s8.s32 "
        "{%0,%1,%2,%3}, {%4,%5,%6,%7}, {%8,%9}, {%0,%1,%2,%3};"
        : "+r"(d[0]), "+r"(d[1]), "+r"(d[2]), "+r"(d[3])
        : "r"(a[0]), "r"(a[1]), "r"(a[2]), "r"(a[3]), "r"(b[0]), "r"(b[1]));
}
__device__ __forceinline__ void mma_s8u8(int* d, const unsigned* a, const unsigned* b){
    asm volatile("mma.sync.aligned.m16n8k32.row.col.s32.s8.u8.s32 "
        "{%0,%1,%2,%3}, {%4,%5,%6,%7}, {%8,%9}, {%0,%1,%2,%3};"
        : "+r"(d[0]), "+r"(d[1]), "+r"(d[2]), "+r"(d[3])
        : "r"(a[0]), "r"(a[1]), "r"(a[2]), "r"(a[3]), "r"(b[0]), "r"(b[1]));
}
#define CPA(dst, src, sz) asm volatile("cp.async.cg.shared.global [%0], [%1], 16, %2;" :: "r"(dst), "l"(src), "r"(sz) : "memory")
#define CPC()  asm volatile("cp.async.commit_group;" ::: "memory")
#define CPW(n) asm volatile("cp.async.wait_group %0;" :: "n"(n) : "memory")

// ---------------- prep: all three in one kernel (block = role) ----------------
__global__ __launch_bounds__(512) void prep_all(
    const float* __restrict__ w1, const float* __restrict__ b1,
    const float* __restrict__ g1, const float* __restrict__ be1,
    const float* __restrict__ m1, const float* __restrict__ v1,
    const float* __restrict__ w2, const float* __restrict__ b2,
    const float* __restrict__ g2, const float* __restrict__ be2,
    const float* __restrict__ m2, const float* __restrict__ v2,
    const float* __restrict__ w3, const float* __restrict__ b3,
    const float* __restrict__ g3, const float* __restrict__ be3,
    const float* __restrict__ m3, const float* __restrict__ v3)
{
    __shared__ float sc[512]; __shared__ float red[512];
    int tid = threadIdx.x;
    if (blockIdx.x == 0) {
        if (tid < 128) sc[tid] = __fdiv_rn(g1[tid], __fsqrt_rn(__fadd_rn(v1[tid], BN_EPS_F)));
        __syncthreads();
        float lmax = 0.f;
        for (int i = tid; i < 32768; i += 512) lmax = fmaxf(lmax, fabsf(__fmul_rn(w1[i], sc[i>>8])));
        red[tid] = lmax; __syncthreads();
        for (int s = 256; s > 0; s >>= 1) { if (tid < s) red[tid] = fmaxf(red[tid], red[tid+s]); __syncthreads(); }
        float sw = __fdiv_rn(127.f, fmaxf(red[0], 1e-8f));
        __syncthreads();
        for (int i = tid; i < 32768; i += 512) {
            float wf = __fmul_rn(w1[i], sc[i>>8]);
            g_w1f[(i & 255) * 128 + (i >> 8)] = __fdiv_rn(rintf(__fmul_rn(wf, sw)), sw);
        }
        float bf = 0.f;
        if (tid < 128) bf = __fadd_rn(__fmul_rn(__fsub_rn(b1[tid], m1[tid]), sc[tid]), be1[tid]);
        red[tid] = fabsf(bf); __syncthreads();
        for (int s = 256; s > 0; s >>= 1) { if (tid < s) red[tid] = fmaxf(red[tid], red[tid+s]); __syncthreads(); }
        float sb = __fdiv_rn(32767.f, fmaxf(red[0], 1e-8f));
        if (tid < 128) g_b1[tid] = __fdiv_rn(rintf(__fmul_rn(bf, sb)), sb);
    } else if (blockIdx.x == 1) {
        if (tid < 128) sc[tid] = __fdiv_rn(g2[tid], __fsqrt_rn(__fadd_rn(v2[tid], BN_EPS_F)));
        __syncthreads();
        float lmax = 0.f;
        for (int i = tid; i < 147456; i += 512) lmax = fmaxf(lmax, fabsf(__fmul_rn(w2[i], sc[i/1152])));
        red[tid] = lmax; __syncthreads();
        for (int s = 256; s > 0; s >>= 1) { if (tid < s) red[tid] = fmaxf(red[tid], red[tid+s]); __syncthreads(); }
        float sw = __fdiv_rn(127.f, fmaxf(red[0], 1e-8f));
        __syncthreads();
        for (int i = tid; i < 147456; i += 512) {
            int o = i / 1152, rem = i - o * 1152, ci = rem / 9, t = rem - ci * 9;
            int q = (int)rintf(__fmul_rn(__fmul_rn(w2[i], sc[o]), sw));
            ((signed char*)g_w2q)[(t * 128 + o) * 128 + ci] = (signed char)q;
        }
        float bf = 0.f;
        if (tid < 128) bf = __fadd_rn(__fmul_rn(__fsub_rn(b2[tid], m2[tid]), sc[tid]), be2[tid]);
        red[tid] = fabsf(bf); __syncthreads();
        for (int s = 256; s > 0; s >>= 1) { if (tid < s) red[tid] = fmaxf(red[tid], red[tid+s]); __syncthreads(); }
        float sb = __fdiv_rn(32767.f, fmaxf(red[0], 1e-8f));
        if (tid < 128) g_b2[tid] = __fdiv_rn(rintf(__fmul_rn(bf, sb)), sb);
        if (tid == 0)  g_inv[0] = __fdiv_rn(1.f, __fmul_rn(sw, 25.5f));
    } else {
        sc[tid] = __fdiv_rn(g3[tid], __fsqrt_rn(__fadd_rn(v3[tid], BN_EPS_F)));
        __syncthreads();
        float lmax = 0.f;
        for (int i = tid; i < 65536; i += 512) lmax = fmaxf(lmax, fabsf(__fmul_rn(w3[i], sc[i>>7])));
        red[tid] = lmax; __syncthreads();
        for (int s = 256; s > 0; s >>= 1) { if (tid < s) red[tid] = fmaxf(red[tid], red[tid+s]); __syncthreads(); }
        float sw = __fdiv_rn(127.f, fmaxf(red[0], 1e-8f));
        __syncthreads();
        for (int i = tid; i < 65536; i += 512)
            ((signed char*)g_w3q)[i] = (signed char)(int)rintf(__fmul_rn(__fmul_rn(w3[i], sc[i>>7]), sw));
        float bf = __fadd_rn(__fmul_rn(__fsub_rn(b3[tid], m3[tid]), sc[tid]), be3[tid]);
        red[tid] = fabsf(bf); __syncthreads();
        for (int s = 256; s > 0; s >>= 1) { if (tid < s) red[tid] = fmaxf(red[tid], red[tid+s]); __syncthreads(); }
        float sb = __fdiv_rn(32767.f, fmaxf(red[0], 1e-8f));
        g_b3[tid] = __fdiv_rn(rintf(__fmul_rn(bf, sb)), sb);
        if (tid == 0) g_inv[1] = __fdiv_rn(1.f, __fmul_rn(sw, 25.5f));
    }
}

// ---------------- fully fused persistent kernel, 512 threads / CTA ----------------
// tiles [0,416): conv1 256px; [416,1312): conv2 128px (gate done1[n]==13);
// [1312,2880): conv3 64px (gate done2[n]==28)
__global__ __launch_bounds__(512, 1) void conv_fused(const float* __restrict__ x,
                                                     float* __restrict__ out)
{
    extern __shared__ char smem[];
    const uint32_t SM_W = 0, SM_A0 = 147456, SM_A1 = 170496, SM_FB = 193536;
    __shared__ int s_next;
    uint32_t sb = smem_u32(smem);
    int tid = threadIdx.x, wid = tid >> 5, lane = tid & 31;

    float inv2 = g_inv[0], inv3 = g_inv[1];

    if (tid == 0) s_next = atomicAdd(&g_sync[0], 1);
    __syncthreads();
    int t = s_next;

    // ================= phase 1: conv1 (fp32 FFMA), 256px x 128co tiles =================
    {
        float* Asb = (float*)smem;              // 2 x 16 x 256 floats (32KB)
        float* Wsb = (float*)(smem + 32768);    // 2 x 16 x 128 floats (16KB)
        int tr = tid >> 5, tc = tid & 31;       // co group 0..15, px group 0..31
        int co0 = tr * 8;
        int pxa = tc * 4, pxb = tc * 4 + 128;
        int lr = tid >> 5;                      // loader row 0..15
        int lcA = (tid & 31) * 8;               // A cols, 2 float4
        int lcW = (tid & 31) * 4;               // W cols, 1 float4

        while (t < 416) {
            int n = t / 13, p0 = (t - n * 13) * 256;
            const float* xn = x + ((size_t)n * 256) * 3136;
            int pc1 = min(p0 + lcA, 3132), pc2 = min(p0 + lcA + 4, 3132);

            float acc[8][8];
#pragma unroll
            for (int j = 0; j < 8; j++)
#pragma unroll
                for (int q = 0; q < 8; q++) acc[j][q] = 0.f;

            float4 a1 = *(const float4*)(xn + (size_t)lr * 3136 + pc1);
            float4 a2 = *(const float4*)(xn + (size_t)lr * 3136 + pc2);
            float4 w1 = *(const float4*)(g_w1f + lr * 128 + lcW);
            *(float4*)(Asb + lr * 256 + lcA) = a1;
            *(float4*)(Asb + lr * 256 + lcA + 4) = a2;
            *(float4*)(Wsb + lr * 128 + lcW) = w1;
            __syncthreads();

            for (int p = 0; p < 16; p++) {
                int cuA = (p & 1) * 4096, cuW = (p & 1) * 2048;
                if (p < 15) {
                    int kr = (p + 1) * 16 + lr;
                    a1 = *(const float4*)(xn + (size_t)kr * 3136 + pc1);
                    a2 = *(const float4*)(xn + (size_t)kr * 3136 + pc2);
                    w1 = *(const float4*)(g_w1f + kr * 128 + lcW);
                }
#pragma unroll
                for (int k = 0; k < 16; k++) {
                    float4 av0 = *(const float4*)(Asb + cuA + k * 256 + pxa);
                    float4 av1 = *(const float4*)(Asb + cuA + k * 256 + pxb);
                    float4 wv0 = *(const float4*)(Wsb + cuW + k * 128 + co0);
                    float4 wv1 = *(const float4*)(Wsb + cuW + k * 128 + co0 + 4);
                    float wreg[8] = {wv0.x, wv0.y, wv0.z, wv0.w, wv1.x, wv1.y, wv1.z, wv1.w};
                    float areg[8] = {av0.x, av0.y, av0.z, av0.w, av1.x, av1.y, av1.z, av1.w};
#pragma unroll
                    for (int j = 0; j < 8; j++)
#pragma unroll
                        for (int q = 0; q < 8; q++)
                            acc[j][q] += wreg[j] * areg[q];
                }
                if (p < 15) {
                    int nxA = ((p + 1) & 1) * 4096, nxW = ((p + 1) & 1) * 2048;
                    *(float4*)(Asb + nxA + lr * 256 + lcA) = a1;
                    *(float4*)(Asb + nxA + lr * 256 + lcA + 4) = a2;
                    *(float4*)(Wsb + nxW + lr * 128 + lcW) = w1;
                    __syncthreads();
                }
            }

            float bias[8];
#pragma unroll
            for (int j = 0; j < 8; j++) bias[j] = g_b1[co0 + j];
#pragma unroll
            for (int q = 0; q < 8; q++) {
                int p = p0 + (q < 4 ? (pxa + q) : (pxb + q - 4));
                if (p >= 3136) continue;
                unsigned b0 = 0, b1v = 0;
#pragma unroll
                for (int j = 0; j < 8; j++) {
                    float vv = acc[j][q] + bias[j];
                    vv = fminf(fmaxf(vv, 0.f), 10.f);
                    unsigned a = (unsigned)(int)rintf(vv * 25.5f);
                    if (j < 4) b0 |= a << (8 * j); else b1v |= a << (8 * (j - 4));
                }
                *(uint2*)&g_act1[((unsigned)(n * 3136 + p)) * 32 + tr * 2] = make_uint2(b0, b1v);
            }
            __threadfence();
            __syncthreads();
            if (tid == 0) { atomicAdd(&g_sync[1 + n], 1); s_next = atomicAdd(&g_sync[0], 1); }
            __syncthreads();
            t = s_next;
        }
    }

    // load conv2 weights + b2 (after phase 1 frees smem)
    __syncthreads();
    for (int u = tid; u < 9216; u += 512) {
        uint4 wv = *(const uint4*)(g_w2q + u * 16);
        *(uint4*)(smem + SM_W + SWZ(u * 16)) = wv;
    }
    if (tid < 128) ((float*)(smem + SM_FB))[tid] = g_b2[tid];
    __syncthreads();

    // fragment lane mappings
    int wrb = (wid & 3) * 32, wcb = (wid >> 2) * 32;   // conv2: warp = 32px x 32co
    int sub = lane >> 3, r8 = lane & 7;
    int row8 = (sub & 1) * 8, kh = (sub >> 1) * 16;
    int rowb = (sub >> 1) * 8, khb = (sub & 1) * 16;

    int yym[2], xxm[2];
#pragma unroll
    for (int mt = 0; mt < 2; mt++) {
        int px = wrb + mt * 16 + row8 + r8;
        yym[mt] = px >> 4; xxm[mt] = px & 15;
    }
    uint32_t wbb[2]; int wxx[2];
#pragma unroll
    for (int bt = 0; bt < 2; bt++) {
        int co = wcb + bt * 16 + rowb + r8;
        wbb[bt] = sb + SM_W + co * 128;
        wxx[bt] = (co & 7) * 16;
    }

#define HALO_LOAD(DSTBASE, N_, Y0_, X0_) do { \
    for (int u = tid; u < 1440; u += 512) { \
        int hrow = u >> 3, c16 = u & 7; \
        int iy = hrow / 18, ix = hrow - iy * 18; \
        int gy = (Y0_) + iy - 1, gx = (X0_) + ix - 1; \
        bool ok = (gy >= 0 && gy < 56 && gx >= 0 && gx < 56); \
        const void* src = ok ? (const void*)&g_act1[((unsigned)((N_) * 3136 + gy * 56 + gx)) * 32 + c16 * 4] \
                             : (const void*)g_act1; \
        CPA((DSTBASE) + SWZ(hrow * 128 + c16 * 16), src, ok ? 16u : 0u); \
    } } while (0)

    // ================= phase 2: conv2 (int8 mma), 16 warps x (32px x 32co) =================
    if (t < 1312) {
        int buf = 0;
        {
            int q = t - 416, n = q / 28, r = q - n * 28;
            if (tid == 0) { while (((volatile int*)g_sync)[1 + n] < 13) {} }
            __syncthreads(); __threadfence();
            int y0 = (r >> 2) * 8, tx = r & 3;
            int x0 = (tx < 3) ? tx * 16 : 40;
            HALO_LOAD(sb + SM_A0, n, y0, x0);
            CPC();
        }
        while (t < 1312) {
            int q = t - 416, n = q / 28, r = q - n * 28;
            int y0 = (r >> 2) * 8, tx = r & 3;
            int x0 = (tx < 3) ? tx * 16 : 40;
            uint32_t aBase = sb + (buf ? SM_A1 : SM_A0);
            char* stg = smem + (buf ? SM_A1 : SM_A0);

            if (tid == 0) s_next = atomicAdd(&g_sync[0], 1);
            __syncthreads();
            int t2 = s_next;
            if (t2 < 1312) {
                int q2 = t2 - 416, n2 = q2 / 28, r2n = q2 - n2 * 28;
                if (tid == 0) { while (((volatile int*)g_sync)[1 + n2] < 13) {} }
                __syncthreads(); __threadfence();
                int y2 = (r2n >> 2) * 8, tx2 = r2n & 3;
                int x2 = (tx2 < 3) ? tx2 * 16 : 40;
                HALO_LOAD(sb + (buf ? SM_A0 : SM_A1), n2, y2, x2);
                CPC(); CPW(1);
            } else {
                CPW(0);
            }
            __syncthreads();

            int acc[2][4][4];
#pragma unroll
            for (int mt = 0; mt < 2; mt++)
#pragma unroll
                for (int nt = 0; nt < 4; nt++)
#pragma unroll
                    for (int qq = 0; qq < 4; qq++) acc[mt][nt][qq] = 0;

            for (int dy = 0; dy < 3; dy++)
                for (int dx = 0; dx < 3; dx++) {
                    uint32_t ab[2]; int axx[2];
#pragma unroll
                    for (int mt = 0; mt < 2; mt++) {
                        int hrow = (yym[mt] + dy) * 18 + xxm[mt] + dx;
                        ab[mt] = aBase + hrow * 128;
                        axx[mt] = (hrow & 7) * 16;
                    }
                    uint32_t wtap = (dy * 3 + dx) * 16384;
#pragma unroll
                    for (int ks = 0; ks < 4; ks++) {
                        unsigned A0[4], A1[4], B[2][4];
                        ldsm4(A0, ab[0] + ((ks * 32 + kh) ^ axx[0]));
                        ldsm4(A1, ab[1] + ((ks * 32 + kh) ^ axx[1]));
#pragma unroll
                        for (int bt = 0; bt < 2; bt++)
                            ldsm4(B[bt], wbb[bt] + wtap + ((ks * 32 + khb) ^ wxx[bt]));
#pragma unroll
                        for (int nt = 0; nt < 4; nt++) {
                            const unsigned* bp = &B[nt >> 1][(nt & 1) * 2];
                            mma_u8s8(acc[0][nt], A0, bp);
                            mma_u8s8(acc[1][nt], A1, bp);
                        }
                    }
                }

            __syncthreads();
            const float* fbs = (const float*)(smem + SM_FB);
#pragma unroll
            for (int mt = 0; mt < 2; mt++)
#pragma unroll
                for (int h = 0; h < 2; h++) {
                    int px = wrb + mt * 16 + (lane >> 2) + h * 8;
#pragma unroll
                    for (int nt = 0; nt < 4; nt++) {
                        int co = wcb + nt * 8 + (lane & 3) * 2;
                        float v0 = (float)acc[mt][nt][h * 2 + 0] * inv2 + fbs[co];
                        float v1 = (float)acc[mt][nt][h * 2 + 1] * inv2 + fbs[co + 1];
                        v0 = fminf(fmaxf(v0, 0.f), 10.f);
                        v1 = fminf(fmaxf(v1, 0.f), 10.f);
                        unsigned u0 = (unsigned)(int)rintf(v0 * 25.5f);
                        unsigned u1 = (unsigned)(int)rintf(v1 * 25.5f);
                        *(unsigned short*)(stg + px * 128 + (co ^ ((px & 7) * 16))) =
                            (unsigned short)(u0 | (u1 << 8));
                    }
                }
            __syncthreads();

            for (int u = tid; u < 1024; u += 512) {
                int px = u >> 3, c16 = u & 7;
                int yy = px >> 4, xx = px & 15;
                unsigned gp = (unsigned)(n * 3136 + (y0 + yy) * 56 + (x0 + xx));
                *(uint4*)&g_act2[gp * 32 + c16 * 4] =
                    *(const uint4*)(stg + px * 128 + ((c16 * 16) ^ ((px & 7) * 16)));
            }
            __threadfence();
            __syncthreads();
            if (tid == 0) atomicAdd(&g_sync[33 + n], 1);

            t = t2; buf ^= 1;
        }
    }
#undef HALO_LOAD

    // ================= phase 3: conv3 (int8 mma), 16 warps x 32co =================
    if (t < 2880) {
        __syncthreads();
        for (int u = tid; u < 4096; u += 512) {
            uint4 wv = *(const uint4*)(g_w3q + u * 16);
            *(uint4*)(smem + SM_W + SWZ(u * 16)) = wv;
        }
        if (tid < 128) ((float4*)(smem + SM_FB + 512))[tid] = *(const float4*)&g_b3[tid * 4];
        __syncthreads();

        const float* fb3 = (const float*)(smem + SM_FB + 512);
        int cb0 = wid * 32;
        int ntl = (sub >> 1) * 8, kb = (sub & 1) * 16;

        unsigned Af[2][4][4];
#pragma unroll
        for (int amt = 0; amt < 2; amt++) {
            int co = cb0 + amt * 16 + row8 + r8;
            uint32_t base = sb + SM_W + co * 128;
            int xx = (co & 7) * 16;
#pragma unroll
            for (int ks = 0; ks < 4; ks++)
                ldsm4(Af[amt][ks], base + ((ks * 32 + kh) ^ xx));
        }

        while (t < 2880) {
            int u0 = t - 1312;
            int n = u0 / 49, p0 = (u0 - n * 49) * 64;

            if (tid == 0) { while (((volatile int*)g_sync)[33 + n] < 28) {} }
            __syncthreads();
            __threadfence();

            for (int u = tid; u < 512; u += 512) {
                int pix = u >> 3, c16 = u & 7;
                uint4 vv = *(const uint4*)&g_act2[((unsigned)(n * 3136 + p0 + pix)) * 32 + c16 * 4];
                *(uint4*)(smem + SM_A0 + SWZ(pix * 128 + c16 * 16)) = vv;
            }
            __syncthreads();

            for (int pg = 0; pg < 2; pg++) {
                int acc[2][4][4];
#pragma unroll
                for (int a = 0; a < 2; a++)
#pragma unroll
                    for (int b = 0; b < 4; b++)
#pragma unroll
                        for (int qq = 0; qq < 4; qq++) acc[a][b][qq] = 0;

#pragma unroll
                for (int ks = 0; ks < 4; ks++) {
                    unsigned Bf[2][4];
#pragma unroll
                    for (int bq = 0; bq < 2; bq++) {
                        int brow = pg * 32 + bq * 16 + ntl + r8;
                        ldsm4(Bf[bq], sb + SM_A0 + brow * 128 + (((ks * 32 + kb)) ^ ((brow & 7) * 16)));
                    }
#pragma unroll
                    for (int amt = 0; amt < 2; amt++)
#pragma unroll
                        for (int nt = 0; nt < 4; nt++)
                            mma_s8u8(acc[amt][nt], Af[amt][ks], &Bf[nt >> 1][(nt & 1) * 2]);
                }

#pragma unroll
                for (int amt = 0; amt < 2; amt++)
#pragma unroll
                    for (int h = 0; h < 2; h++) {
                        int co = cb0 + amt * 16 + (lane >> 2) + h * 8;
                        float bj = fb3[co];
                        size_t base = ((size_t)n * 512 + co) * 3136;
#pragma unroll
                        for (int nt = 0; nt < 4; nt++) {
                            int px = p0 + pg * 32 + nt * 8 + (lane & 3) * 2;
                            float2 o2;
                            o2.x = (float)acc[amt][nt][h * 2 + 0] * inv3 + bj;
                            o2.y = (float)acc[amt][nt][h * 2 + 1] * inv3 + bj;
                            *(float2*)(out + base + px) = o2;
                        }
                    }
            }

            if (tid == 0) s_next = atomicAdd(&g_sync[0], 1);
            __syncthreads();
            __syncthreads();
            t = s_next;
        }
    }
}

// ---------------- launch ----------------
extern "C" void kernel_launch(void* const* d_in, const int* in_sizes, int n_in,
                              void* d_out, int out_size)
{
    const float* x   = (const float*)d_in[0];
    const float* w1  = (const float*)d_in[1];
    const float* b1  = (const float*)d_in[2];
    const float* g1  = (const float*)d_in[3];
    const float* be1 = (const float*)d_in[4];
    const float* m1  = (const float*)d_in[5];
    const float* v1  = (const float*)d_in[6];
    const float* w2  = (const float*)d_in[7];
    const float* b2  = (const float*)d_in[8];
    const float* g2  = (const float*)d_in[9];
    const float* be2 = (const float*)d_in[10];
    const float* m2  = (const float*)d_in[11];
    const float* v2  = (const float*)d_in[12];
    const float* w3  = (const float*)d_in[13];
    const float* b3  = (const float*)d_in[14];
    const float* g3  = (const float*)d_in[15];
    const float* be3 = (const float*)d_in[16];
    const float* m3  = (const float*)d_in[17];
    const float* v3  = (const float*)d_in[18];

    cudaFuncSetAttribute(conv_fused, cudaFuncAttributeMaxDynamicSharedMemorySize, 196096);

    void* syncAddr = nullptr;
    cudaGetSymbolAddress(&syncAddr, g_sync);
    cudaMemsetAsync(syncAddr, 0, 65 * sizeof(int));

    prep_all<<<3, 512>>>(w1, b1, g1, be1, m1, v1,
                         w2, b2, g2, be2, m2, v2,
                         w3, b3, g3, be3, m3, v3);

    conv_fused<<<152, 512, 196096>>>(x, (float*)d_out);
}

// round 12
// speedup vs baseline: 1.8861x; 1.1161x over previous
#include <cuda_runtime.h>
#include <cstdint>

#define BN_EPS_F 1e-3f

__device__ __align__(16) float g_w1f[256*128];
__device__ float g_b1[128];
__device__ __align__(16) unsigned char g_w2q[9*128*128]; // [tap][co][ci] s8
__device__ float g_b2[128];
__device__ __align__(16) unsigned char g_w3q[512*128];   // [co][ci] s8
__device__ float g_b3[512];
__device__ float g_inv[2];
__device__ int   g_sync[65];   // [0]=ctr, [1..32]=done1[n], [33..64]=done2[n]
__device__ unsigned g_wmax[3];
__device__ __align__(16) unsigned g_act1[100352*32];
__device__ __align__(16) unsigned g_act2[100352*32];

__device__ __forceinline__ uint32_t smem_u32(const void* p){
    uint32_t a;
    asm("{ .reg .u64 t; cvta.to.shared.u64 t, %1; cvt.u32.u64 %0, t; }" : "=r"(a) : "l"(p));
    return a;
}
#define SWZ(o) ((o) ^ (((o) >> 3) & 0x70))

__device__ __forceinline__ void ldsm4(unsigned* r, uint32_t addr){
    asm volatile("ldmatrix.sync.aligned.m8n8.x4.shared.b16 {%0,%1,%2,%3}, [%4];"
        : "=r"(r[0]), "=r"(r[1]), "=r"(r[2]), "=r"(r[3]) : "r"(addr));
}
__device__ __forceinline__ void mma_u8s8(int* d, const unsigned* a, const unsigned* b){
    asm volatile("mma.sync.aligned.m16n8k32.row.col.s32.u8.s8.s32 "
        "{%0,%1,%2,%3}, {%4,%5,%6,%7}, {%8,%9}, {%0,%1,%2,%3};"
        : "+r"(d[0]), "+r"(d[1]), "+r"(d[2]), "+r"(d[3])
        : "r"(a[0]), "r"(a[1]), "r"(a[2]), "r"(a[3]), "r"(b[0]), "r"(b[1]));
}
__device__ __forceinline__ void mma_s8u8(int* d, const unsigned* a, const unsigned* b){
    asm volatile("mma.sync.aligned.m16n8k32.row.col.s32.s8.u8.s32 "
        "{%0,%1,%2,%3}, {%4,%5,%6,%7}, {%8,%9}, {%0,%1,%2,%3};"
        : "+r"(d[0]), "+r"(d[1]), "+r"(d[2]), "+r"(d[3])
        : "r"(a[0]), "r"(a[1]), "r"(a[2]), "r"(a[3]), "r"(b[0]), "r"(b[1]));
}
#define CPA(dst, src, sz) asm volatile("cp.async.cg.shared.global [%0], [%1], 16, %2;" :: "r"(dst), "l"(src), "r"(sz) : "memory")
#define CPC()  asm volatile("cp.async.commit_group;" ::: "memory")
#define CPW(n) asm volatile("cp.async.wait_group %0;" :: "n"(n) : "memory")

// ---------------- prep pass 1: per-tensor max|w*sc| with 32 blocks each ----------------
__global__ __launch_bounds__(512) void prep_max(
    const float* __restrict__ w1, const float* __restrict__ g1, const float* __restrict__ v1,
    const float* __restrict__ w2, const float* __restrict__ g2, const float* __restrict__ v2,
    const float* __restrict__ w3, const float* __restrict__ g3, const float* __restrict__ v3)
{
    __shared__ float sc[512]; __shared__ float red[512];
    int tid = threadIdx.x;
    int grp = blockIdx.x >> 5, sub = blockIdx.x & 31;
    float lmax = 0.f;
    if (grp == 0) {
        if (tid < 128) sc[tid] = __fdiv_rn(g1[tid], __fsqrt_rn(__fadd_rn(v1[tid], BN_EPS_F)));
        __syncthreads();
        int base = sub * 1024;
        for (int i = base + tid; i < base + 1024; i += 512)
            lmax = fmaxf(lmax, fabsf(__fmul_rn(w1[i], sc[i >> 8])));
    } else if (grp == 1) {
        if (tid < 128) sc[tid] = __fdiv_rn(g2[tid], __fsqrt_rn(__fadd_rn(v2[tid], BN_EPS_F)));
        __syncthreads();
        int base = sub * 4608;
        for (int i = base + tid; i < base + 4608; i += 512)
            lmax = fmaxf(lmax, fabsf(__fmul_rn(w2[i], sc[i / 1152])));
    } else {
        sc[tid] = __fdiv_rn(g3[tid], __fsqrt_rn(__fadd_rn(v3[tid], BN_EPS_F)));
        __syncthreads();
        int base = sub * 2048;
        for (int i = base + tid; i < base + 2048; i += 512)
            lmax = fmaxf(lmax, fabsf(__fmul_rn(w3[i], sc[i >> 7])));
    }
    red[tid] = lmax; __syncthreads();
    for (int s = 256; s > 0; s >>= 1) { if (tid < s) red[tid] = fmaxf(red[tid], red[tid+s]); __syncthreads(); }
    if (tid == 0) atomicMax(&g_wmax[grp], __float_as_uint(red[0]));
}

// ---------------- prep pass 2: quantize weights (32 blocks/tensor) + biases ----------------
__global__ __launch_bounds__(512) void prep_quant(
    const float* __restrict__ w1, const float* __restrict__ b1,
    const float* __restrict__ g1, const float* __restrict__ be1,
    const float* __restrict__ m1, const float* __restrict__ v1,
    const float* __restrict__ w2, const float* __restrict__ b2,
    const float* __restrict__ g2, const float* __restrict__ be2,
    const float* __restrict__ m2, const float* __restrict__ v2,
    const float* __restrict__ w3, const float* __restrict__ b3,
    const float* __restrict__ g3, const float* __restrict__ be3,
    const float* __restrict__ m3, const float* __restrict__ v3)
{
    __shared__ float sc[512]; __shared__ float red[512];
    int tid = threadIdx.x;
    int grp = blockIdx.x >> 5, sub = blockIdx.x & 31;
    if (grp == 0) {
        if (tid < 128) sc[tid] = __fdiv_rn(g1[tid], __fsqrt_rn(__fadd_rn(v1[tid], BN_EPS_F)));
        __syncthreads();
        float sw = __fdiv_rn(127.f, fmaxf(__uint_as_float(g_wmax[0]), 1e-8f));
        int base = sub * 1024;
        for (int i = base + tid; i < base + 1024; i += 512) {
            float wf = __fmul_rn(w1[i], sc[i >> 8]);
            g_w1f[(i & 255) * 128 + (i >> 8)] = __fdiv_rn(rintf(__fmul_rn(wf, sw)), sw);
        }
        if (sub == 0) {
            float bf = 0.f;
            if (tid < 128) bf = __fadd_rn(__fmul_rn(__fsub_rn(b1[tid], m1[tid]), sc[tid]), be1[tid]);
            red[tid] = fabsf(bf); __syncthreads();
            for (int s = 256; s > 0; s >>= 1) { if (tid < s) red[tid] = fmaxf(red[tid], red[tid+s]); __syncthreads(); }
            float sb = __fdiv_rn(32767.f, fmaxf(red[0], 1e-8f));
            if (tid < 128) g_b1[tid] = __fdiv_rn(rintf(__fmul_rn(bf, sb)), sb);
        }
    } else if (grp == 1) {
        if (tid < 128) sc[tid] = __fdiv_rn(g2[tid], __fsqrt_rn(__fadd_rn(v2[tid], BN_EPS_F)));
        __syncthreads();
        float sw = __fdiv_rn(127.f, fmaxf(__uint_as_float(g_wmax[1]), 1e-8f));
        int base = sub * 4608;
        for (int i = base + tid; i < base + 4608; i += 512) {
            int o = i / 1152, rem = i - o * 1152, ci = rem / 9, t = rem - ci * 9;
            int q = (int)rintf(__fmul_rn(__fmul_rn(w2[i], sc[o]), sw));
            ((signed char*)g_w2q)[(t * 128 + o) * 128 + ci] = (signed char)q;
        }
        if (sub == 0) {
            float bf = 0.f;
            if (tid < 128) bf = __fadd_rn(__fmul_rn(__fsub_rn(b2[tid], m2[tid]), sc[tid]), be2[tid]);
            red[tid] = fabsf(bf); __syncthreads();
            for (int s = 256; s > 0; s >>= 1) { if (tid < s) red[tid] = fmaxf(red[tid], red[tid+s]); __syncthreads(); }
            float sb = __fdiv_rn(32767.f, fmaxf(red[0], 1e-8f));
            if (tid < 128) g_b2[tid] = __fdiv_rn(rintf(__fmul_rn(bf, sb)), sb);
            if (tid == 0)  g_inv[0] = __fdiv_rn(1.f, __fmul_rn(sw, 25.5f));
        }
    } else {
        sc[tid] = __fdiv_rn(g3[tid], __fsqrt_rn(__fadd_rn(v3[tid], BN_EPS_F)));
        __syncthreads();
        float sw = __fdiv_rn(127.f, fmaxf(__uint_as_float(g_wmax[2]), 1e-8f));
        int base = sub * 2048;
        for (int i = base + tid; i < base + 2048; i += 512)
            ((signed char*)g_w3q)[i] = (signed char)(int)rintf(__fmul_rn(__fmul_rn(w3[i], sc[i >> 7]), sw));
        if (sub == 0) {
            float bf = __fadd_rn(__fmul_rn(__fsub_rn(b3[tid], m3[tid]), sc[tid]), be3[tid]);
            red[tid] = fabsf(bf); __syncthreads();
            for (int s = 256; s > 0; s >>= 1) { if (tid < s) red[tid] = fmaxf(red[tid], red[tid+s]); __syncthreads(); }
            float sb = __fdiv_rn(32767.f, fmaxf(red[0], 1e-8f));
            g_b3[tid] = __fdiv_rn(rintf(__fmul_rn(bf, sb)), sb);
            if (tid == 0) g_inv[1] = __fdiv_rn(1.f, __fmul_rn(sw, 25.5f));
        }
    }
}

// ---------------- fully fused persistent kernel, 512 threads / CTA (unchanged R11 winner) ----------------
// tiles [0,416): conv1 256px; [416,1312): conv2 128px (gate done1[n]==13);
// [1312,2880): conv3 64px (gate done2[n]==28)
__global__ __launch_bounds__(512, 1) void conv_fused(const float* __restrict__ x,
                                                     float* __restrict__ out)
{
    extern __shared__ char smem[];
    const uint32_t SM_W = 0, SM_A0 = 147456, SM_A1 = 170496, SM_FB = 193536;
    __shared__ int s_next;
    uint32_t sb = smem_u32(smem);
    int tid = threadIdx.x, wid = tid >> 5, lane = tid & 31;

    float inv2 = g_inv[0], inv3 = g_inv[1];

    if (tid == 0) s_next = atomicAdd(&g_sync[0], 1);
    __syncthreads();
    int t = s_next;

    // ================= phase 1: conv1 (fp32 FFMA), 256px x 128co tiles =================
    {
        float* Asb = (float*)smem;
        float* Wsb = (float*)(smem + 32768);
        int tr = tid >> 5, tc = tid & 31;
        int co0 = tr * 8;
        int pxa = tc * 4, pxb = tc * 4 + 128;
        int lr = tid >> 5;
        int lcA = (tid & 31) * 8;
        int lcW = (tid & 31) * 4;

        while (t < 416) {
            int n = t / 13, p0 = (t - n * 13) * 256;
            const float* xn = x + ((size_t)n * 256) * 3136;
            int pc1 = min(p0 + lcA, 3132), pc2 = min(p0 + lcA + 4, 3132);

            float acc[8][8];
#pragma unroll
            for (int j = 0; j < 8; j++)
#pragma unroll
                for (int q = 0; q < 8; q++) acc[j][q] = 0.f;

            float4 a1 = *(const float4*)(xn + (size_t)lr * 3136 + pc1);
            float4 a2 = *(const float4*)(xn + (size_t)lr * 3136 + pc2);
            float4 w1 = *(const float4*)(g_w1f + lr * 128 + lcW);
            *(float4*)(Asb + lr * 256 + lcA) = a1;
            *(float4*)(Asb + lr * 256 + lcA + 4) = a2;
            *(float4*)(Wsb + lr * 128 + lcW) = w1;
            __syncthreads();

            for (int p = 0; p < 16; p++) {
                int cuA = (p & 1) * 4096, cuW = (p & 1) * 2048;
                if (p < 15) {
                    int kr = (p + 1) * 16 + lr;
                    a1 = *(const float4*)(xn + (size_t)kr * 3136 + pc1);
                    a2 = *(const float4*)(xn + (size_t)kr * 3136 + pc2);
                    w1 = *(const float4*)(g_w1f + kr * 128 + lcW);
                }
#pragma unroll
                for (int k = 0; k < 16; k++) {
                    float4 av0 = *(const float4*)(Asb + cuA + k * 256 + pxa);
                    float4 av1 = *(const float4*)(Asb + cuA + k * 256 + pxb);
                    float4 wv0 = *(const float4*)(Wsb + cuW + k * 128 + co0);
                    float4 wv1 = *(const float4*)(Wsb + cuW + k * 128 + co0 + 4);
                    float wreg[8] = {wv0.x, wv0.y, wv0.z, wv0.w, wv1.x, wv1.y, wv1.z, wv1.w};
                    float areg[8] = {av0.x, av0.y, av0.z, av0.w, av1.x, av1.y, av1.z, av1.w};
#pragma unroll
                    for (int j = 0; j < 8; j++)
#pragma unroll
                        for (int q = 0; q < 8; q++)
                            acc[j][q] += wreg[j] * areg[q];
                }
                if (p < 15) {
                    int nxA = ((p + 1) & 1) * 4096, nxW = ((p + 1) & 1) * 2048;
                    *(float4*)(Asb + nxA + lr * 256 + lcA) = a1;
                    *(float4*)(Asb + nxA + lr * 256 + lcA + 4) = a2;
                    *(float4*)(Wsb + nxW + lr * 128 + lcW) = w1;
                    __syncthreads();
                }
            }

            float bias[8];
#pragma unroll
            for (int j = 0; j < 8; j++) bias[j] = g_b1[co0 + j];
#pragma unroll
            for (int q = 0; q < 8; q++) {
                int p = p0 + (q < 4 ? (pxa + q) : (pxb + q - 4));
                if (p >= 3136) continue;
                unsigned b0 = 0, b1v = 0;
#pragma unroll
                for (int j = 0; j < 8; j++) {
                    float vv = acc[j][q] + bias[j];
                    vv = fminf(fmaxf(vv, 0.f), 10.f);
                    unsigned a = (unsigned)(int)rintf(vv * 25.5f);
                    if (j < 4) b0 |= a << (8 * j); else b1v |= a << (8 * (j - 4));
                }
                *(uint2*)&g_act1[((unsigned)(n * 3136 + p)) * 32 + tr * 2] = make_uint2(b0, b1v);
            }
            __threadfence();
            __syncthreads();
            if (tid == 0) { atomicAdd(&g_sync[1 + n], 1); s_next = atomicAdd(&g_sync[0], 1); }
            __syncthreads();
            t = s_next;
        }
    }

    // load conv2 weights + b2
    __syncthreads();
    for (int u = tid; u < 9216; u += 512) {
        uint4 wv = *(const uint4*)(g_w2q + u * 16);
        *(uint4*)(smem + SM_W + SWZ(u * 16)) = wv;
    }
    if (tid < 128) ((float*)(smem + SM_FB))[tid] = g_b2[tid];
    __syncthreads();

    int wrb = (wid & 3) * 32, wcb = (wid >> 2) * 32;
    int sub = lane >> 3, r8 = lane & 7;
    int row8 = (sub & 1) * 8, kh = (sub >> 1) * 16;
    int rowb = (sub >> 1) * 8, khb = (sub & 1) * 16;

    int yym[2], xxm[2];
#pragma unroll
    for (int mt = 0; mt < 2; mt++) {
        int px = wrb + mt * 16 + row8 + r8;
        yym[mt] = px >> 4; xxm[mt] = px & 15;
    }
    uint32_t wbb[2]; int wxx[2];
#pragma unroll
    for (int bt = 0; bt < 2; bt++) {
        int co = wcb + bt * 16 + rowb + r8;
        wbb[bt] = sb + SM_W + co * 128;
        wxx[bt] = (co & 7) * 16;
    }

#define HALO_LOAD(DSTBASE, N_, Y0_, X0_) do { \
    for (int u = tid; u < 1440; u += 512) { \
        int hrow = u >> 3, c16 = u & 7; \
        int iy = hrow / 18, ix = hrow - iy * 18; \
        int gy = (Y0_) + iy - 1, gx = (X0_) + ix - 1; \
        bool ok = (gy >= 0 && gy < 56 && gx >= 0 && gx < 56); \
        const void* src = ok ? (const void*)&g_act1[((unsigned)((N_) * 3136 + gy * 56 + gx)) * 32 + c16 * 4] \
                             : (const void*)g_act1; \
        CPA((DSTBASE) + SWZ(hrow * 128 + c16 * 16), src, ok ? 16u : 0u); \
    } } while (0)

    // ================= phase 2: conv2 (int8 mma) =================
    if (t < 1312) {
        int buf = 0;
        {
            int q = t - 416, n = q / 28, r = q - n * 28;
            if (tid == 0) { while (((volatile int*)g_sync)[1 + n] < 13) {} }
            __syncthreads(); __threadfence();
            int y0 = (r >> 2) * 8, tx = r & 3;
            int x0 = (tx < 3) ? tx * 16 : 40;
            HALO_LOAD(sb + SM_A0, n, y0, x0);
            CPC();
        }
        while (t < 1312) {
            int q = t - 416, n = q / 28, r = q - n * 28;
            int y0 = (r >> 2) * 8, tx = r & 3;
            int x0 = (tx < 3) ? tx * 16 : 40;
            uint32_t aBase = sb + (buf ? SM_A1 : SM_A0);
            char* stg = smem + (buf ? SM_A1 : SM_A0);

            if (tid == 0) s_next = atomicAdd(&g_sync[0], 1);
            __syncthreads();
            int t2 = s_next;
            if (t2 < 1312) {
                int q2 = t2 - 416, n2 = q2 / 28, r2n = q2 - n2 * 28;
                if (tid == 0) { while (((volatile int*)g_sync)[1 + n2] < 13) {} }
                __syncthreads(); __threadfence();
                int y2 = (r2n >> 2) * 8, tx2 = r2n & 3;
                int x2 = (tx2 < 3) ? tx2 * 16 : 40;
                HALO_LOAD(sb + (buf ? SM_A0 : SM_A1), n2, y2, x2);
                CPC(); CPW(1);
            } else {
                CPW(0);
            }
            __syncthreads();

            int acc[2][4][4];
#pragma unroll
            for (int mt = 0; mt < 2; mt++)
#pragma unroll
                for (int nt = 0; nt < 4; nt++)
#pragma unroll
                    for (int qq = 0; qq < 4; qq++) acc[mt][nt][qq] = 0;

            for (int dy = 0; dy < 3; dy++)
                for (int dx = 0; dx < 3; dx++) {
                    uint32_t ab[2]; int axx[2];
#pragma unroll
                    for (int mt = 0; mt < 2; mt++) {
                        int hrow = (yym[mt] + dy) * 18 + xxm[mt] + dx;
                        ab[mt] = aBase + hrow * 128;
                        axx[mt] = (hrow & 7) * 16;
                    }
                    uint32_t wtap = (dy * 3 + dx) * 16384;
#pragma unroll
                    for (int ks = 0; ks < 4; ks++) {
                        unsigned A0[4], A1[4], B[2][4];
                        ldsm4(A0, ab[0] + ((ks * 32 + kh) ^ axx[0]));
                        ldsm4(A1, ab[1] + ((ks * 32 + kh) ^ axx[1]));
#pragma unroll
                        for (int bt = 0; bt < 2; bt++)
                            ldsm4(B[bt], wbb[bt] + wtap + ((ks * 32 + khb) ^ wxx[bt]));
#pragma unroll
                        for (int nt = 0; nt < 4; nt++) {
                            const unsigned* bp = &B[nt >> 1][(nt & 1) * 2];
                            mma_u8s8(acc[0][nt], A0, bp);
                            mma_u8s8(acc[1][nt], A1, bp);
                        }
                    }
                }

            __syncthreads();
            const float* fbs = (const float*)(smem + SM_FB);
#pragma unroll
            for (int mt = 0; mt < 2; mt++)
#pragma unroll
                for (int h = 0; h < 2; h++) {
                    int px = wrb + mt * 16 + (lane >> 2) + h * 8;
#pragma unroll
                    for (int nt = 0; nt < 4; nt++) {
                        int co = wcb + nt * 8 + (lane & 3) * 2;
                        float v0 = (float)acc[mt][nt][h * 2 + 0] * inv2 + fbs[co];
                        float v1 = (float)acc[mt][nt][h * 2 + 1] * inv2 + fbs[co + 1];
                        v0 = fminf(fmaxf(v0, 0.f), 10.f);
                        v1 = fminf(fmaxf(v1, 0.f), 10.f);
                        unsigned u0 = (unsigned)(int)rintf(v0 * 25.5f);
                        unsigned u1 = (unsigned)(int)rintf(v1 * 25.5f);
                        *(unsigned short*)(stg + px * 128 + (co ^ ((px & 7) * 16))) =
                            (unsigned short)(u0 | (u1 << 8));
                    }
                }
            __syncthreads();

            for (int u = tid; u < 1024; u += 512) {
                int px = u >> 3, c16 = u & 7;
                int yy = px >> 4, xx = px & 15;
                unsigned gp = (unsigned)(n * 3136 + (y0 + yy) * 56 + (x0 + xx));
                *(uint4*)&g_act2[gp * 32 + c16 * 4] =
                    *(const uint4*)(stg + px * 128 + ((c16 * 16) ^ ((px & 7) * 16)));
            }
            __threadfence();
            __syncthreads();
            if (tid == 0) atomicAdd(&g_sync[33 + n], 1);

            t = t2; buf ^= 1;
        }
    }
#undef HALO_LOAD

    // ================= phase 3: conv3 (int8 mma) =================
    if (t < 2880) {
        __syncthreads();
        for (int u = tid; u < 4096; u += 512) {
            uint4 wv = *(const uint4*)(g_w3q + u * 16);
            *(uint4*)(smem + SM_W + SWZ(u * 16)) = wv;
        }
        if (tid < 128) ((float4*)(smem + SM_FB + 512))[tid] = *(const float4*)&g_b3[tid * 4];
        __syncthreads();

        const float* fb3 = (const float*)(smem + SM_FB + 512);
        int cb0 = wid * 32;
        int ntl = (sub >> 1) * 8, kb = (sub & 1) * 16;

        unsigned Af[2][4][4];
#pragma unroll
        for (int amt = 0; amt < 2; amt++) {
            int co = cb0 + amt * 16 + row8 + r8;
            uint32_t base = sb + SM_W + co * 128;
            int xx = (co & 7) * 16;
#pragma unroll
            for (int ks = 0; ks < 4; ks++)
                ldsm4(Af[amt][ks], base + ((ks * 32 + kh) ^ xx));
        }

        while (t < 2880) {
            int u0 = t - 1312;
            int n = u0 / 49, p0 = (u0 - n * 49) * 64;

            if (tid == 0) { while (((volatile int*)g_sync)[33 + n] < 28) {} }
            __syncthreads();
            __threadfence();

            for (int u = tid; u < 512; u += 512) {
                int pix = u >> 3, c16 = u & 7;
                uint4 vv = *(const uint4*)&g_act2[((unsigned)(n * 3136 + p0 + pix)) * 32 + c16 * 4];
                *(uint4*)(smem + SM_A0 + SWZ(pix * 128 + c16 * 16)) = vv;
            }
            __syncthreads();

            for (int pg = 0; pg < 2; pg++) {
                int acc[2][4][4];
#pragma unroll
                for (int a = 0; a < 2; a++)
#pragma unroll
                    for (int b = 0; b < 4; b++)
#pragma unroll
                        for (int qq = 0; qq < 4; qq++) acc[a][b][qq] = 0;

#pragma unroll
                for (int ks = 0; ks < 4; ks++) {
                    unsigned Bf[2][4];
#pragma unroll
                    for (int bq = 0; bq < 2; bq++) {
                        int brow = pg * 32 + bq * 16 + ntl + r8;
                        ldsm4(Bf[bq], sb + SM_A0 + brow * 128 + (((ks * 32 + kb)) ^ ((brow & 7) * 16)));
                    }
#pragma unroll
                    for (int amt = 0; amt < 2; amt++)
#pragma unroll
                        for (int nt = 0; nt < 4; nt++)
                            mma_s8u8(acc[amt][nt], Af[amt][ks], &Bf[nt >> 1][(nt & 1) * 2]);
                }

#pragma unroll
                for (int amt = 0; amt < 2; amt++)
#pragma unroll
                    for (int h = 0; h < 2; h++) {
                        int co = cb0 + amt * 16 + (lane >> 2) + h * 8;
                        float bj = fb3[co];
                        size_t base = ((size_t)n * 512 + co) * 3136;
#pragma unroll
                        for (int nt = 0; nt < 4; nt++) {
                            int px = p0 + pg * 32 + nt * 8 + (lane & 3) * 2;
                            float2 o2;
                            o2.x = (float)acc[amt][nt][h * 2 + 0] * inv3 + bj;
                            o2.y = (float)acc[amt][nt][h * 2 + 1] * inv3 + bj;
                            *(float2*)(out + base + px) = o2;
                        }
                    }
            }

            if (tid == 0) s_next = atomicAdd(&g_sync[0], 1);
            __syncthreads();
            __syncthreads();
            t = s_next;
        }
    }
}

// ---------------- launch ----------------
extern "C" void kernel_launch(void* const* d_in, const int* in_sizes, int n_in,
                              void* d_out, int out_size)
{
    const float* x   = (const float*)d_in[0];
    const float* w1  = (const float*)d_in[1];
    const float* b1  = (const float*)d_in[2];
    const float* g1  = (const float*)d_in[3];
    const float* be1 = (const float*)d_in[4];
    const float* m1  = (const float*)d_in[5];
    const float* v1  = (const float*)d_in[6];
    const float* w2  = (const float*)d_in[7];
    const float* b2  = (const float*)d_in[8];
    const float* g2  = (const float*)d_in[9];
    const float* be2 = (const float*)d_in[10];
    const float* m2  = (const float*)d_in[11];
    const float* v2  = (const float*)d_in[12];
    const float* w3  = (const float*)d_in[13];
    const float* b3  = (const float*)d_in[14];
    const float* g3  = (const float*)d_in[15];
    const float* be3 = (const float*)d_in[16];
    const float* m3  = (const float*)d_in[17];
    const float* v3  = (const float*)d_in[18];

    cudaFuncSetAttribute(conv_fused, cudaFuncAttributeMaxDynamicSharedMemorySize, 196096);

    void* syncAddr = nullptr;
    cudaGetSymbolAddress(&syncAddr, g_sync);
    cudaMemsetAsync(syncAddr, 0, 65 * sizeof(int));
    void* maxAddr = nullptr;
    cudaGetSymbolAddress(&maxAddr, g_wmax);
    cudaMemsetAsync(maxAddr, 0, 3 * sizeof(unsigned));

    prep_max<<<96, 512>>>(w1, g1, v1, w2, g2, v2, w3, g3, v3);
    prep_quant<<<96, 512>>>(w1, b1, g1, be1, m1, v1,
                            w2, b2, g2, be2, m2, v2,
                            w3, b3, g3, be3, m3, v3);

    conv_fused<<<152, 512, 196096>>>(x, (float*)d_out);
}

// round 13
// speedup vs baseline: 2.0807x; 1.1032x over previous
#include <cuda_runtime.h>
#include <cstdint>

#define BN_EPS_F 1e-3f

__device__ __align__(16) float g_w1f[256*128];
__device__ float g_b1[128];
__device__ __align__(16) unsigned char g_w2q[9*128*128]; // [tap][co][ci] s8
__device__ float g_b2[128];
__device__ __align__(16) unsigned char g_w3q[512*128];   // [co][ci] s8
__device__ float g_b3[512];
__device__ float g_inv[2];
// [0]=c1, [1]=c2a, [2]=c2b, [3]=c3a, [4]=c3b, [5..36]=done1[n], [37..68]=done2[n]
__device__ int   g_sync[69];
__device__ unsigned g_wmax[3];
__device__ __align__(16) unsigned g_act1[100352*32];
__device__ __align__(16) unsigned g_act2[100352*32];

__device__ __forceinline__ uint32_t smem_u32(const void* p){
    uint32_t a;
    asm("{ .reg .u64 t; cvta.to.shared.u64 t, %1; cvt.u32.u64 %0, t; }" : "=r"(a) : "l"(p));
    return a;
}
#define SWZ(o) ((o) ^ (((o) >> 3) & 0x70))

__device__ __forceinline__ void ldsm4(unsigned* r, uint32_t addr){
    asm volatile("ldmatrix.sync.aligned.m8n8.x4.shared.b16 {%0,%1,%2,%3}, [%4];"
        : "=r"(r[0]), "=r"(r[1]), "=r"(r[2]), "=r"(r[3]) : "r"(addr));
}
__device__ __forceinline__ void mma_u8s8(int* d, const unsigned* a, const unsigned* b){
    asm volatile("mma.sync.aligned.m16n8k32.row.col.s32.u8.s8.s32 "
        "{%0,%1,%2,%3}, {%4,%5,%6,%7}, {%8,%9}, {%0,%1,%2,%3};"
        : "+r"(d[0]), "+r"(d[1]), "+r"(d[2]), "+r"(d[3])
        : "r"(a[0]), "r"(a[1]), "r"(a[2]), "r"(a[3]), "r"(b[0]), "r"(b[1]));
}
__device__ __forceinline__ void mma_s8u8(int* d, const unsigned* a, const unsigned* b){
    asm volatile("mma.sync.aligned.m16n8k32.row.col.s32.s8.u8.s32 "
        "{%0,%1,%2,%3}, {%4,%5,%6,%7}, {%8,%9}, {%0,%1,%2,%3};"
        : "+r"(d[0]), "+r"(d[1]), "+r"(d[2]), "+r"(d[3])
        : "r"(a[0]), "r"(a[1]), "r"(a[2]), "r"(a[3]), "r"(b[0]), "r"(b[1]));
}
#define CPA(dst, src, sz) asm volatile("cp.async.cg.shared.global [%0], [%1], 16, %2;" :: "r"(dst), "l"(src), "r"(sz) : "memory")
#define CPC()  asm volatile("cp.async.commit_group;" ::: "memory")
#define CPW(n) asm volatile("cp.async.wait_group %0;" :: "n"(n) : "memory")

// ---------------- prep pass 1 (unchanged R12 winner) ----------------
__global__ __launch_bounds__(512) void prep_max(
    const float* __restrict__ w1, const float* __restrict__ g1, const float* __restrict__ v1,
    const float* __restrict__ w2, const float* __restrict__ g2, const float* __restrict__ v2,
    const float* __restrict__ w3, const float* __restrict__ g3, const float* __restrict__ v3)
{
    __shared__ float sc[512]; __shared__ float red[512];
    int tid = threadIdx.x;
    int grp = blockIdx.x >> 5, sub = blockIdx.x & 31;
    float lmax = 0.f;
    if (grp == 0) {
        if (tid < 128) sc[tid] = __fdiv_rn(g1[tid], __fsqrt_rn(__fadd_rn(v1[tid], BN_EPS_F)));
        __syncthreads();
        int base = sub * 1024;
        for (int i = base + tid; i < base + 1024; i += 512)
            lmax = fmaxf(lmax, fabsf(__fmul_rn(w1[i], sc[i >> 8])));
    } else if (grp == 1) {
        if (tid < 128) sc[tid] = __fdiv_rn(g2[tid], __fsqrt_rn(__fadd_rn(v2[tid], BN_EPS_F)));
        __syncthreads();
        int base = sub * 4608;
        for (int i = base + tid; i < base + 4608; i += 512)
            lmax = fmaxf(lmax, fabsf(__fmul_rn(w2[i], sc[i / 1152])));
    } else {
        sc[tid] = __fdiv_rn(g3[tid], __fsqrt_rn(__fadd_rn(v3[tid], BN_EPS_F)));
        __syncthreads();
        int base = sub * 2048;
        for (int i = base + tid; i < base + 2048; i += 512)
            lmax = fmaxf(lmax, fabsf(__fmul_rn(w3[i], sc[i >> 7])));
    }
    red[tid] = lmax; __syncthreads();
    for (int s = 256; s > 0; s >>= 1) { if (tid < s) red[tid] = fmaxf(red[tid], red[tid+s]); __syncthreads(); }
    if (tid == 0) atomicMax(&g_wmax[grp], __float_as_uint(red[0]));
}

// ---------------- prep pass 2 (unchanged R12 winner) ----------------
__global__ __launch_bounds__(512) void prep_quant(
    const float* __restrict__ w1, const float* __restrict__ b1,
    const float* __restrict__ g1, const float* __restrict__ be1,
    const float* __restrict__ m1, const float* __restrict__ v1,
    const float* __restrict__ w2, const float* __restrict__ b2,
    const float* __restrict__ g2, const float* __restrict__ be2,
    const float* __restrict__ m2, const float* __restrict__ v2,
    const float* __restrict__ w3, const float* __restrict__ b3,
    const float* __restrict__ g3, const float* __restrict__ be3,
    const float* __restrict__ m3, const float* __restrict__ v3)
{
    __shared__ float sc[512]; __shared__ float red[512];
    int tid = threadIdx.x;
    int grp = blockIdx.x >> 5, sub = blockIdx.x & 31;
    if (grp == 0) {
        if (tid < 128) sc[tid] = __fdiv_rn(g1[tid], __fsqrt_rn(__fadd_rn(v1[tid], BN_EPS_F)));
        __syncthreads();
        float sw = __fdiv_rn(127.f, fmaxf(__uint_as_float(g_wmax[0]), 1e-8f));
        int base = sub * 1024;
        for (int i = base + tid; i < base + 1024; i += 512) {
            float wf = __fmul_rn(w1[i], sc[i >> 8]);
            g_w1f[(i & 255) * 128 + (i >> 8)] = __fdiv_rn(rintf(__fmul_rn(wf, sw)), sw);
        }
        if (sub == 0) {
            float bf = 0.f;
            if (tid < 128) bf = __fadd_rn(__fmul_rn(__fsub_rn(b1[tid], m1[tid]), sc[tid]), be1[tid]);
            red[tid] = fabsf(bf); __syncthreads();
            for (int s = 256; s > 0; s >>= 1) { if (tid < s) red[tid] = fmaxf(red[tid], red[tid+s]); __syncthreads(); }
            float sb = __fdiv_rn(32767.f, fmaxf(red[0], 1e-8f));
            if (tid < 128) g_b1[tid] = __fdiv_rn(rintf(__fmul_rn(bf, sb)), sb);
        }
    } else if (grp == 1) {
        if (tid < 128) sc[tid] = __fdiv_rn(g2[tid], __fsqrt_rn(__fadd_rn(v2[tid], BN_EPS_F)));
        __syncthreads();
        float sw = __fdiv_rn(127.f, fmaxf(__uint_as_float(g_wmax[1]), 1e-8f));
        int base = sub * 4608;
        for (int i = base + tid; i < base + 4608; i += 512) {
            int o = i / 1152, rem = i - o * 1152, ci = rem / 9, t = rem - ci * 9;
            int q = (int)rintf(__fmul_rn(__fmul_rn(w2[i], sc[o]), sw));
            ((signed char*)g_w2q)[(t * 128 + o) * 128 + ci] = (signed char)q;
        }
        if (sub == 0) {
            float bf = 0.f;
            if (tid < 128) bf = __fadd_rn(__fmul_rn(__fsub_rn(b2[tid], m2[tid]), sc[tid]), be2[tid]);
            red[tid] = fabsf(bf); __syncthreads();
            for (int s = 256; s > 0; s >>= 1) { if (tid < s) red[tid] = fmaxf(red[tid], red[tid+s]); __syncthreads(); }
            float sb = __fdiv_rn(32767.f, fmaxf(red[0], 1e-8f));
            if (tid < 128) g_b2[tid] = __fdiv_rn(rintf(__fmul_rn(bf, sb)), sb);
            if (tid == 0)  g_inv[0] = __fdiv_rn(1.f, __fmul_rn(sw, 25.5f));
        }
    } else {
        sc[tid] = __fdiv_rn(g3[tid], __fsqrt_rn(__fadd_rn(v3[tid], BN_EPS_F)));
        __syncthreads();
        float sw = __fdiv_rn(127.f, fmaxf(__uint_as_float(g_wmax[2]), 1e-8f));
        int base = sub * 2048;
        for (int i = base + tid; i < base + 2048; i += 512)
            ((signed char*)g_w3q)[i] = (signed char)(int)rintf(__fmul_rn(__fmul_rn(w3[i], sc[i >> 7]), sw));
        if (sub == 0) {
            float bf = __fadd_rn(__fmul_rn(__fsub_rn(b3[tid], m3[tid]), sc[tid]), be3[tid]);
            red[tid] = fabsf(bf); __syncthreads();
            for (int s = 256; s > 0; s >>= 1) { if (tid < s) red[tid] = fmaxf(red[tid], red[tid+s]); __syncthreads(); }
            float sb = __fdiv_rn(32767.f, fmaxf(red[0], 1e-8f));
            g_b3[tid] = __fdiv_rn(rintf(__fmul_rn(bf, sb)), sb);
            if (tid == 0) g_inv[1] = __fdiv_rn(1.f, __fmul_rn(sw, 25.5f));
        }
    }
}

// ---------------- fused persistent kernel, 256 threads, 2 CTAs/SM, co-half split ----------------
__global__ __launch_bounds__(256, 2) void conv_fused(const float* __restrict__ x,
                                                     float* __restrict__ out)
{
    extern __shared__ char smem[];
    const uint32_t SM_W = 0, SM_H = 73728, SM_FB = 96768;
    __shared__ int s_next;
    uint32_t sb = smem_u32(smem);
    int tid = threadIdx.x, wid = tid >> 5, lane = tid & 31;
    int parity = blockIdx.x & 1;

    float inv2 = g_inv[0], inv3 = g_inv[1];

    if (tid == 0) s_next = atomicAdd(&g_sync[0], 1);
    __syncthreads();
    int t = s_next;

    // ================= phase 1: conv1 fp32, 128px x 128co, shared counter [0,800) =================
    {
        float* Asb = (float*)smem;              // 2 x 2048 floats
        float* Wsb = (float*)(smem + 16384);    // 2 x 2048 floats
        int tr = tid >> 4, tc = tid & 15;
        int co0 = tr * 8;
        int pxa = tc * 4, pxb = tc * 4 + 64;
        int lr = tid >> 4;
        int lc1 = (tid & 15) * 4, lc2 = lc1 + 64;

        while (t < 800) {
            int n = t / 25, p0 = (t - n * 25) * 128;
            const float* xn = x + ((size_t)n * 256) * 3136;
            int pc1 = min(p0 + lc1, 3132), pc2 = min(p0 + lc2, 3132);

            float acc[8][8];
#pragma unroll
            for (int j = 0; j < 8; j++)
#pragma unroll
                for (int q = 0; q < 8; q++) acc[j][q] = 0.f;

            float4 a1 = *(const float4*)(xn + (size_t)lr * 3136 + pc1);
            float4 a2 = *(const float4*)(xn + (size_t)lr * 3136 + pc2);
            float4 w1 = *(const float4*)(g_w1f + lr * 128 + lc1);
            float4 w2 = *(const float4*)(g_w1f + lr * 128 + lc2);
            *(float4*)(Asb + lr * 128 + lc1) = a1;
            *(float4*)(Asb + lr * 128 + lc2) = a2;
            *(float4*)(Wsb + lr * 128 + lc1) = w1;
            *(float4*)(Wsb + lr * 128 + lc2) = w2;
            __syncthreads();

            for (int p = 0; p < 16; p++) {
                int cu = (p & 1) * 2048;
                if (p < 15) {
                    int kr = (p + 1) * 16 + lr;
                    a1 = *(const float4*)(xn + (size_t)kr * 3136 + pc1);
                    a2 = *(const float4*)(xn + (size_t)kr * 3136 + pc2);
                    w1 = *(const float4*)(g_w1f + kr * 128 + lc1);
                    w2 = *(const float4*)(g_w1f + kr * 128 + lc2);
                }
#pragma unroll
                for (int k = 0; k < 16; k++) {
                    float4 av0 = *(const float4*)(Asb + cu + k * 128 + pxa);
                    float4 av1 = *(const float4*)(Asb + cu + k * 128 + pxb);
                    float4 wv0 = *(const float4*)(Wsb + cu + k * 128 + co0);
                    float4 wv1 = *(const float4*)(Wsb + cu + k * 128 + co0 + 4);
                    float wreg[8] = {wv0.x, wv0.y, wv0.z, wv0.w, wv1.x, wv1.y, wv1.z, wv1.w};
                    float areg[8] = {av0.x, av0.y, av0.z, av0.w, av1.x, av1.y, av1.z, av1.w};
#pragma unroll
                    for (int j = 0; j < 8; j++)
#pragma unroll
                        for (int q = 0; q < 8; q++)
                            acc[j][q] += wreg[j] * areg[q];
                }
                if (p < 15) {
                    int nx = ((p + 1) & 1) * 2048;
                    *(float4*)(Asb + nx + lr * 128 + lc1) = a1;
                    *(float4*)(Asb + nx + lr * 128 + lc2) = a2;
                    *(float4*)(Wsb + nx + lr * 128 + lc1) = w1;
                    *(float4*)(Wsb + nx + lr * 128 + lc2) = w2;
                    __syncthreads();
                }
            }

            float bias[8];
#pragma unroll
            for (int j = 0; j < 8; j++) bias[j] = g_b1[co0 + j];
#pragma unroll
            for (int q = 0; q < 8; q++) {
                int p = p0 + (q < 4 ? (pxa + q) : (pxb + q - 4));
                if (p >= 3136) continue;
                unsigned b0 = 0, b1v = 0;
#pragma unroll
                for (int j = 0; j < 8; j++) {
                    float vv = acc[j][q] + bias[j];
                    vv = fminf(fmaxf(vv, 0.f), 10.f);
                    unsigned a = (unsigned)(int)rintf(vv * 25.5f);
                    if (j < 4) b0 |= a << (8 * j); else b1v |= a << (8 * (j - 4));
                }
                *(uint2*)&g_act1[((unsigned)(n * 3136 + p)) * 32 + tr * 2] = make_uint2(b0, b1v);
            }
            __threadfence();
            __syncthreads();
            if (tid == 0) { atomicAdd(&g_sync[5 + n], 1); s_next = atomicAdd(&g_sync[0], 1); }
            __syncthreads();
            t = s_next;
        }
    }

    // ================= phase 2: conv2 int8 mma, co-half, 8 warps x (32px x 32co) =================
    __syncthreads();
    for (int u = tid; u < 4608; u += 256) {     // W2 half: 576 rows x 128B
        int row = u >> 3, c16 = u & 7;
        int tp = row >> 6, c = row & 63;
        uint4 wv = *(const uint4*)(g_w2q + ((tp * 128 + parity * 64 + c) * 128) + c16 * 16);
        *(uint4*)(smem + SM_W + SWZ(row * 128 + c16 * 16)) = wv;
    }
    if (tid < 64) ((float*)(smem + SM_FB))[tid] = g_b2[parity * 64 + tid];
    __syncthreads();

    int wrb = (wid & 3) * 32, wcb = (wid >> 2) * 32;
    int sub = lane >> 3, r8 = lane & 7;
    int row8 = (sub & 1) * 8, kh = (sub >> 1) * 16;
    int rowb = (sub >> 1) * 8, khb = (sub & 1) * 16;

    int yym[2], xxm[2];
#pragma unroll
    for (int mt = 0; mt < 2; mt++) {
        int px = wrb + mt * 16 + row8 + r8;
        yym[mt] = px >> 4; xxm[mt] = px & 15;
    }
    uint32_t wbb[2]; int wxx[2];
#pragma unroll
    for (int bt = 0; bt < 2; bt++) {
        int co = wcb + bt * 16 + rowb + r8;
        wbb[bt] = sb + SM_W + co * 128;
        wxx[bt] = (co & 7) * 16;
    }

    {
        if (tid == 0) s_next = atomicAdd(&g_sync[1 + parity], 1);
        __syncthreads();
        int t2 = s_next;

        while (t2 < 896) {
            int n = t2 / 28, r = t2 - n * 28;
            int y0 = (r >> 2) * 8, tx = r & 3;
            int x0 = (tx < 3) ? tx * 16 : 40;

            if (tid == 0) { while (((volatile int*)g_sync)[5 + n] < 25) {} }
            __syncthreads(); __threadfence();

            for (int u = tid; u < 1440; u += 256) {
                int hrow = u >> 3, c16 = u & 7;
                int iy = hrow / 18, ix = hrow - iy * 18;
                int gy = y0 + iy - 1, gx = x0 + ix - 1;
                bool ok = (gy >= 0 && gy < 56 && gx >= 0 && gx < 56);
                const void* src = ok ? (const void*)&g_act1[((unsigned)(n * 3136 + gy * 56 + gx)) * 32 + c16 * 4]
                                     : (const void*)g_act1;
                CPA(sb + SM_H + SWZ(hrow * 128 + c16 * 16), src, ok ? 16u : 0u);
            }
            CPC(); CPW(0);
            __syncthreads();

            int acc[2][4][4];
#pragma unroll
            for (int mt = 0; mt < 2; mt++)
#pragma unroll
                for (int nt = 0; nt < 4; nt++)
#pragma unroll
                    for (int qq = 0; qq < 4; qq++) acc[mt][nt][qq] = 0;

            for (int dy = 0; dy < 3; dy++)
                for (int dx = 0; dx < 3; dx++) {
                    uint32_t ab[2]; int axx[2];
#pragma unroll
                    for (int mt = 0; mt < 2; mt++) {
                        int hrow = (yym[mt] + dy) * 18 + xxm[mt] + dx;
                        ab[mt] = sb + SM_H + hrow * 128;
                        axx[mt] = (hrow & 7) * 16;
                    }
                    uint32_t wtap = (dy * 3 + dx) * 8192;
#pragma unroll
                    for (int ks = 0; ks < 4; ks++) {
                        unsigned A0[4], A1[4], B[2][4];
                        ldsm4(A0, ab[0] + ((ks * 32 + kh) ^ axx[0]));
                        ldsm4(A1, ab[1] + ((ks * 32 + kh) ^ axx[1]));
#pragma unroll
                        for (int bt = 0; bt < 2; bt++)
                            ldsm4(B[bt], wbb[bt] + wtap + ((ks * 32 + khb) ^ wxx[bt]));
#pragma unroll
                        for (int nt = 0; nt < 4; nt++) {
                            const unsigned* bp = &B[nt >> 1][(nt & 1) * 2];
                            mma_u8s8(acc[0][nt], A0, bp);
                            mma_u8s8(acc[1][nt], A1, bp);
                        }
                    }
                }

            __syncthreads();   // halo reads done; reuse SM_H as staging
            const float* fbs = (const float*)(smem + SM_FB);
            char* stg = smem + SM_H;
#pragma unroll
            for (int mt = 0; mt < 2; mt++)
#pragma unroll
                for (int h = 0; h < 2; h++) {
                    int px = wrb + mt * 16 + (lane >> 2) + h * 8;
#pragma unroll
                    for (int nt = 0; nt < 4; nt++) {
                        int co = wcb + nt * 8 + (lane & 3) * 2;
                        float v0 = (float)acc[mt][nt][h * 2 + 0] * inv2 + fbs[co];
                        float v1 = (float)acc[mt][nt][h * 2 + 1] * inv2 + fbs[co + 1];
                        v0 = fminf(fmaxf(v0, 0.f), 10.f);
                        v1 = fminf(fmaxf(v1, 0.f), 10.f);
                        unsigned u0 = (unsigned)(int)rintf(v0 * 25.5f);
                        unsigned u1 = (unsigned)(int)rintf(v1 * 25.5f);
                        *(unsigned short*)(stg + px * 128 + (co ^ ((px & 7) * 16))) =
                            (unsigned short)(u0 | (u1 << 8));
                    }
                }
            __syncthreads();

            for (int u = tid; u < 512; u += 256) {
                int px = u >> 2, c16 = u & 3;
                int yy = px >> 4, xx = px & 15;
                unsigned gp = (unsigned)(n * 3136 + (y0 + yy) * 56 + (x0 + xx));
                *(uint4*)&g_act2[gp * 32 + parity * 16 + c16 * 4] =
                    *(const uint4*)(stg + px * 128 + ((c16 * 16) ^ ((px & 7) * 16)));
            }
            __threadfence();
            __syncthreads();
            if (tid == 0) { atomicAdd(&g_sync[37 + n], 1); s_next = atomicAdd(&g_sync[1 + parity], 1); }
            __syncthreads();
            t2 = s_next;
        }
    }

    // ================= phase 3: conv3 int8 mma, co-half (256 co), 8 warps x 32co =================
    {
        __syncthreads();
        for (int u = tid; u < 2048; u += 256) {     // W3 half: 256 rows x 128B
            int row = u >> 3, c16 = u & 7;
            uint4 wv = *(const uint4*)(g_w3q + (parity * 256 + row) * 128 + c16 * 16);
            *(uint4*)(smem + SM_W + SWZ(row * 128 + c16 * 16)) = wv;
        }
        if (tid < 64) ((float4*)(smem + SM_FB))[tid] = *(const float4*)&g_b3[parity * 256 + tid * 4];
        __syncthreads();

        const float* fb3 = (const float*)(smem + SM_FB);
        int cb0 = wid * 32;
        int ntl = (sub >> 1) * 8, kb = (sub & 1) * 16;

        unsigned Af[2][4][4];
#pragma unroll
        for (int amt = 0; amt < 2; amt++) {
            int co = cb0 + amt * 16 + row8 + r8;
            uint32_t base = sb + SM_W + co * 128;
            int xx = (co & 7) * 16;
#pragma unroll
            for (int ks = 0; ks < 4; ks++)
                ldsm4(Af[amt][ks], base + ((ks * 32 + kh) ^ xx));
        }

        if (tid == 0) s_next = atomicAdd(&g_sync[3 + parity], 1);
        __syncthreads();
        int t3 = s_next;

        while (t3 < 1568) {
            int n = t3 / 49, p0 = (t3 - n * 49) * 64;

            if (tid == 0) { while (((volatile int*)g_sync)[37 + n] < 56) {} }
            __syncthreads();
            __threadfence();

            for (int u = tid; u < 512; u += 256) {
                int pix = u >> 3, c16 = u & 7;
                uint4 vv = *(const uint4*)&g_act2[((unsigned)(n * 3136 + p0 + pix)) * 32 + c16 * 4];
                *(uint4*)(smem + SM_H + SWZ(pix * 128 + c16 * 16)) = vv;
            }
            __syncthreads();

            for (int pg = 0; pg < 2; pg++) {
                int acc[2][4][4];
#pragma unroll
                for (int a = 0; a < 2; a++)
#pragma unroll
                    for (int b = 0; b < 4; b++)
#pragma unroll
                        for (int qq = 0; qq < 4; qq++) acc[a][b][qq] = 0;

#pragma unroll
                for (int ks = 0; ks < 4; ks++) {
                    unsigned Bf[2][4];
#pragma unroll
                    for (int bq = 0; bq < 2; bq++) {
                        int brow = pg * 32 + bq * 16 + ntl + r8;
                        ldsm4(Bf[bq], sb + SM_H + brow * 128 + (((ks * 32 + kb)) ^ ((brow & 7) * 16)));
                    }
#pragma unroll
                    for (int amt = 0; amt < 2; amt++)
#pragma unroll
                        for (int nt = 0; nt < 4; nt++)
                            mma_s8u8(acc[amt][nt], Af[amt][ks], &Bf[nt >> 1][(nt & 1) * 2]);
                }

#pragma unroll
                for (int amt = 0; amt < 2; amt++)
#pragma unroll
                    for (int h = 0; h < 2; h++) {
                        int co = parity * 256 + cb0 + amt * 16 + (lane >> 2) + h * 8;
                        float bj = fb3[co - parity * 256];
                        size_t base = ((size_t)n * 512 + co) * 3136;
#pragma unroll
                        for (int nt = 0; nt < 4; nt++) {
                            int px = p0 + pg * 32 + nt * 8 + (lane & 3) * 2;
                            float2 o2;
                            o2.x = (float)acc[amt][nt][h * 2 + 0] * inv3 + bj;
                            o2.y = (float)acc[amt][nt][h * 2 + 1] * inv3 + bj;
                            *(float2*)(out + base + px) = o2;
                        }
                    }
            }

            if (tid == 0) s_next = atomicAdd(&g_sync[3 + parity], 1);
            __syncthreads();
            __syncthreads();
            t3 = s_next;
        }
    }
}

// ---------------- launch ----------------
extern "C" void kernel_launch(void* const* d_in, const int* in_sizes, int n_in,
                              void* d_out, int out_size)
{
    const float* x   = (const float*)d_in[0];
    const float* w1  = (const float*)d_in[1];
    const float* b1  = (const float*)d_in[2];
    const float* g1  = (const float*)d_in[3];
    const float* be1 = (const float*)d_in[4];
    const float* m1  = (const float*)d_in[5];
    const float* v1  = (const float*)d_in[6];
    const float* w2  = (const float*)d_in[7];
    const float* b2  = (const float*)d_in[8];
    const float* g2  = (const float*)d_in[9];
    const float* be2 = (const float*)d_in[10];
    const float* m2  = (const float*)d_in[11];
    const float* v2  = (const float*)d_in[12];
    const float* w3  = (const float*)d_in[13];
    const float* b3  = (const float*)d_in[14];
    const float* g3  = (const float*)d_in[15];
    const float* be3 = (const float*)d_in[16];
    const float* m3  = (const float*)d_in[17];
    const float* v3  = (const float*)d_in[18];

    cudaFuncSetAttribute(conv_fused, cudaFuncAttributeMaxDynamicSharedMemorySize, 98304);

    void* syncAddr = nullptr;
    cudaGetSymbolAddress(&syncAddr, g_sync);
    cudaMemsetAsync(syncAddr, 0, 69 * sizeof(int));
    void* maxAddr = nullptr;
    cudaGetSymbolAddress(&maxAddr, g_wmax);
    cudaMemsetAsync(maxAddr, 0, 3 * sizeof(unsigned));

    prep_max<<<96, 512>>>(w1, g1, v1, w2, g2, v2, w3, g3, v3);
    prep_quant<<<96, 512>>>(w1, b1, g1, be1, m1, v1,
                            w2, b2, g2, be2, m2, v2,
                            w3, b3, g3, be3, m3, v3);

    conv_fused<<<304, 256, 98304>>>(x, (float*)d_out);
}

// round 14
// speedup vs baseline: 2.1130x; 1.0155x over previous
#include <cuda_runtime.h>
#include <cstdint>

#define BN_EPS_F 1e-3f

__device__ __align__(16) float g_w1f[256*128];
__device__ float g_b1[128];
__device__ __align__(16) unsigned char g_w2q[9*128*128]; // [tap][co][ci] s8
__device__ float g_b2[128];
__device__ __align__(16) unsigned char g_w3q[512*128];   // [co][ci] s8
__device__ float g_b3[512];
__device__ float g_inv[2];
// [0]=c1, [1]=c2a, [2]=c2b, [3]=c3a, [4]=c3b, [5..36]=done1[n], [37..68]=done2[n]
__device__ int   g_sync[69];
__device__ unsigned g_wmax[3];
__device__ __align__(16) unsigned g_act1[100352*32];
__device__ __align__(16) unsigned g_act2[100352*32];

__device__ __forceinline__ uint32_t smem_u32(const void* p){
    uint32_t a;
    asm("{ .reg .u64 t; cvta.to.shared.u64 t, %1; cvt.u32.u64 %0, t; }" : "=r"(a) : "l"(p));
    return a;
}
#define SWZ(o) ((o) ^ (((o) >> 3) & 0x70))

__device__ __forceinline__ void ldsm4(unsigned* r, uint32_t addr){
    asm volatile("ldmatrix.sync.aligned.m8n8.x4.shared.b16 {%0,%1,%2,%3}, [%4];"
        : "=r"(r[0]), "=r"(r[1]), "=r"(r[2]), "=r"(r[3]) : "r"(addr));
}
__device__ __forceinline__ void mma_u8s8(int* d, const unsigned* a, const unsigned* b){
    asm volatile("mma.sync.aligned.m16n8k32.row.col.s32.u8.s8.s32 "
        "{%0,%1,%2,%3}, {%4,%5,%6,%7}, {%8,%9}, {%0,%1,%2,%3};"
        : "+r"(d[0]), "+r"(d[1]), "+r"(d[2]), "+r"(d[3])
        : "r"(a[0]), "r"(a[1]), "r"(a[2]), "r"(a[3]), "r"(b[0]), "r"(b[1]));
}
__device__ __forceinline__ void mma_s8u8(int* d, const unsigned* a, const unsigned* b){
    asm volatile("mma.sync.aligned.m16n8k32.row.col.s32.s8.u8.s32 "
        "{%0,%1,%2,%3}, {%4,%5,%6,%7}, {%8,%9}, {%0,%1,%2,%3};"
        : "+r"(d[0]), "+r"(d[1]), "+r"(d[2]), "+r"(d[3])
        : "r"(a[0]), "r"(a[1]), "r"(a[2]), "r"(a[3]), "r"(b[0]), "r"(b[1]));
}
#define CPA(dst, src, sz) asm volatile("cp.async.cg.shared.global [%0], [%1], 16, %2;" :: "r"(dst), "l"(src), "r"(sz) : "memory")
#define CPC()  asm volatile("cp.async.commit_group;" ::: "memory")
#define CPW(n) asm volatile("cp.async.wait_group %0;" :: "n"(n) : "memory")

// ---------------- prep pass 1 (unchanged) ----------------
__global__ __launch_bounds__(512) void prep_max(
    const float* __restrict__ w1, const float* __restrict__ g1, const float* __restrict__ v1,
    const float* __restrict__ w2, const float* __restrict__ g2, const float* __restrict__ v2,
    const float* __restrict__ w3, const float* __restrict__ g3, const float* __restrict__ v3)
{
    __shared__ float sc[512]; __shared__ float red[512];
    int tid = threadIdx.x;
    int grp = blockIdx.x >> 5, sub = blockIdx.x & 31;
    float lmax = 0.f;
    if (grp == 0) {
        if (tid < 128) sc[tid] = __fdiv_rn(g1[tid], __fsqrt_rn(__fadd_rn(v1[tid], BN_EPS_F)));
        __syncthreads();
        int base = sub * 1024;
        for (int i = base + tid; i < base + 1024; i += 512)
            lmax = fmaxf(lmax, fabsf(__fmul_rn(w1[i], sc[i >> 8])));
    } else if (grp == 1) {
        if (tid < 128) sc[tid] = __fdiv_rn(g2[tid], __fsqrt_rn(__fadd_rn(v2[tid], BN_EPS_F)));
        __syncthreads();
        int base = sub * 4608;
        for (int i = base + tid; i < base + 4608; i += 512)
            lmax = fmaxf(lmax, fabsf(__fmul_rn(w2[i], sc[i / 1152])));
    } else {
        sc[tid] = __fdiv_rn(g3[tid], __fsqrt_rn(__fadd_rn(v3[tid], BN_EPS_F)));
        __syncthreads();
        int base = sub * 2048;
        for (int i = base + tid; i < base + 2048; i += 512)
            lmax = fmaxf(lmax, fabsf(__fmul_rn(w3[i], sc[i >> 7])));
    }
    red[tid] = lmax; __syncthreads();
    for (int s = 256; s > 0; s >>= 1) { if (tid < s) red[tid] = fmaxf(red[tid], red[tid+s]); __syncthreads(); }
    if (tid == 0) atomicMax(&g_wmax[grp], __float_as_uint(red[0]));
}

// ---------------- prep pass 2 (unchanged) ----------------
__global__ __launch_bounds__(512) void prep_quant(
    const float* __restrict__ w1, const float* __restrict__ b1,
    const float* __restrict__ g1, const float* __restrict__ be1,
    const float* __restrict__ m1, const float* __restrict__ v1,
    const float* __restrict__ w2, const float* __restrict__ b2,
    const float* __restrict__ g2, const float* __restrict__ be2,
    const float* __restrict__ m2, const float* __restrict__ v2,
    const float* __restrict__ w3, const float* __restrict__ b3,
    const float* __restrict__ g3, const float* __restrict__ be3,
    const float* __restrict__ m3, const float* __restrict__ v3)
{
    __shared__ float sc[512]; __shared__ float red[512];
    int tid = threadIdx.x;
    int grp = blockIdx.x >> 5, sub = blockIdx.x & 31;
    if (grp == 0) {
        if (tid < 128) sc[tid] = __fdiv_rn(g1[tid], __fsqrt_rn(__fadd_rn(v1[tid], BN_EPS_F)));
        __syncthreads();
        float sw = __fdiv_rn(127.f, fmaxf(__uint_as_float(g_wmax[0]), 1e-8f));
        int base = sub * 1024;
        for (int i = base + tid; i < base + 1024; i += 512) {
            float wf = __fmul_rn(w1[i], sc[i >> 8]);
            g_w1f[(i & 255) * 128 + (i >> 8)] = __fdiv_rn(rintf(__fmul_rn(wf, sw)), sw);
        }
        if (sub == 0) {
            float bf = 0.f;
            if (tid < 128) bf = __fadd_rn(__fmul_rn(__fsub_rn(b1[tid], m1[tid]), sc[tid]), be1[tid]);
            red[tid] = fabsf(bf); __syncthreads();
            for (int s = 256; s > 0; s >>= 1) { if (tid < s) red[tid] = fmaxf(red[tid], red[tid+s]); __syncthreads(); }
            float sb = __fdiv_rn(32767.f, fmaxf(red[0], 1e-8f));
            if (tid < 128) g_b1[tid] = __fdiv_rn(rintf(__fmul_rn(bf, sb)), sb);
        }
    } else if (grp == 1) {
        if (tid < 128) sc[tid] = __fdiv_rn(g2[tid], __fsqrt_rn(__fadd_rn(v2[tid], BN_EPS_F)));
        __syncthreads();
        float sw = __fdiv_rn(127.f, fmaxf(__uint_as_float(g_wmax[1]), 1e-8f));
        int base = sub * 4608;
        for (int i = base + tid; i < base + 4608; i += 512) {
            int o = i / 1152, rem = i - o * 1152, ci = rem / 9, t = rem - ci * 9;
            int q = (int)rintf(__fmul_rn(__fmul_rn(w2[i], sc[o]), sw));
            ((signed char*)g_w2q)[(t * 128 + o) * 128 + ci] = (signed char)q;
        }
        if (sub == 0) {
            float bf = 0.f;
            if (tid < 128) bf = __fadd_rn(__fmul_rn(__fsub_rn(b2[tid], m2[tid]), sc[tid]), be2[tid]);
            red[tid] = fabsf(bf); __syncthreads();
            for (int s = 256; s > 0; s >>= 1) { if (tid < s) red[tid] = fmaxf(red[tid], red[tid+s]); __syncthreads(); }
            float sb = __fdiv_rn(32767.f, fmaxf(red[0], 1e-8f));
            if (tid < 128) g_b2[tid] = __fdiv_rn(rintf(__fmul_rn(bf, sb)), sb);
            if (tid == 0)  g_inv[0] = __fdiv_rn(1.f, __fmul_rn(sw, 25.5f));
        }
    } else {
        sc[tid] = __fdiv_rn(g3[tid], __fsqrt_rn(__fadd_rn(v3[tid], BN_EPS_F)));
        __syncthreads();
        float sw = __fdiv_rn(127.f, fmaxf(__uint_as_float(g_wmax[2]), 1e-8f));
        int base = sub * 2048;
        for (int i = base + tid; i < base + 2048; i += 512)
            ((signed char*)g_w3q)[i] = (signed char)(int)rintf(__fmul_rn(__fmul_rn(w3[i], sc[i >> 7]), sw));
        if (sub == 0) {
            float bf = __fadd_rn(__fmul_rn(__fsub_rn(b3[tid], m3[tid]), sc[tid]), be3[tid]);
            red[tid] = fabsf(bf); __syncthreads();
            for (int s = 256; s > 0; s >>= 1) { if (tid < s) red[tid] = fmaxf(red[tid], red[tid+s]); __syncthreads(); }
            float sb = __fdiv_rn(32767.f, fmaxf(red[0], 1e-8f));
            g_b3[tid] = __fdiv_rn(rintf(__fmul_rn(bf, sb)), sb);
            if (tid == 0) g_inv[1] = __fdiv_rn(1.f, __fmul_rn(sw, 25.5f));
        }
    }
}

// ---------------- fused persistent kernel, 256 threads, 2 CTAs/SM, co-half split ----------------
__global__ __launch_bounds__(256, 2) void conv_fused(const float* __restrict__ x,
                                                     float* __restrict__ out)
{
    extern __shared__ char smem[];
    const uint32_t SM_W = 0, SM_H = 73728, SM_FB = 96768;
    __shared__ int s_next;
    uint32_t sb = smem_u32(smem);
    int tid = threadIdx.x, wid = tid >> 5, lane = tid & 31;
    int parity = blockIdx.x & 1;

    float inv2 = g_inv[0], inv3 = g_inv[1];

    if (tid == 0) s_next = atomicAdd(&g_sync[0], 1);
    __syncthreads();
    int t = s_next;

    // ================= phase 1: conv1 fp32, 128px x 128co, shared counter [0,800) =================
    {
        float* Asb = (float*)smem;
        float* Wsb = (float*)(smem + 16384);
        int tr = tid >> 4, tc = tid & 15;
        int co0 = tr * 8;
        int pxa = tc * 4, pxb = tc * 4 + 64;
        int lr = tid >> 4;
        int lc1 = (tid & 15) * 4, lc2 = lc1 + 64;

        while (t < 800) {
            int n = t / 25, p0 = (t - n * 25) * 128;
            const float* xn = x + ((size_t)n * 256) * 3136;
            int pc1 = min(p0 + lc1, 3132), pc2 = min(p0 + lc2, 3132);

            float acc[8][8];
#pragma unroll
            for (int j = 0; j < 8; j++)
#pragma unroll
                for (int q = 0; q < 8; q++) acc[j][q] = 0.f;

            float4 a1 = *(const float4*)(xn + (size_t)lr * 3136 + pc1);
            float4 a2 = *(const float4*)(xn + (size_t)lr * 3136 + pc2);
            float4 w1 = *(const float4*)(g_w1f + lr * 128 + lc1);
            float4 w2 = *(const float4*)(g_w1f + lr * 128 + lc2);
            *(float4*)(Asb + lr * 128 + lc1) = a1;
            *(float4*)(Asb + lr * 128 + lc2) = a2;
            *(float4*)(Wsb + lr * 128 + lc1) = w1;
            *(float4*)(Wsb + lr * 128 + lc2) = w2;
            __syncthreads();

            for (int p = 0; p < 16; p++) {
                int cu = (p & 1) * 2048;
                if (p < 15) {
                    int kr = (p + 1) * 16 + lr;
                    a1 = *(const float4*)(xn + (size_t)kr * 3136 + pc1);
                    a2 = *(const float4*)(xn + (size_t)kr * 3136 + pc2);
                    w1 = *(const float4*)(g_w1f + kr * 128 + lc1);
                    w2 = *(const float4*)(g_w1f + kr * 128 + lc2);
                }
#pragma unroll
                for (int k = 0; k < 16; k++) {
                    float4 av0 = *(const float4*)(Asb + cu + k * 128 + pxa);
                    float4 av1 = *(const float4*)(Asb + cu + k * 128 + pxb);
                    float4 wv0 = *(const float4*)(Wsb + cu + k * 128 + co0);
                    float4 wv1 = *(const float4*)(Wsb + cu + k * 128 + co0 + 4);
                    float wreg[8] = {wv0.x, wv0.y, wv0.z, wv0.w, wv1.x, wv1.y, wv1.z, wv1.w};
                    float areg[8] = {av0.x, av0.y, av0.z, av0.w, av1.x, av1.y, av1.z, av1.w};
#pragma unroll
                    for (int j = 0; j < 8; j++)
#pragma unroll
                        for (int q = 0; q < 8; q++)
                            acc[j][q] += wreg[j] * areg[q];
                }
                if (p < 15) {
                    int nx = ((p + 1) & 1) * 2048;
                    *(float4*)(Asb + nx + lr * 128 + lc1) = a1;
                    *(float4*)(Asb + nx + lr * 128 + lc2) = a2;
                    *(float4*)(Wsb + nx + lr * 128 + lc1) = w1;
                    *(float4*)(Wsb + nx + lr * 128 + lc2) = w2;
                    __syncthreads();
                }
            }

            float bias[8];
#pragma unroll
            for (int j = 0; j < 8; j++) bias[j] = g_b1[co0 + j];
#pragma unroll
            for (int q = 0; q < 8; q++) {
                int p = p0 + (q < 4 ? (pxa + q) : (pxb + q - 4));
                if (p >= 3136) continue;
                unsigned b0 = 0, b1v = 0;
#pragma unroll
                for (int j = 0; j < 8; j++) {
                    float vv = acc[j][q] + bias[j];
                    vv = fminf(fmaxf(vv, 0.f), 10.f);
                    unsigned a = (unsigned)(int)rintf(vv * 25.5f);
                    if (j < 4) b0 |= a << (8 * j); else b1v |= a << (8 * (j - 4));
                }
                *(uint2*)&g_act1[((unsigned)(n * 3136 + p)) * 32 + tr * 2] = make_uint2(b0, b1v);
            }
            __threadfence();
            __syncthreads();
            if (tid == 0) { atomicAdd(&g_sync[5 + n], 1); s_next = atomicAdd(&g_sync[0], 1); }
            __syncthreads();
            t = s_next;
        }
    }

    // ================= phase 2: conv2 int8 mma, co-half, 8 warps x (32px x 32co) =================
    __syncthreads();
    for (int u = tid; u < 4608; u += 256) {
        int row = u >> 3, c16 = u & 7;
        int tp = row >> 6, c = row & 63;
        uint4 wv = *(const uint4*)(g_w2q + ((tp * 128 + parity * 64 + c) * 128) + c16 * 16);
        *(uint4*)(smem + SM_W + SWZ(row * 128 + c16 * 16)) = wv;
    }
    if (tid < 64) ((float*)(smem + SM_FB))[tid] = g_b2[parity * 64 + tid];
    __syncthreads();

    int wrb = (wid & 3) * 32, wcb = (wid >> 2) * 32;
    int sub = lane >> 3, r8 = lane & 7;
    int row8 = (sub & 1) * 8, kh = (sub >> 1) * 16;
    int rowb = (sub >> 1) * 8, khb = (sub & 1) * 16;

    int yym[2], xxm[2];
#pragma unroll
    for (int mt = 0; mt < 2; mt++) {
        int px = wrb + mt * 16 + row8 + r8;
        yym[mt] = px >> 4; xxm[mt] = px & 15;
    }
    uint32_t wbb[2]; int wxx[2];
#pragma unroll
    for (int bt = 0; bt < 2; bt++) {
        int co = wcb + bt * 16 + rowb + r8;
        wbb[bt] = sb + SM_W + co * 128;
        wxx[bt] = (co & 7) * 16;
    }

    {
        if (tid == 0) s_next = atomicAdd(&g_sync[1 + parity], 1);
        __syncthreads();
        int t2 = s_next;

        while (t2 < 896) {
            int n = t2 / 28, r = t2 - n * 28;
            int y0 = (r >> 2) * 8, tx = r & 3;
            int x0 = (tx < 3) ? tx * 16 : 40;

            if (tid == 0) { while (((volatile int*)g_sync)[5 + n] < 25) {} }
            __syncthreads(); __threadfence();

            for (int u = tid; u < 1440; u += 256) {
                int hrow = u >> 3, c16 = u & 7;
                int iy = hrow / 18, ix = hrow - iy * 18;
                int gy = y0 + iy - 1, gx = x0 + ix - 1;
                bool ok = (gy >= 0 && gy < 56 && gx >= 0 && gx < 56);
                const void* src = ok ? (const void*)&g_act1[((unsigned)(n * 3136 + gy * 56 + gx)) * 32 + c16 * 4]
                                     : (const void*)g_act1;
                CPA(sb + SM_H + SWZ(hrow * 128 + c16 * 16), src, ok ? 16u : 0u);
            }
            CPC(); CPW(0);
            __syncthreads();

            int acc[2][4][4];
#pragma unroll
            for (int mt = 0; mt < 2; mt++)
#pragma unroll
                for (int nt = 0; nt < 4; nt++)
#pragma unroll
                    for (int qq = 0; qq < 4; qq++) acc[mt][nt][qq] = 0;

            for (int dy = 0; dy < 3; dy++)
                for (int dx = 0; dx < 3; dx++) {
                    uint32_t ab[2]; int axx[2];
#pragma unroll
                    for (int mt = 0; mt < 2; mt++) {
                        int hrow = (yym[mt] + dy) * 18 + xxm[mt] + dx;
                        ab[mt] = sb + SM_H + hrow * 128;
                        axx[mt] = (hrow & 7) * 16;
                    }
                    uint32_t wtap = (dy * 3 + dx) * 8192;
#pragma unroll
                    for (int ks = 0; ks < 4; ks++) {
                        unsigned A0[4], A1[4], B[2][4];
                        ldsm4(A0, ab[0] + ((ks * 32 + kh) ^ axx[0]));
                        ldsm4(A1, ab[1] + ((ks * 32 + kh) ^ axx[1]));
#pragma unroll
                        for (int bt = 0; bt < 2; bt++)
                            ldsm4(B[bt], wbb[bt] + wtap + ((ks * 32 + khb) ^ wxx[bt]));
#pragma unroll
                        for (int nt = 0; nt < 4; nt++) {
                            const unsigned* bp = &B[nt >> 1][(nt & 1) * 2];
                            mma_u8s8(acc[0][nt], A0, bp);
                            mma_u8s8(acc[1][nt], A1, bp);
                        }
                    }
                }

            __syncthreads();
            const float* fbs = (const float*)(smem + SM_FB);
            char* stg = smem + SM_H;
#pragma unroll
            for (int mt = 0; mt < 2; mt++)
#pragma unroll
                for (int h = 0; h < 2; h++) {
                    int px = wrb + mt * 16 + (lane >> 2) + h * 8;
#pragma unroll
                    for (int nt = 0; nt < 4; nt++) {
                        int co = wcb + nt * 8 + (lane & 3) * 2;
                        float v0 = (float)acc[mt][nt][h * 2 + 0] * inv2 + fbs[co];
                        float v1 = (float)acc[mt][nt][h * 2 + 1] * inv2 + fbs[co + 1];
                        v0 = fminf(fmaxf(v0, 0.f), 10.f);
                        v1 = fminf(fmaxf(v1, 0.f), 10.f);
                        unsigned u0 = (unsigned)(int)rintf(v0 * 25.5f);
                        unsigned u1 = (unsigned)(int)rintf(v1 * 25.5f);
                        *(unsigned short*)(stg + px * 128 + (co ^ ((px & 7) * 16))) =
                            (unsigned short)(u0 | (u1 << 8));
                    }
                }
            __syncthreads();

            for (int u = tid; u < 512; u += 256) {
                int px = u >> 2, c16 = u & 3;
                int yy = px >> 4, xx = px & 15;
                unsigned gp = (unsigned)(n * 3136 + (y0 + yy) * 56 + (x0 + xx));
                *(uint4*)&g_act2[gp * 32 + parity * 16 + c16 * 4] =
                    *(const uint4*)(stg + px * 128 + ((c16 * 16) ^ ((px & 7) * 16)));
            }
            __threadfence();
            __syncthreads();
            if (tid == 0) { atomicAdd(&g_sync[37 + n], 1); s_next = atomicAdd(&g_sync[1 + parity], 1); }
            __syncthreads();
            t2 = s_next;
        }
    }

    // ================= phase 3: conv3 int8 mma, co-half, 128px tiles, double-buffered act =================
    {
        __syncthreads();
        for (int u = tid; u < 2048; u += 256) {     // W3 half at base 0: 256 rows x 128B
            int row = u >> 3, c16 = u & 7;
            uint4 wv = *(const uint4*)(g_w3q + (parity * 256 + row) * 128 + c16 * 16);
            *(uint4*)(smem + SWZ(row * 128 + c16 * 16)) = wv;
        }
        if (tid < 64) ((float4*)(smem + 65536))[tid] = *(const float4*)&g_b3[parity * 256 + tid * 4];
        __syncthreads();

        const float* fb3 = (const float*)(smem + 65536);
        int cb0 = wid * 32;
        int ntl = (sub >> 1) * 8, kb = (sub & 1) * 16;

        unsigned Af[2][4][4];
#pragma unroll
        for (int amt = 0; amt < 2; amt++) {
            int co = cb0 + amt * 16 + row8 + r8;
            uint32_t base = sb + co * 128;
            int xx = (co & 7) * 16;
#pragma unroll
            for (int ks = 0; ks < 4; ks++)
                ldsm4(Af[amt][ks], base + ((ks * 32 + kh) ^ xx));
        }

        if (tid == 0) s_next = atomicAdd(&g_sync[3 + parity], 1);
        __syncthreads();
        int t3 = s_next;
        int buf3 = 0;

        if (t3 < 800) {   // prefetch first tile
            int n = t3 / 25, p0 = (t3 - n * 25) * 128;
            if (tid == 0) { while (((volatile int*)g_sync)[37 + n] < 56) {} }
            __syncthreads(); __threadfence();
            for (int u = tid; u < 1024; u += 256) {
                int pix = u >> 3, c16 = u & 7;
                int p = p0 + pix;
                bool ok = p < 3136;
                const void* src = ok ? (const void*)&g_act2[((unsigned)(n * 3136 + p)) * 32 + c16 * 4]
                                     : (const void*)g_act2;
                CPA(sb + 32768 + SWZ(pix * 128 + c16 * 16), src, ok ? 16u : 0u);
            }
            CPC();
        }

        while (t3 < 800) {
            int n = t3 / 25, p0 = (t3 - n * 25) * 128;
            uint32_t aB = sb + 32768 + buf3 * 16384;

            if (tid == 0) s_next = atomicAdd(&g_sync[3 + parity], 1);
            __syncthreads();
            int t3n = s_next;
            if (t3n < 800) {
                int n2 = t3n / 25, p02 = (t3n - n2 * 25) * 128;
                if (tid == 0) { while (((volatile int*)g_sync)[37 + n2] < 56) {} }
                __syncthreads(); __threadfence();
                uint32_t dB = sb + 32768 + (buf3 ^ 1) * 16384;
                for (int u = tid; u < 1024; u += 256) {
                    int pix = u >> 3, c16 = u & 7;
                    int p = p02 + pix;
                    bool ok = p < 3136;
                    const void* src = ok ? (const void*)&g_act2[((unsigned)(n2 * 3136 + p)) * 32 + c16 * 4]
                                         : (const void*)g_act2;
                    CPA(dB + SWZ(pix * 128 + c16 * 16), src, ok ? 16u : 0u);
                }
                CPC(); CPW(1);
            } else {
                CPW(0);
            }
            __syncthreads();

            for (int pg = 0; pg < 4; pg++) {
                int acc[2][4][4];
#pragma unroll
                for (int a = 0; a < 2; a++)
#pragma unroll
                    for (int b = 0; b < 4; b++)
#pragma unroll
                        for (int qq = 0; qq < 4; qq++) acc[a][b][qq] = 0;

#pragma unroll
                for (int ks = 0; ks < 4; ks++) {
                    unsigned Bf[2][4];
#pragma unroll
                    for (int bq = 0; bq < 2; bq++) {
                        int brow = pg * 32 + bq * 16 + ntl + r8;
                        ldsm4(Bf[bq], aB + brow * 128 + (((ks * 32 + kb)) ^ ((brow & 7) * 16)));
                    }
#pragma unroll
                    for (int amt = 0; amt < 2; amt++)
#pragma unroll
                        for (int nt = 0; nt < 4; nt++)
                            mma_s8u8(acc[amt][nt], Af[amt][ks], &Bf[nt >> 1][(nt & 1) * 2]);
                }

#pragma unroll
                for (int amt = 0; amt < 2; amt++)
#pragma unroll
                    for (int h = 0; h < 2; h++) {
                        int co = parity * 256 + cb0 + amt * 16 + (lane >> 2) + h * 8;
                        float bj = fb3[co - parity * 256];
                        size_t base = ((size_t)n * 512 + co) * 3136;
#pragma unroll
                        for (int nt = 0; nt < 4; nt++) {
                            int px = p0 + pg * 32 + nt * 8 + (lane & 3) * 2;
                            if (px < 3136) {
                                float2 o2;
                                o2.x = (float)acc[amt][nt][h * 2 + 0] * inv3 + bj;
                                o2.y = (float)acc[amt][nt][h * 2 + 1] * inv3 + bj;
                                *(float2*)(out + base + px) = o2;
                            }
                        }
                    }
            }
            __syncthreads();
            t3 = t3n; buf3 ^= 1;
        }
    }
}

// ---------------- launch ----------------
extern "C" void kernel_launch(void* const* d_in, const int* in_sizes, int n_in,
                              void* d_out, int out_size)
{
    const float* x   = (const float*)d_in[0];
    const float* w1  = (const float*)d_in[1];
    const float* b1  = (const float*)d_in[2];
    const float* g1  = (const float*)d_in[3];
    const float* be1 = (const float*)d_in[4];
    const float* m1  = (const float*)d_in[5];
    const float* v1  = (const float*)d_in[6];
    const float* w2  = (const float*)d_in[7];
    const float* b2  = (const float*)d_in[8];
    const float* g2  = (const float*)d_in[9];
    const float* be2 = (const float*)d_in[10];
    const float* m2  = (const float*)d_in[11];
    const float* v2  = (const float*)d_in[12];
    const float* w3  = (const float*)d_in[13];
    const float* b3  = (const float*)d_in[14];
    const float* g3  = (const float*)d_in[15];
    const float* be3 = (const float*)d_in[16];
    const float* m3  = (const float*)d_in[17];
    const float* v3  = (const float*)d_in[18];

    cudaFuncSetAttribute(conv_fused, cudaFuncAttributeMaxDynamicSharedMemorySize, 98304);

    void* syncAddr = nullptr;
    cudaGetSymbolAddress(&syncAddr, g_sync);
    cudaMemsetAsync(syncAddr, 0, 69 * sizeof(int));
    void* maxAddr = nullptr;
    cudaGetSymbolAddress(&maxAddr, g_wmax);
    cudaMemsetAsync(maxAddr, 0, 3 * sizeof(unsigned));

    prep_max<<<96, 512>>>(w1, g1, v1, w2, g2, v2, w3, g3, v3);
    prep_quant<<<96, 512>>>(w1, b1, g1, be1, m1, v1,
                            w2, b2, g2, be2, m2, v2,
                            w3, b3, g3, be3, m3, v3);

    conv_fused<<<304, 256, 98304>>>(x, (float*)d_out);
}